// round 1
// baseline (speedup 1.0000x reference)
#include <cuda_runtime.h>
#include <math.h>

#define B_    2
#define SEQL  2048
#define DIM_  1024
#define NH_   16
#define HD_   64
#define HID_  2816
#define NTOK  (B_*SEQL)          // 4096

// ---------------- scratch (device globals; no allocations allowed) ----------
__device__ float g_t[B_*512];
__device__ float g_kc[4*256];            // [which][b][256] circular-conv kernels
__device__ float g_xmod[NTOK*DIM_];
__device__ float g_qraw[NTOK*DIM_];
__device__ float g_kraw[NTOK*DIM_];
__device__ float g_vraw[NTOK*DIM_];
__device__ float g_q[NTOK*DIM_];         // [B][NH][S][64]
__device__ float g_k[NTOK*DIM_];
__device__ float g_v[NTOK*DIM_];
__device__ float g_attn[NTOK*DIM_];      // [B][S][NH*64]
__device__ float g_ha[NTOK*DIM_];
__device__ float g_x1[NTOK*DIM_];
__device__ float g_x1m[NTOK*DIM_];
__device__ float g_hm[NTOK*DIM_];
__device__ float g_g1[NTOK*HID_];
__device__ float g_g3[NTOK*HID_];
__device__ float g_hh[NTOK*HID_];

// ---------------- proj: t = silu(ada) @ proj_w + proj_b ---------------------
__global__ void proj_kernel(const float* __restrict__ ada, const float* __restrict__ pw,
                            const float* __restrict__ pb)
{
    int j = blockIdx.x * blockDim.x + threadIdx.x;   // 0..511
    int b = blockIdx.y;
    float acc = pb[j];
    const float* ap = ada + b*DIM_;
    for (int d = 0; d < DIM_; ++d) {
        float a = ap[d];
        float s = a / (1.0f + __expf(-a));           // silu
        acc = fmaf(s, pw[d*512 + j], acc);
    }
    g_t[b*512 + j] = acc;
}

// ------------- circular-conv kernel from ftime: k[d]=1/256 Σ F[m] cos(2πmd/256)
__global__ void kconv_kernel()
{
    int d = threadIdx.x;
    int which = blockIdx.x, b = blockIdx.y;
    const float* F = g_t + b*512 + which*256;
    float acc = 0.f;
    for (int m = 0; m < 256; ++m) {
        int md = (m * d) & 255;
        acc = fmaf(F[m], cospif((float)md * (1.0f/128.0f)), acc);
    }
    g_kc[(which*2 + b)*256 + d] = acc * (1.0f/256.0f);
}

// ------------- adafm modulate: per 16x16 patch, 256-pt circular conv ---------
__global__ __launch_bounds__(256) void modulate_kernel(const float* __restrict__ X,
                                                       float* __restrict__ Y, int which)
{
    __shared__ float xp[256];
    __shared__ float kk[256];
    int jb = blockIdx.x, ib = blockIdx.y, b = blockIdx.z;
    int n = threadIdx.x;
    int r = n >> 4, c = n & 15;
    size_t gi = ((size_t)(b*SEQL + ib*16 + r))*DIM_ + jb*16 + c;
    xp[n] = X[gi];
    kk[n] = g_kc[(which*2 + b)*256 + n];
    __syncthreads();
    float acc = 0.f;
    #pragma unroll 8
    for (int m = 0; m < 256; ++m)
        acc = fmaf(xp[m], kk[(n - m) & 255], acc);
    Y[gi] = acc;
}

// ------------- generic SGEMM: C[M,N] = A[M,K] (row) @ B[K,N] (row) -----------
// 128x128x8 tiles, 256 threads, 8x8 per thread, gmem prefetch.
__global__ __launch_bounds__(256) void sgemm_kernel(const float* __restrict__ A,
                                                    const float* __restrict__ Bm,
                                                    float* __restrict__ C,
                                                    int M, int N, int K)
{
    __shared__ float As[8][128];
    __shared__ float Bs[8][128];
    int tid = threadIdx.x;
    int tx = tid & 15, ty = tid >> 4;
    int row0 = blockIdx.y * 128, col0 = blockIdx.x * 128;
    int am = tid >> 1, ak = (tid & 1) * 4;
    int bk = tid >> 5, bn = (tid & 31) * 4;

    float acc[8][8];
    #pragma unroll
    for (int i = 0; i < 8; i++)
        #pragma unroll
        for (int j = 0; j < 8; j++) acc[i][j] = 0.f;

    float4 av = *(const float4*)(A  + (size_t)(row0+am)*K + ak);
    float4 bv = *(const float4*)(Bm + (size_t)bk*N + col0 + bn);

    for (int k0 = 0; k0 < K; k0 += 8) {
        As[ak+0][am] = av.x; As[ak+1][am] = av.y;
        As[ak+2][am] = av.z; As[ak+3][am] = av.w;
        *(float4*)&Bs[bk][bn] = bv;
        __syncthreads();
        if (k0 + 8 < K) {
            av = *(const float4*)(A  + (size_t)(row0+am)*K + (k0+8) + ak);
            bv = *(const float4*)(Bm + (size_t)(k0+8+bk)*N + col0 + bn);
        }
        #pragma unroll
        for (int kk = 0; kk < 8; kk++) {
            float4 a0 = *(const float4*)&As[kk][ty*8];
            float4 a1 = *(const float4*)&As[kk][ty*8+4];
            float4 b0 = *(const float4*)&Bs[kk][tx*8];
            float4 b1 = *(const float4*)&Bs[kk][tx*8+4];
            float ar[8] = {a0.x,a0.y,a0.z,a0.w,a1.x,a1.y,a1.z,a1.w};
            float br[8] = {b0.x,b0.y,b0.z,b0.w,b1.x,b1.y,b1.z,b1.w};
            #pragma unroll
            for (int i = 0; i < 8; i++)
                #pragma unroll
                for (int j = 0; j < 8; j++)
                    acc[i][j] = fmaf(ar[i], br[j], acc[i][j]);
        }
        __syncthreads();
    }
    #pragma unroll
    for (int i = 0; i < 8; i++) {
        float* Cp = C + (size_t)(row0 + ty*8 + i)*N + col0 + tx*8;
        *(float4*)Cp     = make_float4(acc[i][0],acc[i][1],acc[i][2],acc[i][3]);
        *(float4*)(Cp+4) = make_float4(acc[i][4],acc[i][5],acc[i][6],acc[i][7]);
    }
}

// ------------- rotary + justnorm(q,k)*sqk_eff + permute to [B,H,S,64] --------
__global__ __launch_bounds__(512) void rotnorm_kernel(const float* __restrict__ fc,
                                                      const float* __restrict__ fs,
                                                      const float* __restrict__ sqk)
{
    int row = blockIdx.x;                 // b*SEQL + s
    int s = row & (SEQL - 1);
    int b = row >> 11;
    int h = threadIdx.x >> 5;             // 16 warps = 16 heads
    int i = threadIdx.x & 31;             // pair index (HD/2 = 32)
    float c = fc[s*32 + i], sn = fs[s*32 + i];
    size_t gin = (size_t)row*DIM_ + h*64 + 2*i;
    float qa = g_qraw[gin], qb = g_qraw[gin+1];
    float ka = g_kraw[gin], kb = g_kraw[gin+1];
    float ra = qa*c - qb*sn, rb = qa*sn + qb*c;
    float ta = ka*c - kb*sn, tb = ka*sn + kb*c;
    float sq = ra*ra + rb*rb, sk = ta*ta + tb*tb;
    #pragma unroll
    for (int o = 16; o; o >>= 1) {
        sq += __shfl_xor_sync(0xffffffffu, sq, o);
        sk += __shfl_xor_sync(0xffffffffu, sk, o);
    }
    float invq = 1.0f / fmaxf(sqrtf(sq), 1e-12f);
    float invk = 1.0f / fmaxf(sqrtf(sk), 1e-12f);
    float sa = sqk[h*64 + 2*i]   * 32.0f;   // sqrt(DIM)=32
    float sb = sqk[h*64 + 2*i+1] * 32.0f;
    size_t go = ((size_t)(b*NH_ + h)*SEQL + s)*64 + 2*i;
    g_q[go]   = ra*invq*sa;  g_q[go+1] = rb*invq*sb;
    g_k[go]   = ta*invk*sa;  g_k[go+1] = tb*invk*sb;
    g_v[go]   = g_vraw[gin]; g_v[go+1] = g_vraw[gin+1];
}

// ------------- flash attention fp32, Br=Bc=64, scale = sqrt(HD)=8 ------------
#define ATPAD 68
#define ATT_SMEM (4*64*ATPAD*4)

__global__ __launch_bounds__(256) void attn_kernel()
{
    extern __shared__ float sm[];
    float* Qts = sm;                  // [d][r] (d-major, padded)
    float* Kts = sm + 64*ATPAD;       // [d][c]
    float* Vs  = sm + 2*64*ATPAD;     // [c][d]
    float* Pst = sm + 3*64*ATPAD;     // [c][r]
    int tid = threadIdx.x;
    int tx = tid & 15, ty = tid >> 4;
    int q0 = blockIdx.x * 64;
    int h = blockIdx.y, b = blockIdx.z;
    size_t base = ((size_t)(b*NH_ + h))*SEQL*HD_;
    const float* Qb = g_q + base;
    const float* Kb = g_k + base;
    const float* Vb = g_v + base;

    {   // load Q tile transposed
        int rr = tid >> 4;
        int d4 = (tid & 15) * 4;
        #pragma unroll
        for (int r0 = 0; r0 < 64; r0 += 16) {
            int r = rr + r0;
            float4 vq = *(const float4*)(Qb + (size_t)(q0 + r)*HD_ + d4);
            Qts[(d4+0)*ATPAD + r] = vq.x;
            Qts[(d4+1)*ATPAD + r] = vq.y;
            Qts[(d4+2)*ATPAD + r] = vq.z;
            Qts[(d4+3)*ATPAD + r] = vq.w;
        }
    }

    float mrun[4], lrun[4], oacc[4][4];
    #pragma unroll
    for (int i = 0; i < 4; i++) {
        mrun[i] = -1e30f; lrun[i] = 0.f;
        #pragma unroll
        for (int j = 0; j < 4; j++) oacc[i][j] = 0.f;
    }

    for (int k0 = 0; k0 < SEQL; k0 += 64) {
        __syncthreads();
        {   // load K (transposed) and V (natural)
            int rr = tid >> 4;
            int d4 = (tid & 15) * 4;
            #pragma unroll
            for (int r0 = 0; r0 < 64; r0 += 16) {
                int r = rr + r0;
                float4 kv = *(const float4*)(Kb + (size_t)(k0 + r)*HD_ + d4);
                Kts[(d4+0)*ATPAD + r] = kv.x;
                Kts[(d4+1)*ATPAD + r] = kv.y;
                Kts[(d4+2)*ATPAD + r] = kv.z;
                Kts[(d4+3)*ATPAD + r] = kv.w;
                float4 vv = *(const float4*)(Vb + (size_t)(k0 + r)*HD_ + d4);
                *(float4*)&Vs[r*ATPAD + d4] = vv;
            }
        }
        __syncthreads();

        float s[4][4];
        #pragma unroll
        for (int i = 0; i < 4; i++)
            #pragma unroll
            for (int j = 0; j < 4; j++) s[i][j] = 0.f;
        #pragma unroll 16
        for (int d = 0; d < 64; ++d) {
            float4 qa = *(const float4*)&Qts[d*ATPAD + ty*4];
            float4 kb = *(const float4*)&Kts[d*ATPAD + tx*4];
            float qr[4] = {qa.x,qa.y,qa.z,qa.w};
            float kr[4] = {kb.x,kb.y,kb.z,kb.w};
            #pragma unroll
            for (int i = 0; i < 4; i++)
                #pragma unroll
                for (int j = 0; j < 4; j++)
                    s[i][j] = fmaf(qr[i], kr[j], s[i][j]);
        }

        #pragma unroll
        for (int rr = 0; rr < 4; ++rr) {
            #pragma unroll
            for (int cc = 0; cc < 4; cc++) s[rr][cc] *= 8.0f;   // scale = sqrt(HD)
            float tm = fmaxf(fmaxf(s[rr][0], s[rr][1]), fmaxf(s[rr][2], s[rr][3]));
            #pragma unroll
            for (int o = 1; o < 16; o <<= 1)
                tm = fmaxf(tm, __shfl_xor_sync(0xffffffffu, tm, o));
            float mn = fmaxf(mrun[rr], tm);
            float f = __expf(mrun[rr] - mn);
            float rs = 0.f;
            #pragma unroll
            for (int cc = 0; cc < 4; cc++) {
                float p = __expf(s[rr][cc] - mn);
                s[rr][cc] = p; rs += p;
            }
            #pragma unroll
            for (int o = 1; o < 16; o <<= 1)
                rs += __shfl_xor_sync(0xffffffffu, rs, o);
            lrun[rr] = lrun[rr]*f + rs;
            mrun[rr] = mn;
            #pragma unroll
            for (int cc = 0; cc < 4; cc++) oacc[rr][cc] *= f;
            #pragma unroll
            for (int cc = 0; cc < 4; cc++)
                Pst[(tx*4 + cc)*ATPAD + ty*4 + rr] = s[rr][cc];
        }
        __syncthreads();

        #pragma unroll 16
        for (int c = 0; c < 64; ++c) {
            float4 pa = *(const float4*)&Pst[c*ATPAD + ty*4];
            float4 vb = *(const float4*)&Vs[c*ATPAD + tx*4];
            float pr[4] = {pa.x,pa.y,pa.z,pa.w};
            float vr[4] = {vb.x,vb.y,vb.z,vb.w};
            #pragma unroll
            for (int i = 0; i < 4; i++)
                #pragma unroll
                for (int j = 0; j < 4; j++)
                    oacc[i][j] = fmaf(pr[i], vr[j], oacc[i][j]);
        }
    }

    #pragma unroll
    for (int rr = 0; rr < 4; ++rr) {
        float inv = 1.0f / lrun[rr];
        float4 w = make_float4(oacc[rr][0]*inv, oacc[rr][1]*inv,
                               oacc[rr][2]*inv, oacc[rr][3]*inv);
        size_t oi = ((size_t)(b*SEQL) + q0 + ty*4 + rr)*DIM_ + h*HD_ + tx*4;
        *(float4*)(g_attn + oi) = w;
    }
}

// ------------- combine: out = justnorm(justnorm(x) + lr*(justnorm(h)-justnorm(x)))
__device__ __forceinline__ float block_sum(float v, float* shm)
{
    #pragma unroll
    for (int o = 16; o; o >>= 1) v += __shfl_xor_sync(0xffffffffu, v, o);
    __syncthreads();
    if ((threadIdx.x & 31) == 0) shm[threadIdx.x >> 5] = v;
    __syncthreads();
    if (threadIdx.x < 32) {
        float t = (threadIdx.x < 8) ? shm[threadIdx.x] : 0.f;
        #pragma unroll
        for (int o = 4; o; o >>= 1) t += __shfl_xor_sync(0xffffffffu, t, o);
        if (threadIdx.x == 0) shm[0] = t;
    }
    __syncthreads();
    return shm[0];
}

__global__ __launch_bounds__(256) void combine_kernel(const float* __restrict__ X,
                                                      const float* __restrict__ H,
                                                      const float* __restrict__ alpha,
                                                      float* __restrict__ Out)
{
    __shared__ float shm[8];
    int row = blockIdx.x;
    const float* xp = X + (size_t)row*DIM_;
    const float* hp = H + (size_t)row*DIM_;
    float xv[4], hv[4];
    float sx = 0.f, sh = 0.f;
    #pragma unroll
    for (int i = 0; i < 4; i++) {
        int j = threadIdx.x + i*256;
        xv[i] = xp[j]; hv[i] = hp[j];
        sx = fmaf(xv[i], xv[i], sx);
        sh = fmaf(hv[i], hv[i], sh);
    }
    float nx = block_sum(sx, shm);
    float nh = block_sum(sh, shm);
    float invx = 1.0f / fmaxf(sqrtf(nx), 1e-12f);
    float invh = 1.0f / fmaxf(sqrtf(nh), 1e-12f);
    float yv[4]; float sy = 0.f;
    #pragma unroll
    for (int i = 0; i < 4; i++) {
        int j = threadIdx.x + i*256;
        float lr = fabsf(alpha[j] * 1.6f);     // 0.05*sqrt(DIM) = 1.6
        float hn = xv[i]*invx;
        float y = hn + lr*(hv[i]*invh - hn);
        yv[i] = y; sy = fmaf(y, y, sy);
    }
    float ny = block_sum(sy, shm);
    float invy = 1.0f / fmaxf(sqrtf(ny), 1e-12f);
    #pragma unroll
    for (int i = 0; i < 4; i++)
        Out[(size_t)row*DIM_ + threadIdx.x + i*256] = yv[i]*invy;
}

// ------------- swiglu gate: hh = silu(g1*sv*sqrtH) * (g3*su) -----------------
__global__ void hmid_kernel(const float* __restrict__ su, const float* __restrict__ sv)
{
    int idx = blockIdx.x*256 + threadIdx.x;
    int j = idx % HID_;
    float z = g_g1[idx] * sv[j] * 53.06599665f;   // sqrt(2816)
    float sg = 1.0f / (1.0f + __expf(-z));
    g_hh[idx] = z * sg * (g_g3[idx] * su[j]);
}

// ------------------------------- launcher ------------------------------------
extern "C" void kernel_launch(void* const* d_in, const int* in_sizes, int n_in,
                              void* d_out, int out_size)
{
    const float* x   = (const float*)d_in[0];
    const float* fc  = (const float*)d_in[1];
    const float* fs  = (const float*)d_in[2];
    const float* ada = (const float*)d_in[3];
    const float* wq  = (const float*)d_in[4];
    const float* wk  = (const float*)d_in[5];
    const float* wv  = (const float*)d_in[6];
    const float* wo  = (const float*)d_in[7];
    const float* sqk = (const float*)d_in[8];
    const float* w1  = (const float*)d_in[9];
    const float* w2  = (const float*)d_in[10];
    const float* w3  = (const float*)d_in[11];
    const float* su  = (const float*)d_in[12];
    const float* sv  = (const float*)d_in[13];
    const float* pw  = (const float*)d_in[14];
    const float* pb  = (const float*)d_in[15];
    const float* aat = (const float*)d_in[16];
    const float* aml = (const float*)d_in[17];
    float* out = (float*)d_out;

    float *xmod, *qraw, *kraw, *vraw, *attn, *ha, *x1, *x1m, *g1, *g3, *hh, *hm;
    cudaGetSymbolAddress((void**)&xmod, g_xmod);
    cudaGetSymbolAddress((void**)&qraw, g_qraw);
    cudaGetSymbolAddress((void**)&kraw, g_kraw);
    cudaGetSymbolAddress((void**)&vraw, g_vraw);
    cudaGetSymbolAddress((void**)&attn, g_attn);
    cudaGetSymbolAddress((void**)&ha,   g_ha);
    cudaGetSymbolAddress((void**)&x1,   g_x1);
    cudaGetSymbolAddress((void**)&x1m,  g_x1m);
    cudaGetSymbolAddress((void**)&g1,   g_g1);
    cudaGetSymbolAddress((void**)&g3,   g_g3);
    cudaGetSymbolAddress((void**)&hh,   g_hh);
    cudaGetSymbolAddress((void**)&hm,   g_hm);

    // 1. adafm projection + conv kernels
    proj_kernel<<<dim3(2, 2), 256>>>(ada, pw, pb);
    kconv_kernel<<<dim3(2, 2), 256>>>();

    // 2. attention branch
    modulate_kernel<<<dim3(64, 128, B_), 256>>>(x, xmod, 0);
    sgemm_kernel<<<dim3(DIM_/128, NTOK/128), 256>>>(xmod, wq, qraw, NTOK, DIM_, DIM_);
    sgemm_kernel<<<dim3(DIM_/128, NTOK/128), 256>>>(xmod, wk, kraw, NTOK, DIM_, DIM_);
    sgemm_kernel<<<dim3(DIM_/128, NTOK/128), 256>>>(xmod, wv, vraw, NTOK, DIM_, DIM_);
    rotnorm_kernel<<<NTOK, 512>>>(fc, fs, sqk);
    cudaFuncSetAttribute(attn_kernel, cudaFuncAttributeMaxDynamicSharedMemorySize, ATT_SMEM);
    attn_kernel<<<dim3(SEQL/64, NH_, B_), 256, ATT_SMEM>>>();
    sgemm_kernel<<<dim3(DIM_/128, NTOK/128), 256>>>(attn, wo, ha, NTOK, DIM_, DIM_);
    combine_kernel<<<NTOK, 256>>>(x, ha, aat, x1);

    // 3. mlp branch
    modulate_kernel<<<dim3(64, 128, B_), 256>>>(x1, x1m, 1);
    sgemm_kernel<<<dim3(HID_/128, NTOK/128), 256>>>(x1m, w1, g1, NTOK, HID_, DIM_);
    sgemm_kernel<<<dim3(HID_/128, NTOK/128), 256>>>(x1m, w3, g3, NTOK, HID_, DIM_);
    hmid_kernel<<<(NTOK*HID_)/256, 256>>>(su, sv);
    sgemm_kernel<<<dim3(DIM_/128, NTOK/128), 256>>>(hh, w2, hm, NTOK, DIM_, HID_);
    combine_kernel<<<NTOK, 256>>>(x1, hm, aml, out);
}

// round 4
// speedup vs baseline: 2.8307x; 2.8307x over previous
#include <cuda_runtime.h>
#include <cuda_bf16.h>
#include <math.h>
#include <cstdint>

#define B_    2
#define SEQL  2048
#define DIM_  1024
#define NH_   16
#define HD_   64
#define HID_  2816
#define NTOK  (B_*SEQL)          // 4096

// ---------------- scratch (device globals; no allocations allowed) ----------
__device__ float g_t[B_*512];
__device__ float g_kc[4*256];
__device__ float g_qraw[NTOK*DIM_];
__device__ float g_kraw[NTOK*DIM_];
__device__ float g_vraw[NTOK*DIM_];
__device__ float g_q[NTOK*DIM_];         // [B][NH][S][64]
__device__ float g_k[NTOK*DIM_];
__device__ float g_v[NTOK*DIM_];
__device__ float g_ha[NTOK*DIM_];
__device__ float g_x1[NTOK*DIM_];
__device__ float g_hm[NTOK*DIM_];
__device__ float g_g1[NTOK*HID_];
__device__ float g_g3[NTOK*HID_];
// bf16 activations (A operands of GEMMs)
__device__ __nv_bfloat16 g_xmodb[NTOK*DIM_];
__device__ __nv_bfloat16 g_attnb[NTOK*DIM_];
__device__ __nv_bfloat16 g_x1mb[NTOK*DIM_];
__device__ __nv_bfloat16 g_hhb[NTOK*HID_];
// bf16 transposed weights [N][K]
__device__ __nv_bfloat16 g_wqt[DIM_*DIM_];
__device__ __nv_bfloat16 g_wkt[DIM_*DIM_];
__device__ __nv_bfloat16 g_wvt[DIM_*DIM_];
__device__ __nv_bfloat16 g_wot[DIM_*DIM_];
__device__ __nv_bfloat16 g_w1t[HID_*DIM_];
__device__ __nv_bfloat16 g_w3t[HID_*DIM_];
__device__ __nv_bfloat16 g_w2t[DIM_*HID_];

// ====================== mma.sync bf16 GEMM (family-safe) =====================
__device__ __forceinline__ uint32_t smem_u32(const void* p) {
    uint32_t a;
    asm("{ .reg .u64 t; cvta.to.shared.u64 t, %1; cvt.u32.u64 %0, t; }" : "=r"(a) : "l"(p));
    return a;
}
__device__ __forceinline__ void ldsm_x4(uint32_t* r, uint32_t addr) {
    asm volatile("ldmatrix.sync.aligned.m8n8.x4.shared.b16 {%0,%1,%2,%3}, [%4];"
                 : "=r"(r[0]), "=r"(r[1]), "=r"(r[2]), "=r"(r[3]) : "r"(addr));
}
__device__ __forceinline__ void ldsm_x2(uint32_t* r, uint32_t addr) {
    asm volatile("ldmatrix.sync.aligned.m8n8.x2.shared.b16 {%0,%1}, [%2];"
                 : "=r"(r[0]), "=r"(r[1]) : "r"(addr));
}
__device__ __forceinline__ void mma16816(float* c, const uint32_t* a, const uint32_t* b) {
    asm volatile("mma.sync.aligned.m16n8k16.row.col.f32.bf16.bf16.f32 "
                 "{%0,%1,%2,%3}, {%4,%5,%6,%7}, {%8,%9}, {%0,%1,%2,%3};"
                 : "+f"(c[0]), "+f"(c[1]), "+f"(c[2]), "+f"(c[3])
                 : "r"(a[0]), "r"(a[1]), "r"(a[2]), "r"(a[3]), "r"(b[0]), "r"(b[1]));
}

// C[M,N] = A[M,K](row,bf16) @ Bt[N,K](row,bf16)^T. 128x128 tiles, K-chunk 32.
// 8 warps: warp (wr,wc) in 2x4 grid owns 64x32. Padded smem stride 40 elems
// (80B): 8-row ldmatrix starts hit each 4-word bank group exactly once.
#define SPAD 40
__global__ __launch_bounds__(256) void tgemm_kernel(const __nv_bfloat16* __restrict__ A,
                                                    const __nv_bfloat16* __restrict__ Bt,
                                                    float* __restrict__ C,
                                                    int M, int N, int K)
{
    __shared__ __nv_bfloat16 sA[2][128][SPAD];
    __shared__ __nv_bfloat16 sB[2][128][SPAD];
    int tid = threadIdx.x, lane = tid & 31, wid = tid >> 5;
    int wr = wid >> 2, wc = wid & 3;
    int row0 = blockIdx.y * 128, col0 = blockIdx.x * 128;

    uint32_t sAb = smem_u32(&sA[0][0][0]);
    uint32_t sBb = smem_u32(&sB[0][0][0]);
    const uint32_t BUFB = 128 * SPAD * 2;    // bytes per buffer

    int srow = tid >> 2, sseg = tid & 3;
    const __nv_bfloat16* Ag = A  + (size_t)(row0 + srow)*K + sseg*8;
    const __nv_bfloat16* Bg = Bt + (size_t)(col0 + srow)*K + sseg*8;

    float acc[4][4][4];
    #pragma unroll
    for (int i = 0; i < 4; i++)
        #pragma unroll
        for (int j = 0; j < 4; j++)
            #pragma unroll
            for (int q = 0; q < 4; q++) acc[i][j][q] = 0.f;

    // preload chunk 0
    {
        uint4 a0 = *(const uint4*)Ag;
        uint4 a1 = *(const uint4*)(Ag + (size_t)64*K);
        uint4 b0 = *(const uint4*)Bg;
        uint4 b1 = *(const uint4*)(Bg + (size_t)64*K);
        *(uint4*)&sA[0][srow][sseg*8]    = a0;
        *(uint4*)&sA[0][srow+64][sseg*8] = a1;
        *(uint4*)&sB[0][srow][sseg*8]    = b0;
        *(uint4*)&sB[0][srow+64][sseg*8] = b1;
    }
    __syncthreads();

    int NC = K >> 5;
    // per-lane ldmatrix address components
    int aq = lane >> 3, arow = lane & 7;           // quad, row-in-matrix
    int a_r = (aq & 1)*8 + arow;                   // + mt*16 + wr*64
    int a_kb = (aq >> 1)*16;                       // byte offset of k-half
    int b_l = lane & 15;
    int b_r = b_l & 7;                             // + nt*8 + wc*32
    int b_kb = (b_l >> 3)*16;

    for (int c = 0; c < NC; c++) {
        int cur = c & 1;
        uint4 pa0, pa1, pb0, pb1;
        if (c + 1 < NC) {
            const __nv_bfloat16* Ap = Ag + (size_t)(c+1)*32;
            const __nv_bfloat16* Bp = Bg + (size_t)(c+1)*32;
            pa0 = *(const uint4*)Ap;
            pa1 = *(const uint4*)(Ap + (size_t)64*K);
            pb0 = *(const uint4*)Bp;
            pb1 = *(const uint4*)(Bp + (size_t)64*K);
        }

        uint32_t aBase = sAb + cur*BUFB;
        uint32_t bBase = sBb + cur*BUFB;
        #pragma unroll
        for (int ks = 0; ks < 2; ks++) {
            uint32_t afr[4][4], bfr[4][2];
            #pragma unroll
            for (int mt = 0; mt < 4; mt++)
                ldsm_x4(afr[mt], aBase + (wr*64 + mt*16 + a_r)*(SPAD*2) + ks*32 + a_kb);
            #pragma unroll
            for (int nt = 0; nt < 4; nt++)
                ldsm_x2(bfr[nt], bBase + (wc*32 + nt*8 + b_r)*(SPAD*2) + ks*32 + b_kb);
            #pragma unroll
            for (int mt = 0; mt < 4; mt++)
                #pragma unroll
                for (int nt = 0; nt < 4; nt++)
                    mma16816(acc[mt][nt], afr[mt], bfr[nt]);
        }

        if (c + 1 < NC) {
            int nb = cur ^ 1;
            *(uint4*)&sA[nb][srow][sseg*8]    = pa0;
            *(uint4*)&sA[nb][srow+64][sseg*8] = pa1;
            *(uint4*)&sB[nb][srow][sseg*8]    = pb0;
            *(uint4*)&sB[nb][srow+64][sseg*8] = pb1;
        }
        __syncthreads();
    }

    int cr = lane >> 2, cc = (lane & 3)*2;
    #pragma unroll
    for (int mt = 0; mt < 4; mt++) {
        #pragma unroll
        for (int nt = 0; nt < 4; nt++) {
            size_t r0 = (size_t)(row0 + wr*64 + mt*16 + cr);
            int col = col0 + wc*32 + nt*8 + cc;
            *(float2*)(C + r0*N + col)      = make_float2(acc[mt][nt][0], acc[mt][nt][1]);
            *(float2*)(C + (r0+8)*N + col)  = make_float2(acc[mt][nt][2], acc[mt][nt][3]);
        }
    }
}

// -------- weight transpose + bf16 convert: W[K][N] fp32 -> Wt[N][K] bf16 -----
__global__ void wtrans_kernel(const float* __restrict__ W, __nv_bfloat16* __restrict__ Wt,
                              int K, int N)
{
    __shared__ float t[32][33];
    int tx = threadIdx.x, ty = threadIdx.y;
    int n = blockIdx.x*32 + tx;
    int k0 = blockIdx.y*32;
    #pragma unroll
    for (int j = 0; j < 32; j += 8)
        t[ty+j][tx] = W[(size_t)(k0+ty+j)*N + n];
    __syncthreads();
    int k = k0 + tx;
    int nb = blockIdx.x*32;
    #pragma unroll
    for (int j = 0; j < 32; j += 8)
        Wt[(size_t)(nb+ty+j)*K + k] = __float2bfloat16(t[tx][ty+j]);
}

// ---------------- proj: t = silu(ada) @ proj_w + proj_b ---------------------
__global__ void proj_kernel(const float* __restrict__ ada, const float* __restrict__ pw,
                            const float* __restrict__ pb)
{
    int j = blockIdx.x * blockDim.x + threadIdx.x;
    int b = blockIdx.y;
    float acc = pb[j];
    const float* ap = ada + b*DIM_;
    for (int d = 0; d < DIM_; ++d) {
        float a = ap[d];
        float s = a / (1.0f + __expf(-a));
        acc = fmaf(s, pw[d*512 + j], acc);
    }
    g_t[b*512 + j] = acc;
}

__global__ void kconv_kernel()
{
    int d = threadIdx.x;
    int which = blockIdx.x, b = blockIdx.y;
    const float* F = g_t + b*512 + which*256;
    float acc = 0.f;
    for (int m = 0; m < 256; ++m) {
        int md = (m * d) & 255;
        acc = fmaf(F[m], cospif((float)md * (1.0f/128.0f)), acc);
    }
    g_kc[(which*2 + b)*256 + d] = acc * (1.0f/256.0f);
}

// ------------- adafm modulate -> bf16 output --------------------------------
__global__ __launch_bounds__(256) void modulate_kernel(const float* __restrict__ X,
                                                       __nv_bfloat16* __restrict__ Y, int which)
{
    __shared__ float xp[256];
    __shared__ float kk[256];
    int jb = blockIdx.x, ib = blockIdx.y, b = blockIdx.z;
    int n = threadIdx.x;
    int r = n >> 4, c = n & 15;
    size_t gi = ((size_t)(b*SEQL + ib*16 + r))*DIM_ + jb*16 + c;
    xp[n] = X[gi];
    kk[n] = g_kc[(which*2 + b)*256 + n];
    __syncthreads();
    float acc = 0.f;
    #pragma unroll 8
    for (int m = 0; m < 256; ++m)
        acc = fmaf(xp[m], kk[(n - m) & 255], acc);
    Y[gi] = __float2bfloat16(acc);
}

// ------------- rotary + justnorm(q,k)*sqk_eff + permute ---------------------
__global__ __launch_bounds__(512) void rotnorm_kernel(const float* __restrict__ fc,
                                                      const float* __restrict__ fs,
                                                      const float* __restrict__ sqk)
{
    int row = blockIdx.x;
    int s = row & (SEQL - 1);
    int b = row >> 11;
    int h = threadIdx.x >> 5;
    int i = threadIdx.x & 31;
    float c = fc[s*32 + i], sn = fs[s*32 + i];
    size_t gin = (size_t)row*DIM_ + h*64 + 2*i;
    float qa = g_qraw[gin], qb = g_qraw[gin+1];
    float ka = g_kraw[gin], kb = g_kraw[gin+1];
    float ra = qa*c - qb*sn, rb = qa*sn + qb*c;
    float ta = ka*c - kb*sn, tb = ka*sn + kb*c;
    float sq = ra*ra + rb*rb, sk = ta*ta + tb*tb;
    #pragma unroll
    for (int o = 16; o; o >>= 1) {
        sq += __shfl_xor_sync(0xffffffffu, sq, o);
        sk += __shfl_xor_sync(0xffffffffu, sk, o);
    }
    float invq = 1.0f / fmaxf(sqrtf(sq), 1e-12f);
    float invk = 1.0f / fmaxf(sqrtf(sk), 1e-12f);
    float sa = sqk[h*64 + 2*i]   * 32.0f;
    float sb = sqk[h*64 + 2*i+1] * 32.0f;
    size_t go = ((size_t)(b*NH_ + h)*SEQL + s)*64 + 2*i;
    g_q[go]   = ra*invq*sa;  g_q[go+1] = rb*invq*sb;
    g_k[go]   = ta*invk*sa;  g_k[go+1] = tb*invk*sb;
    g_v[go]   = g_vraw[gin]; g_v[go+1] = g_vraw[gin+1];
}

// ------------- flash attention fp32 (writes bf16 for wo GEMM) ---------------
#define ATPAD 68
#define ATT_SMEM (4*64*ATPAD*4)

__global__ __launch_bounds__(256) void attn_kernel()
{
    extern __shared__ float sm[];
    float* Qts = sm;
    float* Kts = sm + 64*ATPAD;
    float* Vs  = sm + 2*64*ATPAD;
    float* Pst = sm + 3*64*ATPAD;
    int tid = threadIdx.x;
    int tx = tid & 15, ty = tid >> 4;
    int q0 = blockIdx.x * 64;
    int h = blockIdx.y, b = blockIdx.z;
    size_t base = ((size_t)(b*NH_ + h))*SEQL*HD_;
    const float* Qb = g_q + base;
    const float* Kb = g_k + base;
    const float* Vb = g_v + base;

    {
        int rr = tid >> 4;
        int d4 = (tid & 15) * 4;
        #pragma unroll
        for (int r0 = 0; r0 < 64; r0 += 16) {
            int r = rr + r0;
            float4 vq = *(const float4*)(Qb + (size_t)(q0 + r)*HD_ + d4);
            Qts[(d4+0)*ATPAD + r] = vq.x;
            Qts[(d4+1)*ATPAD + r] = vq.y;
            Qts[(d4+2)*ATPAD + r] = vq.z;
            Qts[(d4+3)*ATPAD + r] = vq.w;
        }
    }

    float mrun[4], lrun[4], oacc[4][4];
    #pragma unroll
    for (int i = 0; i < 4; i++) {
        mrun[i] = -1e30f; lrun[i] = 0.f;
        #pragma unroll
        for (int j = 0; j < 4; j++) oacc[i][j] = 0.f;
    }

    for (int k0 = 0; k0 < SEQL; k0 += 64) {
        __syncthreads();
        {
            int rr = tid >> 4;
            int d4 = (tid & 15) * 4;
            #pragma unroll
            for (int r0 = 0; r0 < 64; r0 += 16) {
                int r = rr + r0;
                float4 kv = *(const float4*)(Kb + (size_t)(k0 + r)*HD_ + d4);
                Kts[(d4+0)*ATPAD + r] = kv.x;
                Kts[(d4+1)*ATPAD + r] = kv.y;
                Kts[(d4+2)*ATPAD + r] = kv.z;
                Kts[(d4+3)*ATPAD + r] = kv.w;
                float4 vv = *(const float4*)(Vb + (size_t)(k0 + r)*HD_ + d4);
                *(float4*)&Vs[r*ATPAD + d4] = vv;
            }
        }
        __syncthreads();

        float s[4][4];
        #pragma unroll
        for (int i = 0; i < 4; i++)
            #pragma unroll
            for (int j = 0; j < 4; j++) s[i][j] = 0.f;
        #pragma unroll 16
        for (int d = 0; d < 64; ++d) {
            float4 qa = *(const float4*)&Qts[d*ATPAD + ty*4];
            float4 kb = *(const float4*)&Kts[d*ATPAD + tx*4];
            float qr[4] = {qa.x,qa.y,qa.z,qa.w};
            float kr[4] = {kb.x,kb.y,kb.z,kb.w};
            #pragma unroll
            for (int i = 0; i < 4; i++)
                #pragma unroll
                for (int j = 0; j < 4; j++)
                    s[i][j] = fmaf(qr[i], kr[j], s[i][j]);
        }

        #pragma unroll
        for (int rr = 0; rr < 4; ++rr) {
            #pragma unroll
            for (int cc = 0; cc < 4; cc++) s[rr][cc] *= 8.0f;
            float tm = fmaxf(fmaxf(s[rr][0], s[rr][1]), fmaxf(s[rr][2], s[rr][3]));
            #pragma unroll
            for (int o = 1; o < 16; o <<= 1)
                tm = fmaxf(tm, __shfl_xor_sync(0xffffffffu, tm, o));
            float mn = fmaxf(mrun[rr], tm);
            float f = __expf(mrun[rr] - mn);
            float rs = 0.f;
            #pragma unroll
            for (int cc = 0; cc < 4; cc++) {
                float p = __expf(s[rr][cc] - mn);
                s[rr][cc] = p; rs += p;
            }
            #pragma unroll
            for (int o = 1; o < 16; o <<= 1)
                rs += __shfl_xor_sync(0xffffffffu, rs, o);
            lrun[rr] = lrun[rr]*f + rs;
            mrun[rr] = mn;
            #pragma unroll
            for (int cc = 0; cc < 4; cc++) oacc[rr][cc] *= f;
            #pragma unroll
            for (int cc = 0; cc < 4; cc++)
                Pst[(tx*4 + cc)*ATPAD + ty*4 + rr] = s[rr][cc];
        }
        __syncthreads();

        #pragma unroll 16
        for (int c = 0; c < 64; ++c) {
            float4 pa = *(const float4*)&Pst[c*ATPAD + ty*4];
            float4 vb = *(const float4*)&Vs[c*ATPAD + tx*4];
            float pr[4] = {pa.x,pa.y,pa.z,pa.w};
            float vr[4] = {vb.x,vb.y,vb.z,vb.w};
            #pragma unroll
            for (int i = 0; i < 4; i++)
                #pragma unroll
                for (int j = 0; j < 4; j++)
                    oacc[i][j] = fmaf(pr[i], vr[j], oacc[i][j]);
        }
    }

    #pragma unroll
    for (int rr = 0; rr < 4; ++rr) {
        float inv = 1.0f / lrun[rr];
        size_t oi = ((size_t)(b*SEQL) + q0 + ty*4 + rr)*DIM_ + h*HD_ + tx*4;
        __nv_bfloat162 p0, p1;
        p0.x = __float2bfloat16(oacc[rr][0]*inv);
        p0.y = __float2bfloat16(oacc[rr][1]*inv);
        p1.x = __float2bfloat16(oacc[rr][2]*inv);
        p1.y = __float2bfloat16(oacc[rr][3]*inv);
        *(__nv_bfloat162*)(g_attnb + oi)     = p0;
        *(__nv_bfloat162*)(g_attnb + oi + 2) = p1;
    }
}

// ------------- combine ------------------------------------------------------
__device__ __forceinline__ float block_sum(float v, float* shm)
{
    #pragma unroll
    for (int o = 16; o; o >>= 1) v += __shfl_xor_sync(0xffffffffu, v, o);
    __syncthreads();
    if ((threadIdx.x & 31) == 0) shm[threadIdx.x >> 5] = v;
    __syncthreads();
    if (threadIdx.x < 32) {
        float t = (threadIdx.x < 8) ? shm[threadIdx.x] : 0.f;
        #pragma unroll
        for (int o = 4; o; o >>= 1) t += __shfl_xor_sync(0xffffffffu, t, o);
        if (threadIdx.x == 0) shm[0] = t;
    }
    __syncthreads();
    return shm[0];
}

__global__ __launch_bounds__(256) void combine_kernel(const float* __restrict__ X,
                                                      const float* __restrict__ H,
                                                      const float* __restrict__ alpha,
                                                      float* __restrict__ Out)
{
    __shared__ float shm[8];
    int row = blockIdx.x;
    const float* xp = X + (size_t)row*DIM_;
    const float* hp = H + (size_t)row*DIM_;
    float xv[4], hv[4];
    float sx = 0.f, sh = 0.f;
    #pragma unroll
    for (int i = 0; i < 4; i++) {
        int j = threadIdx.x + i*256;
        xv[i] = xp[j]; hv[i] = hp[j];
        sx = fmaf(xv[i], xv[i], sx);
        sh = fmaf(hv[i], hv[i], sh);
    }
    float nx = block_sum(sx, shm);
    float nh = block_sum(sh, shm);
    float invx = 1.0f / fmaxf(sqrtf(nx), 1e-12f);
    float invh = 1.0f / fmaxf(sqrtf(nh), 1e-12f);
    float yv[4]; float sy = 0.f;
    #pragma unroll
    for (int i = 0; i < 4; i++) {
        int j = threadIdx.x + i*256;
        float lr = fabsf(alpha[j] * 1.6f);
        float hn = xv[i]*invx;
        float y = hn + lr*(hv[i]*invh - hn);
        yv[i] = y; sy = fmaf(y, y, sy);
    }
    float ny = block_sum(sy, shm);
    float invy = 1.0f / fmaxf(sqrtf(ny), 1e-12f);
    #pragma unroll
    for (int i = 0; i < 4; i++)
        Out[(size_t)row*DIM_ + threadIdx.x + i*256] = yv[i]*invy;
}

// ------------- swiglu gate -> bf16 ------------------------------------------
__global__ void hmid_kernel(const float* __restrict__ su, const float* __restrict__ sv)
{
    int idx = blockIdx.x*256 + threadIdx.x;
    int j = idx % HID_;
    float z = g_g1[idx] * sv[j] * 53.06599665f;
    float sg = 1.0f / (1.0f + __expf(-z));
    g_hhb[idx] = __float2bfloat16(z * sg * (g_g3[idx] * su[j]));
}

// ------------------------------- launcher ------------------------------------
extern "C" void kernel_launch(void* const* d_in, const int* in_sizes, int n_in,
                              void* d_out, int out_size)
{
    const float* x   = (const float*)d_in[0];
    const float* fc  = (const float*)d_in[1];
    const float* fs  = (const float*)d_in[2];
    const float* ada = (const float*)d_in[3];
    const float* wq  = (const float*)d_in[4];
    const float* wk  = (const float*)d_in[5];
    const float* wv  = (const float*)d_in[6];
    const float* wo  = (const float*)d_in[7];
    const float* sqk = (const float*)d_in[8];
    const float* w1  = (const float*)d_in[9];
    const float* w2  = (const float*)d_in[10];
    const float* w3  = (const float*)d_in[11];
    const float* su  = (const float*)d_in[12];
    const float* sv  = (const float*)d_in[13];
    const float* pw  = (const float*)d_in[14];
    const float* pb  = (const float*)d_in[15];
    const float* aat = (const float*)d_in[16];
    const float* aml = (const float*)d_in[17];
    float* out = (float*)d_out;

    float *qraw, *kraw, *vraw, *ha, *x1, *g1, *g3, *hm;
    __nv_bfloat16 *xmodb, *attnb, *x1mb, *hhb;
    __nv_bfloat16 *wqt, *wkt, *wvt, *wot, *w1t, *w3t, *w2t;
    cudaGetSymbolAddress((void**)&qraw, g_qraw);
    cudaGetSymbolAddress((void**)&kraw, g_kraw);
    cudaGetSymbolAddress((void**)&vraw, g_vraw);
    cudaGetSymbolAddress((void**)&ha,   g_ha);
    cudaGetSymbolAddress((void**)&x1,   g_x1);
    cudaGetSymbolAddress((void**)&g1,   g_g1);
    cudaGetSymbolAddress((void**)&g3,   g_g3);
    cudaGetSymbolAddress((void**)&hm,   g_hm);
    cudaGetSymbolAddress((void**)&xmodb, g_xmodb);
    cudaGetSymbolAddress((void**)&attnb, g_attnb);
    cudaGetSymbolAddress((void**)&x1mb,  g_x1mb);
    cudaGetSymbolAddress((void**)&hhb,   g_hhb);
    cudaGetSymbolAddress((void**)&wqt, g_wqt);
    cudaGetSymbolAddress((void**)&wkt, g_wkt);
    cudaGetSymbolAddress((void**)&wvt, g_wvt);
    cudaGetSymbolAddress((void**)&wot, g_wot);
    cudaGetSymbolAddress((void**)&w1t, g_w1t);
    cudaGetSymbolAddress((void**)&w3t, g_w3t);
    cudaGetSymbolAddress((void**)&w2t, g_w2t);

    cudaFuncSetAttribute(attn_kernel, cudaFuncAttributeMaxDynamicSharedMemorySize, ATT_SMEM);

    // 0. weight transposes (bf16, [N][K])
    wtrans_kernel<<<dim3(DIM_/32, DIM_/32), dim3(32,8)>>>(wq, wqt, DIM_, DIM_);
    wtrans_kernel<<<dim3(DIM_/32, DIM_/32), dim3(32,8)>>>(wk, wkt, DIM_, DIM_);
    wtrans_kernel<<<dim3(DIM_/32, DIM_/32), dim3(32,8)>>>(wv, wvt, DIM_, DIM_);
    wtrans_kernel<<<dim3(DIM_/32, DIM_/32), dim3(32,8)>>>(wo, wot, DIM_, DIM_);
    wtrans_kernel<<<dim3(HID_/32, DIM_/32), dim3(32,8)>>>(w1, w1t, DIM_, HID_);
    wtrans_kernel<<<dim3(HID_/32, DIM_/32), dim3(32,8)>>>(w3, w3t, DIM_, HID_);
    wtrans_kernel<<<dim3(DIM_/32, HID_/32), dim3(32,8)>>>(w2, w2t, HID_, DIM_);

    // 1. adafm projection + conv kernels
    proj_kernel<<<dim3(2, 2), 256>>>(ada, pw, pb);
    kconv_kernel<<<dim3(2, 2), 256>>>();

    // 2. attention branch
    modulate_kernel<<<dim3(64, 128, B_), 256>>>(x, xmodb, 0);
    tgemm_kernel<<<dim3(DIM_/128, NTOK/128), 256>>>(xmodb, wqt, qraw, NTOK, DIM_, DIM_);
    tgemm_kernel<<<dim3(DIM_/128, NTOK/128), 256>>>(xmodb, wkt, kraw, NTOK, DIM_, DIM_);
    tgemm_kernel<<<dim3(DIM_/128, NTOK/128), 256>>>(xmodb, wvt, vraw, NTOK, DIM_, DIM_);
    rotnorm_kernel<<<NTOK, 512>>>(fc, fs, sqk);
    attn_kernel<<<dim3(SEQL/64, NH_, B_), 256, ATT_SMEM>>>();
    tgemm_kernel<<<dim3(DIM_/128, NTOK/128), 256>>>(attnb, wot, ha, NTOK, DIM_, DIM_);
    combine_kernel<<<NTOK, 256>>>(x, ha, aat, x1);

    // 3. mlp branch
    modulate_kernel<<<dim3(64, 128, B_), 256>>>(x1, x1mb, 1);
    tgemm_kernel<<<dim3(HID_/128, NTOK/128), 256>>>(x1mb, w1t, g1, NTOK, HID_, DIM_);
    tgemm_kernel<<<dim3(HID_/128, NTOK/128), 256>>>(x1mb, w3t, g3, NTOK, HID_, DIM_);
    hmid_kernel<<<(NTOK*HID_)/256, 256>>>(su, sv);
    tgemm_kernel<<<dim3(DIM_/128, NTOK/128), 256>>>(hhb, w2t, hm, NTOK, DIM_, HID_);
    combine_kernel<<<NTOK, 256>>>(x1, hm, aml, out);
}

// round 5
// speedup vs baseline: 4.5057x; 1.5917x over previous
#include <cuda_runtime.h>
#include <cuda_bf16.h>
#include <math.h>
#include <cstdint>

#define B_    2
#define SEQL  2048
#define DIM_  1024
#define NH_   16
#define HD_   64
#define HID_  2816
#define NTOK  (B_*SEQL)          // 4096

// ---------------- scratch (device globals; no allocations allowed) ----------
__device__ float g_t[B_*512];
__device__ float g_kc[4*256];
__device__ float g_qraw[NTOK*DIM_];
__device__ float g_kraw[NTOK*DIM_];
__device__ float g_vraw[NTOK*DIM_];
__device__ float g_ha[NTOK*DIM_];
__device__ float g_x1[NTOK*DIM_];
__device__ float g_hm[NTOK*DIM_];
__device__ float g_g1[NTOK*HID_];
__device__ float g_g3[NTOK*HID_];
// bf16 activations
__device__ __nv_bfloat16 g_qb[NTOK*DIM_];   // [B][NH][S][64], q pre-scaled by 8
__device__ __nv_bfloat16 g_kb[NTOK*DIM_];
__device__ __nv_bfloat16 g_vb[NTOK*DIM_];
__device__ __nv_bfloat16 g_xmodb[NTOK*DIM_];
__device__ __nv_bfloat16 g_attnb[NTOK*DIM_];
__device__ __nv_bfloat16 g_x1mb[NTOK*DIM_];
__device__ __nv_bfloat16 g_hhb[NTOK*HID_];
// bf16 transposed weights [N][K]
__device__ __nv_bfloat16 g_wqt[DIM_*DIM_];
__device__ __nv_bfloat16 g_wkt[DIM_*DIM_];
__device__ __nv_bfloat16 g_wvt[DIM_*DIM_];
__device__ __nv_bfloat16 g_wot[DIM_*DIM_];
__device__ __nv_bfloat16 g_w1t[HID_*DIM_];
__device__ __nv_bfloat16 g_w3t[HID_*DIM_];
__device__ __nv_bfloat16 g_w2t[DIM_*HID_];

// ====================== mma.sync helpers (family-safe) =======================
__device__ __forceinline__ uint32_t smem_u32(const void* p) {
    uint32_t a;
    asm("{ .reg .u64 t; cvta.to.shared.u64 t, %1; cvt.u32.u64 %0, t; }" : "=r"(a) : "l"(p));
    return a;
}
__device__ __forceinline__ void ldsm_x4(uint32_t* r, uint32_t addr) {
    asm volatile("ldmatrix.sync.aligned.m8n8.x4.shared.b16 {%0,%1,%2,%3}, [%4];"
                 : "=r"(r[0]), "=r"(r[1]), "=r"(r[2]), "=r"(r[3]) : "r"(addr));
}
__device__ __forceinline__ void ldsm_x2(uint32_t* r, uint32_t addr) {
    asm volatile("ldmatrix.sync.aligned.m8n8.x2.shared.b16 {%0,%1}, [%2];"
                 : "=r"(r[0]), "=r"(r[1]) : "r"(addr));
}
__device__ __forceinline__ void ldsm_x2t(uint32_t* r, uint32_t addr) {
    asm volatile("ldmatrix.sync.aligned.m8n8.x2.trans.shared.b16 {%0,%1}, [%2];"
                 : "=r"(r[0]), "=r"(r[1]) : "r"(addr));
}
__device__ __forceinline__ void mma16816(float* c, const uint32_t* a, const uint32_t* b) {
    asm volatile("mma.sync.aligned.m16n8k16.row.col.f32.bf16.bf16.f32 "
                 "{%0,%1,%2,%3}, {%4,%5,%6,%7}, {%8,%9}, {%0,%1,%2,%3};"
                 : "+f"(c[0]), "+f"(c[1]), "+f"(c[2]), "+f"(c[3])
                 : "r"(a[0]), "r"(a[1]), "r"(a[2]), "r"(a[3]), "r"(b[0]), "r"(b[1]));
}
__device__ __forceinline__ uint32_t packbf(float lo, float hi) {
    __nv_bfloat162 p = __floats2bfloat162_rn(lo, hi);
    return *(uint32_t*)&p;
}

// C[M,N] = A[M,K](row,bf16) @ Bt[N,K](row,bf16)^T. 128x128 tiles, K-chunk 32.
#define SPAD 40
__global__ __launch_bounds__(256) void tgemm_kernel(const __nv_bfloat16* __restrict__ A,
                                                    const __nv_bfloat16* __restrict__ Bt,
                                                    float* __restrict__ C,
                                                    int M, int N, int K)
{
    __shared__ __nv_bfloat16 sA[2][128][SPAD];
    __shared__ __nv_bfloat16 sB[2][128][SPAD];
    int tid = threadIdx.x, lane = tid & 31, wid = tid >> 5;
    int wr = wid >> 2, wc = wid & 3;
    int row0 = blockIdx.y * 128, col0 = blockIdx.x * 128;

    uint32_t sAb = smem_u32(&sA[0][0][0]);
    uint32_t sBb = smem_u32(&sB[0][0][0]);
    const uint32_t BUFB = 128 * SPAD * 2;

    int srow = tid >> 2, sseg = tid & 3;
    const __nv_bfloat16* Ag = A  + (size_t)(row0 + srow)*K + sseg*8;
    const __nv_bfloat16* Bg = Bt + (size_t)(col0 + srow)*K + sseg*8;

    float acc[4][4][4];
    #pragma unroll
    for (int i = 0; i < 4; i++)
        #pragma unroll
        for (int j = 0; j < 4; j++)
            #pragma unroll
            for (int q = 0; q < 4; q++) acc[i][j][q] = 0.f;

    {
        uint4 a0 = *(const uint4*)Ag;
        uint4 a1 = *(const uint4*)(Ag + (size_t)64*K);
        uint4 b0 = *(const uint4*)Bg;
        uint4 b1 = *(const uint4*)(Bg + (size_t)64*K);
        *(uint4*)&sA[0][srow][sseg*8]    = a0;
        *(uint4*)&sA[0][srow+64][sseg*8] = a1;
        *(uint4*)&sB[0][srow][sseg*8]    = b0;
        *(uint4*)&sB[0][srow+64][sseg*8] = b1;
    }
    __syncthreads();

    int NC = K >> 5;
    int aq = lane >> 3, arow = lane & 7;
    int a_r = (aq & 1)*8 + arow;
    int a_kb = (aq >> 1)*16;
    int b_l = lane & 15;
    int b_r = b_l & 7;
    int b_kb = (b_l >> 3)*16;

    for (int c = 0; c < NC; c++) {
        int cur = c & 1;
        uint4 pa0, pa1, pb0, pb1;
        if (c + 1 < NC) {
            const __nv_bfloat16* Ap = Ag + (size_t)(c+1)*32;
            const __nv_bfloat16* Bp = Bg + (size_t)(c+1)*32;
            pa0 = *(const uint4*)Ap;
            pa1 = *(const uint4*)(Ap + (size_t)64*K);
            pb0 = *(const uint4*)Bp;
            pb1 = *(const uint4*)(Bp + (size_t)64*K);
        }

        uint32_t aBase = sAb + cur*BUFB;
        uint32_t bBase = sBb + cur*BUFB;
        #pragma unroll
        for (int ks = 0; ks < 2; ks++) {
            uint32_t afr[4][4], bfr[4][2];
            #pragma unroll
            for (int mt = 0; mt < 4; mt++)
                ldsm_x4(afr[mt], aBase + (wr*64 + mt*16 + a_r)*(SPAD*2) + ks*32 + a_kb);
            #pragma unroll
            for (int nt = 0; nt < 4; nt++)
                ldsm_x2(bfr[nt], bBase + (wc*32 + nt*8 + b_r)*(SPAD*2) + ks*32 + b_kb);
            #pragma unroll
            for (int mt = 0; mt < 4; mt++)
                #pragma unroll
                for (int nt = 0; nt < 4; nt++)
                    mma16816(acc[mt][nt], afr[mt], bfr[nt]);
        }

        if (c + 1 < NC) {
            int nb = cur ^ 1;
            *(uint4*)&sA[nb][srow][sseg*8]    = pa0;
            *(uint4*)&sA[nb][srow+64][sseg*8] = pa1;
            *(uint4*)&sB[nb][srow][sseg*8]    = pb0;
            *(uint4*)&sB[nb][srow+64][sseg*8] = pb1;
        }
        __syncthreads();
    }

    int cr = lane >> 2, cc = (lane & 3)*2;
    #pragma unroll
    for (int mt = 0; mt < 4; mt++) {
        #pragma unroll
        for (int nt = 0; nt < 4; nt++) {
            size_t r0 = (size_t)(row0 + wr*64 + mt*16 + cr);
            int col = col0 + wc*32 + nt*8 + cc;
            *(float2*)(C + r0*N + col)      = make_float2(acc[mt][nt][0], acc[mt][nt][1]);
            *(float2*)(C + (r0+8)*N + col)  = make_float2(acc[mt][nt][2], acc[mt][nt][3]);
        }
    }
}

// -------- weight transpose + bf16 convert ------------------------------------
__global__ void wtrans_kernel(const float* __restrict__ W, __nv_bfloat16* __restrict__ Wt,
                              int K, int N)
{
    __shared__ float t[32][33];
    int tx = threadIdx.x, ty = threadIdx.y;
    int n = blockIdx.x*32 + tx;
    int k0 = blockIdx.y*32;
    #pragma unroll
    for (int j = 0; j < 32; j += 8)
        t[ty+j][tx] = W[(size_t)(k0+ty+j)*N + n];
    __syncthreads();
    int k = k0 + tx;
    int nb = blockIdx.x*32;
    #pragma unroll
    for (int j = 0; j < 32; j += 8)
        Wt[(size_t)(nb+ty+j)*K + k] = __float2bfloat16(t[tx][ty+j]);
}

// ---------------- adafm projection -------------------------------------------
__global__ void proj_kernel(const float* __restrict__ ada, const float* __restrict__ pw,
                            const float* __restrict__ pb)
{
    int j = blockIdx.x * blockDim.x + threadIdx.x;
    int b = blockIdx.y;
    float acc = pb[j];
    const float* ap = ada + b*DIM_;
    for (int d = 0; d < DIM_; ++d) {
        float a = ap[d];
        float s = a / (1.0f + __expf(-a));
        acc = fmaf(s, pw[d*512 + j], acc);
    }
    g_t[b*512 + j] = acc;
}

__global__ void kconv_kernel()
{
    int d = threadIdx.x;
    int which = blockIdx.x, b = blockIdx.y;
    const float* F = g_t + b*512 + which*256;
    float acc = 0.f;
    for (int m = 0; m < 256; ++m) {
        int md = (m * d) & 255;
        acc = fmaf(F[m], cospif((float)md * (1.0f/128.0f)), acc);
    }
    g_kc[(which*2 + b)*256 + d] = acc * (1.0f/256.0f);
}

// ------------- adafm modulate -> bf16 ----------------------------------------
__global__ __launch_bounds__(256) void modulate_kernel(const float* __restrict__ X,
                                                       __nv_bfloat16* __restrict__ Y, int which)
{
    __shared__ float xp[256];
    __shared__ float kk[256];
    int jb = blockIdx.x, ib = blockIdx.y, b = blockIdx.z;
    int n = threadIdx.x;
    int r = n >> 4, c = n & 15;
    size_t gi = ((size_t)(b*SEQL + ib*16 + r))*DIM_ + jb*16 + c;
    xp[n] = X[gi];
    kk[n] = g_kc[(which*2 + b)*256 + n];
    __syncthreads();
    float acc = 0.f;
    #pragma unroll 8
    for (int m = 0; m < 256; ++m)
        acc = fmaf(xp[m], kk[(n - m) & 255], acc);
    Y[gi] = __float2bfloat16(acc);
}

// ------------- rotary + justnorm -> bf16 q(×8)/k/v [B][H][S][64] -------------
__global__ __launch_bounds__(512) void rotnorm_kernel(const float* __restrict__ fc,
                                                      const float* __restrict__ fs,
                                                      const float* __restrict__ sqk)
{
    int row = blockIdx.x;
    int s = row & (SEQL - 1);
    int b = row >> 11;
    int h = threadIdx.x >> 5;
    int i = threadIdx.x & 31;
    float c = fc[s*32 + i], sn = fs[s*32 + i];
    size_t gin = (size_t)row*DIM_ + h*64 + 2*i;
    float qa = g_qraw[gin], qb = g_qraw[gin+1];
    float ka = g_kraw[gin], kb = g_kraw[gin+1];
    float ra = qa*c - qb*sn, rb = qa*sn + qb*c;
    float ta = ka*c - kb*sn, tb = ka*sn + kb*c;
    float sq = ra*ra + rb*rb, sk = ta*ta + tb*tb;
    #pragma unroll
    for (int o = 16; o; o >>= 1) {
        sq += __shfl_xor_sync(0xffffffffu, sq, o);
        sk += __shfl_xor_sync(0xffffffffu, sk, o);
    }
    float invq = 1.0f / fmaxf(sqrtf(sq), 1e-12f);
    float invk = 1.0f / fmaxf(sqrtf(sk), 1e-12f);
    float sa = sqk[h*64 + 2*i]   * 32.0f;
    float sb = sqk[h*64 + 2*i+1] * 32.0f;
    size_t go = ((size_t)(b*NH_ + h)*SEQL + s)*64 + 2*i;
    // fold score scale sqrt(HD)=8 into q
    *(__nv_bfloat162*)(g_qb + go) = __floats2bfloat162_rn(ra*invq*sa*8.0f, rb*invq*sb*8.0f);
    *(__nv_bfloat162*)(g_kb + go) = __floats2bfloat162_rn(ta*invk*sa, tb*invk*sb);
    *(__nv_bfloat162*)(g_vb + go) = __floats2bfloat162_rn(g_vraw[gin], g_vraw[gin+1]);
}

// ------------- flash attention, bf16 mma.sync --------------------------------
// CTA: 128 q rows, 8 warps x 16 rows. KV tiles of 64. Smem rows padded to 72.
#define APAD 72
__global__ __launch_bounds__(256) void attn_kernel()
{
    __shared__ __nv_bfloat16 sQ[128][APAD];
    __shared__ __nv_bfloat16 sK[64][APAD];
    __shared__ __nv_bfloat16 sV[64][APAD];
    int tid = threadIdx.x, lane = tid & 31, wid = tid >> 5;
    int q0 = blockIdx.x * 128;
    int h = blockIdx.y, b = blockIdx.z;
    size_t base = ((size_t)(b*NH_ + h))*SEQL*HD_;
    const __nv_bfloat16* Qg = g_qb + base;
    const __nv_bfloat16* Kg = g_kb + base;
    const __nv_bfloat16* Vg = g_vb + base;

    // load Q tile (128x64)
    {
        int r = tid >> 1, c = (tid & 1)*32;
        const uint4* src = (const uint4*)(Qg + (size_t)(q0 + r)*64 + c);
        uint4 v0 = src[0], v1 = src[1], v2 = src[2], v3 = src[3];
        uint4* d = (uint4*)&sQ[r][c];
        d[0] = v0; d[1] = v1; d[2] = v2; d[3] = v3;
    }

    // prefetch KV tile 0
    int kvr = tid >> 2, kvc = (tid & 3)*16;
    uint4 pk0, pk1, pv0, pv1;
    {
        const __nv_bfloat16* Kt = Kg;
        const __nv_bfloat16* Vt = Vg;
        pk0 = *(const uint4*)(Kt + (size_t)kvr*64 + kvc);
        pk1 = *(const uint4*)(Kt + (size_t)kvr*64 + kvc + 8);
        pv0 = *(const uint4*)(Vt + (size_t)kvr*64 + kvc);
        pv1 = *(const uint4*)(Vt + (size_t)kvr*64 + kvc + 8);
    }
    __syncthreads();

    // Q fragments (held in registers for whole kernel)
    uint32_t aq[4][4];
    {
        int r = wid*16 + (lane & 15);
        int cb = (lane >> 4)*8;
        #pragma unroll
        for (int kc = 0; kc < 4; kc++)
            ldsm_x4(aq[kc], smem_u32(&sQ[r][kc*16 + cb]));
    }

    float mrun[2] = {-1e30f, -1e30f}, lrun[2] = {0.f, 0.f};
    float oacc[8][4];
    #pragma unroll
    for (int nf = 0; nf < 8; nf++)
        #pragma unroll
        for (int q = 0; q < 4; q++) oacc[nf][q] = 0.f;

    for (int t = 0; t < SEQL/64; t++) {
        // store prefetched KV tile
        *(uint4*)&sK[kvr][kvc]     = pk0;
        *(uint4*)&sK[kvr][kvc + 8] = pk1;
        *(uint4*)&sV[kvr][kvc]     = pv0;
        *(uint4*)&sV[kvr][kvc + 8] = pv1;
        __syncthreads();
        if (t + 1 < SEQL/64) {
            const __nv_bfloat16* Kt = Kg + (size_t)(t+1)*64*64;
            const __nv_bfloat16* Vt = Vg + (size_t)(t+1)*64*64;
            pk0 = *(const uint4*)(Kt + (size_t)kvr*64 + kvc);
            pk1 = *(const uint4*)(Kt + (size_t)kvr*64 + kvc + 8);
            pv0 = *(const uint4*)(Vt + (size_t)kvr*64 + kvc);
            pv1 = *(const uint4*)(Vt + (size_t)kvr*64 + kvc + 8);
        }

        // S = Q K^T  (scale already folded into q)
        float s[8][4];
        #pragma unroll
        for (int nf = 0; nf < 8; nf++)
            #pragma unroll
            for (int q = 0; q < 4; q++) s[nf][q] = 0.f;
        #pragma unroll
        for (int kc = 0; kc < 4; kc++) {
            #pragma unroll
            for (int nf = 0; nf < 8; nf++) {
                uint32_t bk[2];
                ldsm_x2(bk, smem_u32(&sK[nf*8 + (lane & 7)][kc*16 + ((lane >> 3) & 1)*8]));
                mma16816(s[nf], aq[kc], bk);
            }
        }

        // online softmax (rows r0 = lane>>2 and r0+8)
        #pragma unroll
        for (int hh = 0; hh < 2; hh++) {
            float tm = -1e30f;
            #pragma unroll
            for (int nf = 0; nf < 8; nf++)
                tm = fmaxf(tm, fmaxf(s[nf][hh*2], s[nf][hh*2+1]));
            tm = fmaxf(tm, __shfl_xor_sync(0xffffffffu, tm, 1));
            tm = fmaxf(tm, __shfl_xor_sync(0xffffffffu, tm, 2));
            float mn = fmaxf(mrun[hh], tm);
            float f = __expf(mrun[hh] - mn);
            float rs = 0.f;
            #pragma unroll
            for (int nf = 0; nf < 8; nf++) {
                float p0 = __expf(s[nf][hh*2]   - mn);
                float p1 = __expf(s[nf][hh*2+1] - mn);
                s[nf][hh*2] = p0; s[nf][hh*2+1] = p1;
                rs += p0 + p1;
            }
            rs += __shfl_xor_sync(0xffffffffu, rs, 1);
            rs += __shfl_xor_sync(0xffffffffu, rs, 2);
            lrun[hh] = lrun[hh]*f + rs;
            mrun[hh] = mn;
            #pragma unroll
            for (int nf = 0; nf < 8; nf++) {
                oacc[nf][hh*2]   *= f;
                oacc[nf][hh*2+1] *= f;
            }
        }

        // P -> bf16 A-fragments (C-frag layout == A-frag layout)
        uint32_t pf[4][4];
        #pragma unroll
        for (int kc = 0; kc < 4; kc++) {
            pf[kc][0] = packbf(s[2*kc][0],   s[2*kc][1]);
            pf[kc][1] = packbf(s[2*kc][2],   s[2*kc][3]);
            pf[kc][2] = packbf(s[2*kc+1][0], s[2*kc+1][1]);
            pf[kc][3] = packbf(s[2*kc+1][2], s[2*kc+1][3]);
        }

        // O += P V   (V fragments via ldmatrix.trans)
        #pragma unroll
        for (int nf = 0; nf < 8; nf++) {
            #pragma unroll
            for (int kc = 0; kc < 4; kc++) {
                uint32_t bv[2];
                ldsm_x2t(bv, smem_u32(&sV[kc*16 + (lane & 15)][nf*8]));
                mma16816(oacc[nf], pf[kc], bv);
            }
        }
        __syncthreads();
    }

    // epilogue: normalize and store bf16 to [B][S][H*64]
    int r0 = wid*16 + (lane >> 2);
    #pragma unroll
    for (int hh = 0; hh < 2; hh++) {
        float inv = 1.0f / lrun[hh];
        int row = q0 + r0 + hh*8;
        size_t o = ((size_t)(b*SEQL) + row)*DIM_ + h*64 + (lane & 3)*2;
        #pragma unroll
        for (int nf = 0; nf < 8; nf++) {
            __nv_bfloat162 p = __floats2bfloat162_rn(oacc[nf][hh*2]*inv, oacc[nf][hh*2+1]*inv);
            *(__nv_bfloat162*)(g_attnb + o + nf*8) = p;
        }
    }
}

// ------------- combine --------------------------------------------------------
__device__ __forceinline__ float block_sum(float v, float* shm)
{
    #pragma unroll
    for (int o = 16; o; o >>= 1) v += __shfl_xor_sync(0xffffffffu, v, o);
    __syncthreads();
    if ((threadIdx.x & 31) == 0) shm[threadIdx.x >> 5] = v;
    __syncthreads();
    if (threadIdx.x < 32) {
        float t = (threadIdx.x < 8) ? shm[threadIdx.x] : 0.f;
        #pragma unroll
        for (int o = 4; o; o >>= 1) t += __shfl_xor_sync(0xffffffffu, t, o);
        if (threadIdx.x == 0) shm[0] = t;
    }
    __syncthreads();
    return shm[0];
}

__global__ __launch_bounds__(256) void combine_kernel(const float* __restrict__ X,
                                                      const float* __restrict__ H,
                                                      const float* __restrict__ alpha,
                                                      float* __restrict__ Out)
{
    __shared__ float shm[8];
    int row = blockIdx.x;
    const float* xp = X + (size_t)row*DIM_;
    const float* hp = H + (size_t)row*DIM_;
    float xv[4], hv[4];
    float sx = 0.f, sh = 0.f;
    #pragma unroll
    for (int i = 0; i < 4; i++) {
        int j = threadIdx.x + i*256;
        xv[i] = xp[j]; hv[i] = hp[j];
        sx = fmaf(xv[i], xv[i], sx);
        sh = fmaf(hv[i], hv[i], sh);
    }
    float nx = block_sum(sx, shm);
    float nh = block_sum(sh, shm);
    float invx = 1.0f / fmaxf(sqrtf(nx), 1e-12f);
    float invh = 1.0f / fmaxf(sqrtf(nh), 1e-12f);
    float yv[4]; float sy = 0.f;
    #pragma unroll
    for (int i = 0; i < 4; i++) {
        int j = threadIdx.x + i*256;
        float lr = fabsf(alpha[j] * 1.6f);
        float hn = xv[i]*invx;
        float y = hn + lr*(hv[i]*invh - hn);
        yv[i] = y; sy = fmaf(y, y, sy);
    }
    float ny = block_sum(sy, shm);
    float invy = 1.0f / fmaxf(sqrtf(ny), 1e-12f);
    #pragma unroll
    for (int i = 0; i < 4; i++)
        Out[(size_t)row*DIM_ + threadIdx.x + i*256] = yv[i]*invy;
}

// ------------- swiglu gate -> bf16 --------------------------------------------
__global__ void hmid_kernel(const float* __restrict__ su, const float* __restrict__ sv)
{
    int idx = blockIdx.x*256 + threadIdx.x;
    int j = idx % HID_;
    float z = g_g1[idx] * sv[j] * 53.06599665f;
    float sg = 1.0f / (1.0f + __expf(-z));
    g_hhb[idx] = __float2bfloat16(z * sg * (g_g3[idx] * su[j]));
}

// ------------------------------- launcher -------------------------------------
extern "C" void kernel_launch(void* const* d_in, const int* in_sizes, int n_in,
                              void* d_out, int out_size)
{
    const float* x   = (const float*)d_in[0];
    const float* fc  = (const float*)d_in[1];
    const float* fs  = (const float*)d_in[2];
    const float* ada = (const float*)d_in[3];
    const float* wq  = (const float*)d_in[4];
    const float* wk  = (const float*)d_in[5];
    const float* wv  = (const float*)d_in[6];
    const float* wo  = (const float*)d_in[7];
    const float* sqk = (const float*)d_in[8];
    const float* w1  = (const float*)d_in[9];
    const float* w2  = (const float*)d_in[10];
    const float* w3  = (const float*)d_in[11];
    const float* su  = (const float*)d_in[12];
    const float* sv  = (const float*)d_in[13];
    const float* pw  = (const float*)d_in[14];
    const float* pb  = (const float*)d_in[15];
    const float* aat = (const float*)d_in[16];
    const float* aml = (const float*)d_in[17];
    float* out = (float*)d_out;

    float *qraw, *kraw, *vraw, *ha, *x1, *g1, *g3, *hm;
    __nv_bfloat16 *xmodb, *attnb, *x1mb, *hhb;
    __nv_bfloat16 *wqt, *wkt, *wvt, *wot, *w1t, *w3t, *w2t;
    cudaGetSymbolAddress((void**)&qraw, g_qraw);
    cudaGetSymbolAddress((void**)&kraw, g_kraw);
    cudaGetSymbolAddress((void**)&vraw, g_vraw);
    cudaGetSymbolAddress((void**)&ha,   g_ha);
    cudaGetSymbolAddress((void**)&x1,   g_x1);
    cudaGetSymbolAddress((void**)&g1,   g_g1);
    cudaGetSymbolAddress((void**)&g3,   g_g3);
    cudaGetSymbolAddress((void**)&hm,   g_hm);
    cudaGetSymbolAddress((void**)&xmodb, g_xmodb);
    cudaGetSymbolAddress((void**)&attnb, g_attnb);
    cudaGetSymbolAddress((void**)&x1mb,  g_x1mb);
    cudaGetSymbolAddress((void**)&hhb,   g_hhb);
    cudaGetSymbolAddress((void**)&wqt, g_wqt);
    cudaGetSymbolAddress((void**)&wkt, g_wkt);
    cudaGetSymbolAddress((void**)&wvt, g_wvt);
    cudaGetSymbolAddress((void**)&wot, g_wot);
    cudaGetSymbolAddress((void**)&w1t, g_w1t);
    cudaGetSymbolAddress((void**)&w3t, g_w3t);
    cudaGetSymbolAddress((void**)&w2t, g_w2t);

    // 0. weight transposes (bf16, [N][K])
    wtrans_kernel<<<dim3(DIM_/32, DIM_/32), dim3(32,8)>>>(wq, wqt, DIM_, DIM_);
    wtrans_kernel<<<dim3(DIM_/32, DIM_/32), dim3(32,8)>>>(wk, wkt, DIM_, DIM_);
    wtrans_kernel<<<dim3(DIM_/32, DIM_/32), dim3(32,8)>>>(wv, wvt, DIM_, DIM_);
    wtrans_kernel<<<dim3(DIM_/32, DIM_/32), dim3(32,8)>>>(wo, wot, DIM_, DIM_);
    wtrans_kernel<<<dim3(HID_/32, DIM_/32), dim3(32,8)>>>(w1, w1t, DIM_, HID_);
    wtrans_kernel<<<dim3(HID_/32, DIM_/32), dim3(32,8)>>>(w3, w3t, DIM_, HID_);
    wtrans_kernel<<<dim3(DIM_/32, HID_/32), dim3(32,8)>>>(w2, w2t, HID_, DIM_);

    // 1. adafm projection + conv kernels
    proj_kernel<<<dim3(2, 2), 256>>>(ada, pw, pb);
    kconv_kernel<<<dim3(2, 2), 256>>>();

    // 2. attention branch
    modulate_kernel<<<dim3(64, 128, B_), 256>>>(x, xmodb, 0);
    tgemm_kernel<<<dim3(DIM_/128, NTOK/128), 256>>>(xmodb, wqt, qraw, NTOK, DIM_, DIM_);
    tgemm_kernel<<<dim3(DIM_/128, NTOK/128), 256>>>(xmodb, wkt, kraw, NTOK, DIM_, DIM_);
    tgemm_kernel<<<dim3(DIM_/128, NTOK/128), 256>>>(xmodb, wvt, vraw, NTOK, DIM_, DIM_);
    rotnorm_kernel<<<NTOK, 512>>>(fc, fs, sqk);
    attn_kernel<<<dim3(SEQL/128, NH_, B_), 256>>>();
    tgemm_kernel<<<dim3(DIM_/128, NTOK/128), 256>>>(attnb, wot, ha, NTOK, DIM_, DIM_);
    combine_kernel<<<NTOK, 256>>>(x, ha, aat, x1);

    // 3. mlp branch
    modulate_kernel<<<dim3(64, 128, B_), 256>>>(x1, x1mb, 1);
    tgemm_kernel<<<dim3(HID_/128, NTOK/128), 256>>>(x1mb, w1t, g1, NTOK, HID_, DIM_);
    tgemm_kernel<<<dim3(HID_/128, NTOK/128), 256>>>(x1mb, w3t, g3, NTOK, HID_, DIM_);
    hmid_kernel<<<(NTOK*HID_)/256, 256>>>(su, sv);
    tgemm_kernel<<<dim3(DIM_/128, NTOK/128), 256>>>(hhb, w2t, hm, NTOK, DIM_, HID_);
    combine_kernel<<<NTOK, 256>>>(x1, hm, aml, out);
}

// round 6
// speedup vs baseline: 4.5718x; 1.0147x over previous
#include <cuda_runtime.h>
#include <cuda_bf16.h>
#include <math.h>
#include <cstdint>

#define B_    2
#define SEQL  2048
#define DIM_  1024
#define NH_   16
#define HD_   64
#define HID_  2816
#define NTOK  (B_*SEQL)          // 4096
#define NQKV  (3*DIM_)           // 3072
#define N13   (2*HID_)           // 5632

// ---------------- scratch (device globals; no allocations allowed) ----------
__device__ float g_t[B_*512];
__device__ float g_kc[4*256];
__device__ float g_ha[NTOK*DIM_];
__device__ float g_x1[NTOK*DIM_];
__device__ float g_hm[NTOK*DIM_];
// bf16 activations
__device__ __nv_bfloat16 g_qkvb[NTOK*NQKV];  // fused qkv gemm out
__device__ __nv_bfloat16 g_g13b[NTOK*N13];   // fused w1/w3 gemm out
__device__ __nv_bfloat16 g_qb[NTOK*DIM_];    // [B][NH][S][64], q pre-scaled by 8
__device__ __nv_bfloat16 g_kb[NTOK*DIM_];
__device__ __nv_bfloat16 g_vb[NTOK*DIM_];
__device__ __nv_bfloat16 g_xmodb[NTOK*DIM_];
__device__ __nv_bfloat16 g_attnb[NTOK*DIM_];
__device__ __nv_bfloat16 g_x1mb[NTOK*DIM_];
__device__ __nv_bfloat16 g_hhb[NTOK*HID_];
// bf16 transposed weights [N][K]
__device__ __nv_bfloat16 g_wqkvt[NQKV*DIM_];
__device__ __nv_bfloat16 g_wot[DIM_*DIM_];
__device__ __nv_bfloat16 g_w13t[N13*DIM_];
__device__ __nv_bfloat16 g_w2t[DIM_*HID_];

// ====================== mma.sync helpers (family-safe) =======================
__device__ __forceinline__ uint32_t smem_u32(const void* p) {
    uint32_t a;
    asm("{ .reg .u64 t; cvta.to.shared.u64 t, %1; cvt.u32.u64 %0, t; }" : "=r"(a) : "l"(p));
    return a;
}
__device__ __forceinline__ void ldsm_x4(uint32_t* r, uint32_t addr) {
    asm volatile("ldmatrix.sync.aligned.m8n8.x4.shared.b16 {%0,%1,%2,%3}, [%4];"
                 : "=r"(r[0]), "=r"(r[1]), "=r"(r[2]), "=r"(r[3]) : "r"(addr));
}
__device__ __forceinline__ void ldsm_x2(uint32_t* r, uint32_t addr) {
    asm volatile("ldmatrix.sync.aligned.m8n8.x2.shared.b16 {%0,%1}, [%2];"
                 : "=r"(r[0]), "=r"(r[1]) : "r"(addr));
}
__device__ __forceinline__ void ldsm_x2t(uint32_t* r, uint32_t addr) {
    asm volatile("ldmatrix.sync.aligned.m8n8.x2.trans.shared.b16 {%0,%1}, [%2];"
                 : "=r"(r[0]), "=r"(r[1]) : "r"(addr));
}
__device__ __forceinline__ void mma16816(float* c, const uint32_t* a, const uint32_t* b) {
    asm volatile("mma.sync.aligned.m16n8k16.row.col.f32.bf16.bf16.f32 "
                 "{%0,%1,%2,%3}, {%4,%5,%6,%7}, {%8,%9}, {%0,%1,%2,%3};"
                 : "+f"(c[0]), "+f"(c[1]), "+f"(c[2]), "+f"(c[3])
                 : "r"(a[0]), "r"(a[1]), "r"(a[2]), "r"(a[3]), "r"(b[0]), "r"(b[1]));
}
__device__ __forceinline__ uint32_t packbf(float lo, float hi) {
    __nv_bfloat162 p = __floats2bfloat162_rn(lo, hi);
    return *(uint32_t*)&p;
}
#define CPASYNC16(saddr, gptr) \
    asm volatile("cp.async.cg.shared.global [%0], [%1], 16;" :: "r"(saddr), "l"(gptr))
#define CP_COMMIT() asm volatile("cp.async.commit_group;" ::: "memory")
#define CP_WAIT(n)  asm volatile("cp.async.wait_group %0;" :: "n"(n) : "memory")

// ============== cp.async 4-stage mma.sync GEMM ===============================
// C[M,N] = A[M,K](row,bf16) @ Bt[N,K](row,bf16)^T. 128x128 tiles, K-chunk 32.
#define SPAD 40
#define STG  4
#define STAGEB (2*128*SPAD*2)    // A+B bytes per stage (20480)
#define GEMM_SMEM (STG*STAGEB)   // 81920

template<typename OutT>
__global__ __launch_bounds__(256) void tgemm_kernel(const __nv_bfloat16* __restrict__ A,
                                                    const __nv_bfloat16* __restrict__ Bt,
                                                    OutT* __restrict__ C,
                                                    int M, int N, int K)
{
    extern __shared__ char smemraw[];
    uint32_t sbase = smem_u32(smemraw);
    int tid = threadIdx.x, lane = tid & 31, wid = tid >> 5;
    int wr = wid >> 2, wc = wid & 3;
    int row0 = blockIdx.y * 128, col0 = blockIdx.x * 128;

    int srow = tid >> 2, sseg = tid & 3;
    const __nv_bfloat16* Ag = A  + (size_t)(row0 + srow)*K + sseg*8;
    const __nv_bfloat16* Bg = Bt + (size_t)(col0 + srow)*K + sseg*8;
    uint32_t sAoff = srow*(SPAD*2) + sseg*16;          // byte offsets within stage
    uint32_t sAoff2 = (srow+64)*(SPAD*2) + sseg*16;
    uint32_t sBhalf = 128*SPAD*2;

    int NC = K >> 5;

    // prologue: stage chunks 0..STG-2
    #pragma unroll
    for (int s = 0; s < STG-1; s++) {
        uint32_t st = sbase + s*STAGEB;
        const __nv_bfloat16* Ap = Ag + (size_t)s*32;
        const __nv_bfloat16* Bp = Bg + (size_t)s*32;
        CPASYNC16(st + sAoff,  Ap);
        CPASYNC16(st + sAoff2, Ap + (size_t)64*K);
        CPASYNC16(st + sBhalf + sAoff,  Bp);
        CPASYNC16(st + sBhalf + sAoff2, Bp + (size_t)64*K);
        CP_COMMIT();
    }

    float acc[4][4][4];
    #pragma unroll
    for (int i = 0; i < 4; i++)
        #pragma unroll
        for (int j = 0; j < 4; j++)
            #pragma unroll
            for (int q = 0; q < 4; q++) acc[i][j][q] = 0.f;

    int aq = lane >> 3, arow = lane & 7;
    int a_r = (aq & 1)*8 + arow;
    int a_kb = (aq >> 1)*16;
    int b_l = lane & 15;
    int b_r = b_l & 7;
    int b_kb = (b_l >> 3)*16;

    int buf = 0;
    for (int c = 0; c < NC; c++) {
        CP_WAIT(STG-2);
        __syncthreads();

        // prefetch chunk c+STG-1 into the buffer freed by chunk c-1
        if (c + STG-1 < NC) {
            int pb = buf - 1; if (pb < 0) pb += STG;
            uint32_t st = sbase + pb*STAGEB;
            const __nv_bfloat16* Ap = Ag + (size_t)(c+STG-1)*32;
            const __nv_bfloat16* Bp = Bg + (size_t)(c+STG-1)*32;
            CPASYNC16(st + sAoff,  Ap);
            CPASYNC16(st + sAoff2, Ap + (size_t)64*K);
            CPASYNC16(st + sBhalf + sAoff,  Bp);
            CPASYNC16(st + sBhalf + sAoff2, Bp + (size_t)64*K);
        }
        CP_COMMIT();   // commit every iter so wait counts stay aligned

        uint32_t aBase = sbase + buf*STAGEB;
        uint32_t bBase = aBase + sBhalf;
        #pragma unroll
        for (int ks = 0; ks < 2; ks++) {
            uint32_t afr[4][4], bfr[4][2];
            #pragma unroll
            for (int mt = 0; mt < 4; mt++)
                ldsm_x4(afr[mt], aBase + (wr*64 + mt*16 + a_r)*(SPAD*2) + ks*32 + a_kb);
            #pragma unroll
            for (int nt = 0; nt < 4; nt++)
                ldsm_x2(bfr[nt], bBase + (wc*32 + nt*8 + b_r)*(SPAD*2) + ks*32 + b_kb);
            #pragma unroll
            for (int mt = 0; mt < 4; mt++)
                #pragma unroll
                for (int nt = 0; nt < 4; nt++)
                    mma16816(acc[mt][nt], afr[mt], bfr[nt]);
        }
        __syncthreads();
        buf++; if (buf == STG) buf = 0;
    }

    int cr = lane >> 2, cc = (lane & 3)*2;
    #pragma unroll
    for (int mt = 0; mt < 4; mt++) {
        #pragma unroll
        for (int nt = 0; nt < 4; nt++) {
            size_t r0 = (size_t)(row0 + wr*64 + mt*16 + cr);
            int col = col0 + wc*32 + nt*8 + cc;
            if constexpr (sizeof(OutT) == 4) {
                *(float2*)((float*)C + r0*N + col)     = make_float2(acc[mt][nt][0], acc[mt][nt][1]);
                *(float2*)((float*)C + (r0+8)*N + col) = make_float2(acc[mt][nt][2], acc[mt][nt][3]);
            } else {
                *(uint32_t*)((__nv_bfloat16*)C + r0*N + col)     = packbf(acc[mt][nt][0], acc[mt][nt][1]);
                *(uint32_t*)((__nv_bfloat16*)C + (r0+8)*N + col) = packbf(acc[mt][nt][2], acc[mt][nt][3]);
            }
        }
    }
}

// -------- weight transpose + bf16 convert ------------------------------------
__global__ void wtrans_kernel(const float* __restrict__ W, __nv_bfloat16* __restrict__ Wt,
                              int K, int N)
{
    __shared__ float t[32][33];
    int tx = threadIdx.x, ty = threadIdx.y;
    int n = blockIdx.x*32 + tx;
    int k0 = blockIdx.y*32;
    #pragma unroll
    for (int j = 0; j < 32; j += 8)
        t[ty+j][tx] = W[(size_t)(k0+ty+j)*N + n];
    __syncthreads();
    int k = k0 + tx;
    int nb = blockIdx.x*32;
    #pragma unroll
    for (int j = 0; j < 32; j += 8)
        Wt[(size_t)(nb+ty+j)*K + k] = __float2bfloat16(t[tx][ty+j]);
}

// ---------------- adafm projection -------------------------------------------
__global__ void proj_kernel(const float* __restrict__ ada, const float* __restrict__ pw,
                            const float* __restrict__ pb)
{
    int j = blockIdx.x * blockDim.x + threadIdx.x;
    int b = blockIdx.y;
    float acc = pb[j];
    const float* ap = ada + b*DIM_;
    for (int d = 0; d < DIM_; ++d) {
        float a = ap[d];
        float s = a / (1.0f + __expf(-a));
        acc = fmaf(s, pw[d*512 + j], acc);
    }
    g_t[b*512 + j] = acc;
}

__global__ void kconv_kernel()
{
    int d = threadIdx.x;
    int which = blockIdx.x, b = blockIdx.y;
    const float* F = g_t + b*512 + which*256;
    float acc = 0.f;
    for (int m = 0; m < 256; ++m) {
        int md = (m * d) & 255;
        acc = fmaf(F[m], cospif((float)md * (1.0f/128.0f)), acc);
    }
    g_kc[(which*2 + b)*256 + d] = acc * (1.0f/256.0f);
}

// ------------- adafm modulate -> bf16 ----------------------------------------
__global__ __launch_bounds__(256) void modulate_kernel(const float* __restrict__ X,
                                                       __nv_bfloat16* __restrict__ Y, int which)
{
    __shared__ float xp[256];
    __shared__ float kk[256];
    int jb = blockIdx.x, ib = blockIdx.y, b = blockIdx.z;
    int n = threadIdx.x;
    int r = n >> 4, c = n & 15;
    size_t gi = ((size_t)(b*SEQL + ib*16 + r))*DIM_ + jb*16 + c;
    xp[n] = X[gi];
    kk[n] = g_kc[(which*2 + b)*256 + n];
    __syncthreads();
    float acc = 0.f;
    #pragma unroll 8
    for (int m = 0; m < 256; ++m)
        acc = fmaf(xp[m], kk[(n - m) & 255], acc);
    Y[gi] = __float2bfloat16(acc);
}

// ------------- rotary + justnorm -> bf16 q(×8)/k/v [B][H][S][64] -------------
__global__ __launch_bounds__(512) void rotnorm_kernel(const float* __restrict__ fc,
                                                      const float* __restrict__ fs,
                                                      const float* __restrict__ sqk)
{
    int row = blockIdx.x;
    int s = row & (SEQL - 1);
    int b = row >> 11;
    int h = threadIdx.x >> 5;
    int i = threadIdx.x & 31;
    float c = fc[s*32 + i], sn = fs[s*32 + i];
    size_t gin = (size_t)row*NQKV + h*64 + 2*i;
    __nv_bfloat162 qv = *(const __nv_bfloat162*)(g_qkvb + gin);
    __nv_bfloat162 kv = *(const __nv_bfloat162*)(g_qkvb + gin + DIM_);
    __nv_bfloat162 vv = *(const __nv_bfloat162*)(g_qkvb + gin + 2*DIM_);
    float qa = __bfloat162float(qv.x), qb = __bfloat162float(qv.y);
    float ka = __bfloat162float(kv.x), kb = __bfloat162float(kv.y);
    float ra = qa*c - qb*sn, rb = qa*sn + qb*c;
    float ta = ka*c - kb*sn, tb = ka*sn + kb*c;
    float sq = ra*ra + rb*rb, sk = ta*ta + tb*tb;
    #pragma unroll
    for (int o = 16; o; o >>= 1) {
        sq += __shfl_xor_sync(0xffffffffu, sq, o);
        sk += __shfl_xor_sync(0xffffffffu, sk, o);
    }
    float invq = 1.0f / fmaxf(sqrtf(sq), 1e-12f);
    float invk = 1.0f / fmaxf(sqrtf(sk), 1e-12f);
    float sa = sqk[h*64 + 2*i]   * 32.0f;
    float sb = sqk[h*64 + 2*i+1] * 32.0f;
    size_t go = ((size_t)(b*NH_ + h)*SEQL + s)*64 + 2*i;
    *(__nv_bfloat162*)(g_qb + go) = __floats2bfloat162_rn(ra*invq*sa*8.0f, rb*invq*sb*8.0f);
    *(__nv_bfloat162*)(g_kb + go) = __floats2bfloat162_rn(ta*invk*sa, tb*invk*sb);
    *(__nv_bfloat162*)(g_vb + go) = vv;
}

// ------------- flash attention, bf16 mma.sync --------------------------------
#define APAD 72
__global__ __launch_bounds__(256) void attn_kernel()
{
    __shared__ __nv_bfloat16 sQ[128][APAD];
    __shared__ __nv_bfloat16 sK[64][APAD];
    __shared__ __nv_bfloat16 sV[64][APAD];
    int tid = threadIdx.x, lane = tid & 31, wid = tid >> 5;
    int q0 = blockIdx.x * 128;
    int h = blockIdx.y, b = blockIdx.z;
    size_t base = ((size_t)(b*NH_ + h))*SEQL*HD_;
    const __nv_bfloat16* Qg = g_qb + base;
    const __nv_bfloat16* Kg = g_kb + base;
    const __nv_bfloat16* Vg = g_vb + base;

    {
        int r = tid >> 1, c = (tid & 1)*32;
        const uint4* src = (const uint4*)(Qg + (size_t)(q0 + r)*64 + c);
        uint4 v0 = src[0], v1 = src[1], v2 = src[2], v3 = src[3];
        uint4* d = (uint4*)&sQ[r][c];
        d[0] = v0; d[1] = v1; d[2] = v2; d[3] = v3;
    }

    int kvr = tid >> 2, kvc = (tid & 3)*16;
    uint4 pk0, pk1, pv0, pv1;
    {
        pk0 = *(const uint4*)(Kg + (size_t)kvr*64 + kvc);
        pk1 = *(const uint4*)(Kg + (size_t)kvr*64 + kvc + 8);
        pv0 = *(const uint4*)(Vg + (size_t)kvr*64 + kvc);
        pv1 = *(const uint4*)(Vg + (size_t)kvr*64 + kvc + 8);
    }
    __syncthreads();

    uint32_t aq[4][4];
    {
        int r = wid*16 + (lane & 15);
        int cb = (lane >> 4)*8;
        #pragma unroll
        for (int kc = 0; kc < 4; kc++)
            ldsm_x4(aq[kc], smem_u32(&sQ[r][kc*16 + cb]));
    }

    float mrun[2] = {-1e30f, -1e30f}, lrun[2] = {0.f, 0.f};
    float oacc[8][4];
    #pragma unroll
    for (int nf = 0; nf < 8; nf++)
        #pragma unroll
        for (int q = 0; q < 4; q++) oacc[nf][q] = 0.f;

    for (int t = 0; t < SEQL/64; t++) {
        *(uint4*)&sK[kvr][kvc]     = pk0;
        *(uint4*)&sK[kvr][kvc + 8] = pk1;
        *(uint4*)&sV[kvr][kvc]     = pv0;
        *(uint4*)&sV[kvr][kvc + 8] = pv1;
        __syncthreads();
        if (t + 1 < SEQL/64) {
            const __nv_bfloat16* Kt = Kg + (size_t)(t+1)*64*64;
            const __nv_bfloat16* Vt = Vg + (size_t)(t+1)*64*64;
            pk0 = *(const uint4*)(Kt + (size_t)kvr*64 + kvc);
            pk1 = *(const uint4*)(Kt + (size_t)kvr*64 + kvc + 8);
            pv0 = *(const uint4*)(Vt + (size_t)kvr*64 + kvc);
            pv1 = *(const uint4*)(Vt + (size_t)kvr*64 + kvc + 8);
        }

        float s[8][4];
        #pragma unroll
        for (int nf = 0; nf < 8; nf++)
            #pragma unroll
            for (int q = 0; q < 4; q++) s[nf][q] = 0.f;
        #pragma unroll
        for (int kc = 0; kc < 4; kc++) {
            #pragma unroll
            for (int nf = 0; nf < 8; nf++) {
                uint32_t bk[2];
                ldsm_x2(bk, smem_u32(&sK[nf*8 + (lane & 7)][kc*16 + ((lane >> 3) & 1)*8]));
                mma16816(s[nf], aq[kc], bk);
            }
        }

        #pragma unroll
        for (int hh = 0; hh < 2; hh++) {
            float tm = -1e30f;
            #pragma unroll
            for (int nf = 0; nf < 8; nf++)
                tm = fmaxf(tm, fmaxf(s[nf][hh*2], s[nf][hh*2+1]));
            tm = fmaxf(tm, __shfl_xor_sync(0xffffffffu, tm, 1));
            tm = fmaxf(tm, __shfl_xor_sync(0xffffffffu, tm, 2));
            float mn = fmaxf(mrun[hh], tm);
            float f = __expf(mrun[hh] - mn);
            float rs = 0.f;
            #pragma unroll
            for (int nf = 0; nf < 8; nf++) {
                float p0 = __expf(s[nf][hh*2]   - mn);
                float p1 = __expf(s[nf][hh*2+1] - mn);
                s[nf][hh*2] = p0; s[nf][hh*2+1] = p1;
                rs += p0 + p1;
            }
            rs += __shfl_xor_sync(0xffffffffu, rs, 1);
            rs += __shfl_xor_sync(0xffffffffu, rs, 2);
            lrun[hh] = lrun[hh]*f + rs;
            mrun[hh] = mn;
            #pragma unroll
            for (int nf = 0; nf < 8; nf++) {
                oacc[nf][hh*2]   *= f;
                oacc[nf][hh*2+1] *= f;
            }
        }

        uint32_t pf[4][4];
        #pragma unroll
        for (int kc = 0; kc < 4; kc++) {
            pf[kc][0] = packbf(s[2*kc][0],   s[2*kc][1]);
            pf[kc][1] = packbf(s[2*kc][2],   s[2*kc][3]);
            pf[kc][2] = packbf(s[2*kc+1][0], s[2*kc+1][1]);
            pf[kc][3] = packbf(s[2*kc+1][2], s[2*kc+1][3]);
        }

        #pragma unroll
        for (int nf = 0; nf < 8; nf++) {
            #pragma unroll
            for (int kc = 0; kc < 4; kc++) {
                uint32_t bv[2];
                ldsm_x2t(bv, smem_u32(&sV[kc*16 + (lane & 15)][nf*8]));
                mma16816(oacc[nf], pf[kc], bv);
            }
        }
        __syncthreads();
    }

    int r0 = wid*16 + (lane >> 2);
    #pragma unroll
    for (int hh = 0; hh < 2; hh++) {
        float inv = 1.0f / lrun[hh];
        int row = q0 + r0 + hh*8;
        size_t o = ((size_t)(b*SEQL) + row)*DIM_ + h*64 + (lane & 3)*2;
        #pragma unroll
        for (int nf = 0; nf < 8; nf++) {
            __nv_bfloat162 p = __floats2bfloat162_rn(oacc[nf][hh*2]*inv, oacc[nf][hh*2+1]*inv);
            *(__nv_bfloat162*)(g_attnb + o + nf*8) = p;
        }
    }
}

// ------------- combine --------------------------------------------------------
__device__ __forceinline__ float block_sum(float v, float* shm)
{
    #pragma unroll
    for (int o = 16; o; o >>= 1) v += __shfl_xor_sync(0xffffffffu, v, o);
    __syncthreads();
    if ((threadIdx.x & 31) == 0) shm[threadIdx.x >> 5] = v;
    __syncthreads();
    if (threadIdx.x < 32) {
        float t = (threadIdx.x < 8) ? shm[threadIdx.x] : 0.f;
        #pragma unroll
        for (int o = 4; o; o >>= 1) t += __shfl_xor_sync(0xffffffffu, t, o);
        if (threadIdx.x == 0) shm[0] = t;
    }
    __syncthreads();
    return shm[0];
}

__global__ __launch_bounds__(256) void combine_kernel(const float* __restrict__ X,
                                                      const float* __restrict__ H,
                                                      const float* __restrict__ alpha,
                                                      float* __restrict__ Out)
{
    __shared__ float shm[8];
    int row = blockIdx.x;
    const float* xp = X + (size_t)row*DIM_;
    const float* hp = H + (size_t)row*DIM_;
    float xv[4], hv[4];
    float sx = 0.f, sh = 0.f;
    #pragma unroll
    for (int i = 0; i < 4; i++) {
        int j = threadIdx.x + i*256;
        xv[i] = xp[j]; hv[i] = hp[j];
        sx = fmaf(xv[i], xv[i], sx);
        sh = fmaf(hv[i], hv[i], sh);
    }
    float nx = block_sum(sx, shm);
    float nh = block_sum(sh, shm);
    float invx = 1.0f / fmaxf(sqrtf(nx), 1e-12f);
    float invh = 1.0f / fmaxf(sqrtf(nh), 1e-12f);
    float yv[4]; float sy = 0.f;
    #pragma unroll
    for (int i = 0; i < 4; i++) {
        int j = threadIdx.x + i*256;
        float lr = fabsf(alpha[j] * 1.6f);
        float hn = xv[i]*invx;
        float y = hn + lr*(hv[i]*invh - hn);
        yv[i] = y; sy = fmaf(y, y, sy);
    }
    float ny = block_sum(sy, shm);
    float invy = 1.0f / fmaxf(sqrtf(ny), 1e-12f);
    #pragma unroll
    for (int i = 0; i < 4; i++)
        Out[(size_t)row*DIM_ + threadIdx.x + i*256] = yv[i]*invy;
}

// ------------- swiglu gate (reads fused g13 bf16) -> bf16 --------------------
__global__ void hmid_kernel(const float* __restrict__ su, const float* __restrict__ sv)
{
    int j = blockIdx.x*256 + threadIdx.x;      // 0..HID_-1 (HID_ = 11*256)
    int row = blockIdx.y;
    float g1 = __bfloat162float(g_g13b[(size_t)row*N13 + j]);
    float g3 = __bfloat162float(g_g13b[(size_t)row*N13 + HID_ + j]);
    float z = g1 * sv[j] * 53.06599665f;
    float sg = 1.0f / (1.0f + __expf(-z));
    g_hhb[(size_t)row*HID_ + j] = __float2bfloat16(z * sg * (g3 * su[j]));
}

// ------------------------------- launcher -------------------------------------
extern "C" void kernel_launch(void* const* d_in, const int* in_sizes, int n_in,
                              void* d_out, int out_size)
{
    const float* x   = (const float*)d_in[0];
    const float* fc  = (const float*)d_in[1];
    const float* fs  = (const float*)d_in[2];
    const float* ada = (const float*)d_in[3];
    const float* wq  = (const float*)d_in[4];
    const float* wk  = (const float*)d_in[5];
    const float* wv  = (const float*)d_in[6];
    const float* wo  = (const float*)d_in[7];
    const float* sqk = (const float*)d_in[8];
    const float* w1  = (const float*)d_in[9];
    const float* w2  = (const float*)d_in[10];
    const float* w3  = (const float*)d_in[11];
    const float* su  = (const float*)d_in[12];
    const float* sv  = (const float*)d_in[13];
    const float* pw  = (const float*)d_in[14];
    const float* pb  = (const float*)d_in[15];
    const float* aat = (const float*)d_in[16];
    const float* aml = (const float*)d_in[17];
    float* out = (float*)d_out;

    float *ha, *x1, *hm;
    __nv_bfloat16 *xmodb, *attnb, *x1mb, *hhb, *qkvb, *g13b;
    __nv_bfloat16 *wqkvt, *wot, *w13t, *w2t;
    cudaGetSymbolAddress((void**)&ha,   g_ha);
    cudaGetSymbolAddress((void**)&x1,   g_x1);
    cudaGetSymbolAddress((void**)&hm,   g_hm);
    cudaGetSymbolAddress((void**)&xmodb, g_xmodb);
    cudaGetSymbolAddress((void**)&attnb, g_attnb);
    cudaGetSymbolAddress((void**)&x1mb,  g_x1mb);
    cudaGetSymbolAddress((void**)&hhb,   g_hhb);
    cudaGetSymbolAddress((void**)&qkvb,  g_qkvb);
    cudaGetSymbolAddress((void**)&g13b,  g_g13b);
    cudaGetSymbolAddress((void**)&wqkvt, g_wqkvt);
    cudaGetSymbolAddress((void**)&wot,   g_wot);
    cudaGetSymbolAddress((void**)&w13t,  g_w13t);
    cudaGetSymbolAddress((void**)&w2t,   g_w2t);

    cudaFuncSetAttribute(tgemm_kernel<float>, cudaFuncAttributeMaxDynamicSharedMemorySize, GEMM_SMEM);
    cudaFuncSetAttribute(tgemm_kernel<__nv_bfloat16>, cudaFuncAttributeMaxDynamicSharedMemorySize, GEMM_SMEM);

    // 0. weight transposes (bf16, [N][K]); qkv and w1/w3 packed contiguously
    wtrans_kernel<<<dim3(DIM_/32, DIM_/32), dim3(32,8)>>>(wq, wqkvt,               DIM_, DIM_);
    wtrans_kernel<<<dim3(DIM_/32, DIM_/32), dim3(32,8)>>>(wk, wqkvt + DIM_*DIM_,   DIM_, DIM_);
    wtrans_kernel<<<dim3(DIM_/32, DIM_/32), dim3(32,8)>>>(wv, wqkvt + 2*DIM_*DIM_, DIM_, DIM_);
    wtrans_kernel<<<dim3(DIM_/32, DIM_/32), dim3(32,8)>>>(wo, wot, DIM_, DIM_);
    wtrans_kernel<<<dim3(HID_/32, DIM_/32), dim3(32,8)>>>(w1, w13t,              DIM_, HID_);
    wtrans_kernel<<<dim3(HID_/32, DIM_/32), dim3(32,8)>>>(w3, w13t + HID_*DIM_,  DIM_, HID_);
    wtrans_kernel<<<dim3(DIM_/32, HID_/32), dim3(32,8)>>>(w2, w2t, HID_, DIM_);

    // 1. adafm projection + conv kernels
    proj_kernel<<<dim3(2, 2), 256>>>(ada, pw, pb);
    kconv_kernel<<<dim3(2, 2), 256>>>();

    // 2. attention branch
    modulate_kernel<<<dim3(64, 128, B_), 256>>>(x, xmodb, 0);
    tgemm_kernel<__nv_bfloat16><<<dim3(NQKV/128, NTOK/128), 256, GEMM_SMEM>>>(xmodb, wqkvt, qkvb, NTOK, NQKV, DIM_);
    rotnorm_kernel<<<NTOK, 512>>>(fc, fs, sqk);
    attn_kernel<<<dim3(SEQL/128, NH_, B_), 256>>>();
    tgemm_kernel<float><<<dim3(DIM_/128, NTOK/128), 256, GEMM_SMEM>>>(attnb, wot, ha, NTOK, DIM_, DIM_);
    combine_kernel<<<NTOK, 256>>>(x, ha, aat, x1);

    // 3. mlp branch
    modulate_kernel<<<dim3(64, 128, B_), 256>>>(x1, x1mb, 1);
    tgemm_kernel<__nv_bfloat16><<<dim3(N13/128, NTOK/128), 256, GEMM_SMEM>>>(x1mb, w13t, g13b, NTOK, N13, DIM_);
    hmid_kernel<<<dim3(HID_/256, NTOK), 256>>>(su, sv);
    tgemm_kernel<float><<<dim3(DIM_/128, NTOK/128), 256, GEMM_SMEM>>>(hhb, w2t, hm, NTOK, DIM_, HID_);
    combine_kernel<<<NTOK, 256>>>(x1, hm, aml, out);
}

// round 7
// speedup vs baseline: 5.4324x; 1.1882x over previous
#include <cuda_runtime.h>
#include <cuda_bf16.h>
#include <math.h>
#include <cstdint>

#define B_    2
#define SEQL  2048
#define DIM_  1024
#define NH_   16
#define HD_   64
#define HID_  2816
#define NTOK  (B_*SEQL)          // 4096
#define NQKV  (3*DIM_)           // 3072
#define N13   (2*HID_)           // 5632
#define NPATB 8192               // patches per batch (128*64)

// ---------------- scratch (device globals; no allocations allowed) ----------
__device__ float g_t[B_*512];
__device__ float g_kc[4*256];
__device__ float g_ha[NTOK*DIM_];
__device__ float g_x1[NTOK*DIM_];
__device__ float g_hm[NTOK*DIM_];
// bf16 activations
__device__ __nv_bfloat16 g_qkvb[NTOK*NQKV];
__device__ __nv_bfloat16 g_g13b[NTOK*N13];
__device__ __nv_bfloat16 g_qb[NTOK*DIM_];
__device__ __nv_bfloat16 g_kb[NTOK*DIM_];
__device__ __nv_bfloat16 g_vb[NTOK*DIM_];
__device__ __nv_bfloat16 g_xmodb[NTOK*DIM_];
__device__ __nv_bfloat16 g_attnb[NTOK*DIM_];
__device__ __nv_bfloat16 g_x1mb[NTOK*DIM_];
__device__ __nv_bfloat16 g_hhb[NTOK*HID_];
// modulate-as-GEMM scratch
__device__ __nv_bfloat16 g_kmat[4*256*256];        // [which][b][n][k]
__device__ __nv_bfloat16 g_xpat[NTOK*DIM_];        // patch-major input
__device__ __nv_bfloat16 g_ypat[NTOK*DIM_];        // patch-major output
// bf16 transposed weights [N][K]
__device__ __nv_bfloat16 g_wqkvt[NQKV*DIM_];
__device__ __nv_bfloat16 g_wot[DIM_*DIM_];
__device__ __nv_bfloat16 g_w13t[N13*DIM_];
__device__ __nv_bfloat16 g_w2t[DIM_*HID_];

// ====================== mma.sync helpers (family-safe) =======================
__device__ __forceinline__ uint32_t smem_u32(const void* p) {
    uint32_t a;
    asm("{ .reg .u64 t; cvta.to.shared.u64 t, %1; cvt.u32.u64 %0, t; }" : "=r"(a) : "l"(p));
    return a;
}
__device__ __forceinline__ void ldsm_x4(uint32_t* r, uint32_t addr) {
    asm volatile("ldmatrix.sync.aligned.m8n8.x4.shared.b16 {%0,%1,%2,%3}, [%4];"
                 : "=r"(r[0]), "=r"(r[1]), "=r"(r[2]), "=r"(r[3]) : "r"(addr));
}
__device__ __forceinline__ void ldsm_x2(uint32_t* r, uint32_t addr) {
    asm volatile("ldmatrix.sync.aligned.m8n8.x2.shared.b16 {%0,%1}, [%2];"
                 : "=r"(r[0]), "=r"(r[1]) : "r"(addr));
}
__device__ __forceinline__ void ldsm_x2t(uint32_t* r, uint32_t addr) {
    asm volatile("ldmatrix.sync.aligned.m8n8.x2.trans.shared.b16 {%0,%1}, [%2];"
                 : "=r"(r[0]), "=r"(r[1]) : "r"(addr));
}
__device__ __forceinline__ void mma16816(float* c, const uint32_t* a, const uint32_t* b) {
    asm volatile("mma.sync.aligned.m16n8k16.row.col.f32.bf16.bf16.f32 "
                 "{%0,%1,%2,%3}, {%4,%5,%6,%7}, {%8,%9}, {%0,%1,%2,%3};"
                 : "+f"(c[0]), "+f"(c[1]), "+f"(c[2]), "+f"(c[3])
                 : "r"(a[0]), "r"(a[1]), "r"(a[2]), "r"(a[3]), "r"(b[0]), "r"(b[1]));
}
__device__ __forceinline__ uint32_t packbf(float lo, float hi) {
    __nv_bfloat162 p = __floats2bfloat162_rn(lo, hi);
    return *(uint32_t*)&p;
}
#define CPASYNC16(saddr, gptr) \
    asm volatile("cp.async.cg.shared.global [%0], [%1], 16;" :: "r"(saddr), "l"(gptr))
#define CP_COMMIT() asm volatile("cp.async.commit_group;" ::: "memory")
#define CP_WAIT(n)  asm volatile("cp.async.wait_group %0;" :: "n"(n) : "memory")

// ============== cp.async 4-stage mma.sync GEMM ===============================
#define SPAD 40
#define STG  4
#define STAGEB (2*128*SPAD*2)
#define GEMM_SMEM (STG*STAGEB)

// shared GEMM body (A/Bt/C already offset for this CTA's batch slice)
template<typename OutT>
__device__ __forceinline__ void tgemm_body(const __nv_bfloat16* __restrict__ A,
                                           const __nv_bfloat16* __restrict__ Bt,
                                           OutT* __restrict__ C,
                                           int N, int K, uint32_t sbase)
{
    int tid = threadIdx.x, lane = tid & 31, wid = tid >> 5;
    int wr = wid >> 2, wc = wid & 3;
    int row0 = blockIdx.y * 128, col0 = blockIdx.x * 128;

    int srow = tid >> 2, sseg = tid & 3;
    const __nv_bfloat16* Ag = A  + (size_t)(row0 + srow)*K + sseg*8;
    const __nv_bfloat16* Bg = Bt + (size_t)(col0 + srow)*K + sseg*8;
    uint32_t sAoff = srow*(SPAD*2) + sseg*16;
    uint32_t sAoff2 = (srow+64)*(SPAD*2) + sseg*16;
    uint32_t sBhalf = 128*SPAD*2;

    int NC = K >> 5;

    #pragma unroll
    for (int s = 0; s < STG-1; s++) {
        uint32_t st = sbase + s*STAGEB;
        const __nv_bfloat16* Ap = Ag + (size_t)s*32;
        const __nv_bfloat16* Bp = Bg + (size_t)s*32;
        CPASYNC16(st + sAoff,  Ap);
        CPASYNC16(st + sAoff2, Ap + (size_t)64*K);
        CPASYNC16(st + sBhalf + sAoff,  Bp);
        CPASYNC16(st + sBhalf + sAoff2, Bp + (size_t)64*K);
        CP_COMMIT();
    }

    float acc[4][4][4];
    #pragma unroll
    for (int i = 0; i < 4; i++)
        #pragma unroll
        for (int j = 0; j < 4; j++)
            #pragma unroll
            for (int q = 0; q < 4; q++) acc[i][j][q] = 0.f;

    int aq = lane >> 3, arow = lane & 7;
    int a_r = (aq & 1)*8 + arow;
    int a_kb = (aq >> 1)*16;
    int b_l = lane & 15;
    int b_r = b_l & 7;
    int b_kb = (b_l >> 3)*16;

    int buf = 0;
    for (int c = 0; c < NC; c++) {
        CP_WAIT(STG-2);
        __syncthreads();

        if (c + STG-1 < NC) {
            int pb = buf - 1; if (pb < 0) pb += STG;
            uint32_t st = sbase + pb*STAGEB;
            const __nv_bfloat16* Ap = Ag + (size_t)(c+STG-1)*32;
            const __nv_bfloat16* Bp = Bg + (size_t)(c+STG-1)*32;
            CPASYNC16(st + sAoff,  Ap);
            CPASYNC16(st + sAoff2, Ap + (size_t)64*K);
            CPASYNC16(st + sBhalf + sAoff,  Bp);
            CPASYNC16(st + sBhalf + sAoff2, Bp + (size_t)64*K);
        }
        CP_COMMIT();

        uint32_t aBase = sbase + buf*STAGEB;
        uint32_t bBase = aBase + sBhalf;
        #pragma unroll
        for (int ks = 0; ks < 2; ks++) {
            uint32_t afr[4][4], bfr[4][2];
            #pragma unroll
            for (int mt = 0; mt < 4; mt++)
                ldsm_x4(afr[mt], aBase + (wr*64 + mt*16 + a_r)*(SPAD*2) + ks*32 + a_kb);
            #pragma unroll
            for (int nt = 0; nt < 4; nt++)
                ldsm_x2(bfr[nt], bBase + (wc*32 + nt*8 + b_r)*(SPAD*2) + ks*32 + b_kb);
            #pragma unroll
            for (int mt = 0; mt < 4; mt++)
                #pragma unroll
                for (int nt = 0; nt < 4; nt++)
                    mma16816(acc[mt][nt], afr[mt], bfr[nt]);
        }
        __syncthreads();
        buf++; if (buf == STG) buf = 0;
    }

    int cr = lane >> 2, cc = (lane & 3)*2;
    #pragma unroll
    for (int mt = 0; mt < 4; mt++) {
        #pragma unroll
        for (int nt = 0; nt < 4; nt++) {
            size_t r0 = (size_t)(row0 + wr*64 + mt*16 + cr);
            int col = col0 + wc*32 + nt*8 + cc;
            if constexpr (sizeof(OutT) == 4) {
                *(float2*)((float*)C + r0*N + col)     = make_float2(acc[mt][nt][0], acc[mt][nt][1]);
                *(float2*)((float*)C + (r0+8)*N + col) = make_float2(acc[mt][nt][2], acc[mt][nt][3]);
            } else {
                *(uint32_t*)((__nv_bfloat16*)C + r0*N + col)     = packbf(acc[mt][nt][0], acc[mt][nt][1]);
                *(uint32_t*)((__nv_bfloat16*)C + (r0+8)*N + col) = packbf(acc[mt][nt][2], acc[mt][nt][3]);
            }
        }
    }
}

template<typename OutT>
__global__ __launch_bounds__(256) void tgemm_kernel(const __nv_bfloat16* __restrict__ A,
                                                    const __nv_bfloat16* __restrict__ Bt,
                                                    OutT* __restrict__ C,
                                                    int M, int N, int K)
{
    extern __shared__ char smemraw[];
    tgemm_body<OutT>(A, Bt, C, N, K, smem_u32(smemraw));
}

// batched modulate GEMM: z = batch index; per-z A/C slices of 8192 rows, per-z Kmat
__global__ __launch_bounds__(256) void tgemm_modb(const __nv_bfloat16* __restrict__ A,
                                                  const __nv_bfloat16* __restrict__ Bt,
                                                  __nv_bfloat16* __restrict__ C)
{
    extern __shared__ char smemraw[];
    int z = blockIdx.z;
    tgemm_body<__nv_bfloat16>(A + (size_t)z*NPATB*256,
                              Bt + (size_t)z*256*256,
                              C + (size_t)z*NPATB*256,
                              256, 256, smem_u32(smemraw));
}

// -------- weight transpose + bf16 convert ------------------------------------
__global__ void wtrans_kernel(const float* __restrict__ W, __nv_bfloat16* __restrict__ Wt,
                              int K, int N)
{
    __shared__ float t[32][33];
    int tx = threadIdx.x, ty = threadIdx.y;
    int n = blockIdx.x*32 + tx;
    int k0 = blockIdx.y*32;
    #pragma unroll
    for (int j = 0; j < 32; j += 8)
        t[ty+j][tx] = W[(size_t)(k0+ty+j)*N + n];
    __syncthreads();
    int k = k0 + tx;
    int nb = blockIdx.x*32;
    #pragma unroll
    for (int j = 0; j < 32; j += 8)
        Wt[(size_t)(nb+ty+j)*K + k] = __float2bfloat16(t[tx][ty+j]);
}

// ---------------- adafm projection -------------------------------------------
__global__ void proj_kernel(const float* __restrict__ ada, const float* __restrict__ pw,
                            const float* __restrict__ pb)
{
    int j = blockIdx.x * blockDim.x + threadIdx.x;
    int b = blockIdx.y;
    float acc = pb[j];
    const float* ap = ada + b*DIM_;
    for (int d = 0; d < DIM_; ++d) {
        float a = ap[d];
        float s = a / (1.0f + __expf(-a));
        acc = fmaf(s, pw[d*512 + j], acc);
    }
    g_t[b*512 + j] = acc;
}

__global__ void kconv_kernel()
{
    int d = threadIdx.x;
    int which = blockIdx.x, b = blockIdx.y;
    const float* F = g_t + b*512 + which*256;
    float acc = 0.f;
    for (int m = 0; m < 256; ++m) {
        int md = (m * d) & 255;
        acc = fmaf(F[m], cospif((float)md * (1.0f/128.0f)), acc);
    }
    g_kc[(which*2 + b)*256 + d] = acc * (1.0f/256.0f);
}

// -------- build conv matrices: Kmat[wb][n][k] = kk[(n-k)&255] ----------------
__global__ void kmat_kernel()
{
    int wb = blockIdx.x;                      // which*2+b
    int n = threadIdx.x;
    const float* kk = g_kc + wb*256;
    __nv_bfloat16* Km = g_kmat + (size_t)wb*256*256 + n*256;
    #pragma unroll 4
    for (int k = 0; k < 256; ++k)
        Km[k] = __float2bfloat16(kk[(n - k) & 255]);
}

// -------- gather: X fp32 row-major -> bf16 patch-major [b][p][256] -----------
__global__ __launch_bounds__(256) void gather_kernel(const float* __restrict__ X,
                                                     __nv_bfloat16* __restrict__ Xp)
{
    int b = blockIdx.y;
    int p = blockIdx.x*4 + (threadIdx.x >> 6);   // patch
    int q = threadIdx.x & 63;
    int r = q >> 2, cs = (q & 3)*4;
    int ib = p >> 6, jb = p & 63;
    float4 v = *(const float4*)(X + ((size_t)(b*SEQL + ib*16 + r))*DIM_ + jb*16 + cs);
    uint2 o;
    o.x = packbf(v.x, v.y);
    o.y = packbf(v.z, v.w);
    *(uint2*)(Xp + ((size_t)(b*NPATB + p))*256 + r*16 + cs) = o;
}

// -------- scatter: bf16 patch-major -> bf16 row-major ------------------------
__global__ __launch_bounds__(256) void scatter_kernel(const __nv_bfloat16* __restrict__ Yp,
                                                      __nv_bfloat16* __restrict__ Y)
{
    int b = blockIdx.y;
    int p = blockIdx.x*4 + (threadIdx.x >> 6);
    int q = threadIdx.x & 63;
    int r = q >> 2, cs = (q & 3)*4;
    int ib = p >> 6, jb = p & 63;
    uint2 v = *(const uint2*)(Yp + ((size_t)(b*NPATB + p))*256 + r*16 + cs);
    *(uint2*)(Y + ((size_t)(b*SEQL + ib*16 + r))*DIM_ + jb*16 + cs) = v;
}

// ------------- rotary + justnorm -> bf16 q(×8)/k/v [B][H][S][64] -------------
__global__ __launch_bounds__(512) void rotnorm_kernel(const float* __restrict__ fc,
                                                      const float* __restrict__ fs,
                                                      const float* __restrict__ sqk)
{
    int row = blockIdx.x;
    int s = row & (SEQL - 1);
    int b = row >> 11;
    int h = threadIdx.x >> 5;
    int i = threadIdx.x & 31;
    float c = fc[s*32 + i], sn = fs[s*32 + i];
    size_t gin = (size_t)row*NQKV + h*64 + 2*i;
    __nv_bfloat162 qv = *(const __nv_bfloat162*)(g_qkvb + gin);
    __nv_bfloat162 kv = *(const __nv_bfloat162*)(g_qkvb + gin + DIM_);
    __nv_bfloat162 vv = *(const __nv_bfloat162*)(g_qkvb + gin + 2*DIM_);
    float qa = __bfloat162float(qv.x), qb = __bfloat162float(qv.y);
    float ka = __bfloat162float(kv.x), kb = __bfloat162float(kv.y);
    float ra = qa*c - qb*sn, rb = qa*sn + qb*c;
    float ta = ka*c - kb*sn, tb = ka*sn + kb*c;
    float sq = ra*ra + rb*rb, sk = ta*ta + tb*tb;
    #pragma unroll
    for (int o = 16; o; o >>= 1) {
        sq += __shfl_xor_sync(0xffffffffu, sq, o);
        sk += __shfl_xor_sync(0xffffffffu, sk, o);
    }
    float invq = 1.0f / fmaxf(sqrtf(sq), 1e-12f);
    float invk = 1.0f / fmaxf(sqrtf(sk), 1e-12f);
    float sa = sqk[h*64 + 2*i]   * 32.0f;
    float sb = sqk[h*64 + 2*i+1] * 32.0f;
    size_t go = ((size_t)(b*NH_ + h)*SEQL + s)*64 + 2*i;
    *(__nv_bfloat162*)(g_qb + go) = __floats2bfloat162_rn(ra*invq*sa*8.0f, rb*invq*sb*8.0f);
    *(__nv_bfloat162*)(g_kb + go) = __floats2bfloat162_rn(ta*invk*sa, tb*invk*sb);
    *(__nv_bfloat162*)(g_vb + go) = vv;
}

// ------------- flash attention, bf16 mma.sync --------------------------------
#define APAD 72
__global__ __launch_bounds__(256) void attn_kernel()
{
    __shared__ __nv_bfloat16 sQ[128][APAD];
    __shared__ __nv_bfloat16 sK[64][APAD];
    __shared__ __nv_bfloat16 sV[64][APAD];
    int tid = threadIdx.x, lane = tid & 31, wid = tid >> 5;
    int q0 = blockIdx.x * 128;
    int h = blockIdx.y, b = blockIdx.z;
    size_t base = ((size_t)(b*NH_ + h))*SEQL*HD_;
    const __nv_bfloat16* Qg = g_qb + base;
    const __nv_bfloat16* Kg = g_kb + base;
    const __nv_bfloat16* Vg = g_vb + base;

    {
        int r = tid >> 1, c = (tid & 1)*32;
        const uint4* src = (const uint4*)(Qg + (size_t)(q0 + r)*64 + c);
        uint4 v0 = src[0], v1 = src[1], v2 = src[2], v3 = src[3];
        uint4* d = (uint4*)&sQ[r][c];
        d[0] = v0; d[1] = v1; d[2] = v2; d[3] = v3;
    }

    int kvr = tid >> 2, kvc = (tid & 3)*16;
    uint4 pk0, pk1, pv0, pv1;
    {
        pk0 = *(const uint4*)(Kg + (size_t)kvr*64 + kvc);
        pk1 = *(const uint4*)(Kg + (size_t)kvr*64 + kvc + 8);
        pv0 = *(const uint4*)(Vg + (size_t)kvr*64 + kvc);
        pv1 = *(const uint4*)(Vg + (size_t)kvr*64 + kvc + 8);
    }
    __syncthreads();

    uint32_t aq[4][4];
    {
        int r = wid*16 + (lane & 15);
        int cb = (lane >> 4)*8;
        #pragma unroll
        for (int kc = 0; kc < 4; kc++)
            ldsm_x4(aq[kc], smem_u32(&sQ[r][kc*16 + cb]));
    }

    float mrun[2] = {-1e30f, -1e30f}, lrun[2] = {0.f, 0.f};
    float oacc[8][4];
    #pragma unroll
    for (int nf = 0; nf < 8; nf++)
        #pragma unroll
        for (int q = 0; q < 4; q++) oacc[nf][q] = 0.f;

    for (int t = 0; t < SEQL/64; t++) {
        *(uint4*)&sK[kvr][kvc]     = pk0;
        *(uint4*)&sK[kvr][kvc + 8] = pk1;
        *(uint4*)&sV[kvr][kvc]     = pv0;
        *(uint4*)&sV[kvr][kvc + 8] = pv1;
        __syncthreads();
        if (t + 1 < SEQL/64) {
            const __nv_bfloat16* Kt = Kg + (size_t)(t+1)*64*64;
            const __nv_bfloat16* Vt = Vg + (size_t)(t+1)*64*64;
            pk0 = *(const uint4*)(Kt + (size_t)kvr*64 + kvc);
            pk1 = *(const uint4*)(Kt + (size_t)kvr*64 + kvc + 8);
            pv0 = *(const uint4*)(Vt + (size_t)kvr*64 + kvc);
            pv1 = *(const uint4*)(Vt + (size_t)kvr*64 + kvc + 8);
        }

        float s[8][4];
        #pragma unroll
        for (int nf = 0; nf < 8; nf++)
            #pragma unroll
            for (int q = 0; q < 4; q++) s[nf][q] = 0.f;
        #pragma unroll
        for (int kc = 0; kc < 4; kc++) {
            #pragma unroll
            for (int nf = 0; nf < 8; nf++) {
                uint32_t bk[2];
                ldsm_x2(bk, smem_u32(&sK[nf*8 + (lane & 7)][kc*16 + ((lane >> 3) & 1)*8]));
                mma16816(s[nf], aq[kc], bk);
            }
        }

        #pragma unroll
        for (int hh = 0; hh < 2; hh++) {
            float tm = -1e30f;
            #pragma unroll
            for (int nf = 0; nf < 8; nf++)
                tm = fmaxf(tm, fmaxf(s[nf][hh*2], s[nf][hh*2+1]));
            tm = fmaxf(tm, __shfl_xor_sync(0xffffffffu, tm, 1));
            tm = fmaxf(tm, __shfl_xor_sync(0xffffffffu, tm, 2));
            float mn = fmaxf(mrun[hh], tm);
            float f = __expf(mrun[hh] - mn);
            float rs = 0.f;
            #pragma unroll
            for (int nf = 0; nf < 8; nf++) {
                float p0 = __expf(s[nf][hh*2]   - mn);
                float p1 = __expf(s[nf][hh*2+1] - mn);
                s[nf][hh*2] = p0; s[nf][hh*2+1] = p1;
                rs += p0 + p1;
            }
            rs += __shfl_xor_sync(0xffffffffu, rs, 1);
            rs += __shfl_xor_sync(0xffffffffu, rs, 2);
            lrun[hh] = lrun[hh]*f + rs;
            mrun[hh] = mn;
            #pragma unroll
            for (int nf = 0; nf < 8; nf++) {
                oacc[nf][hh*2]   *= f;
                oacc[nf][hh*2+1] *= f;
            }
        }

        uint32_t pf[4][4];
        #pragma unroll
        for (int kc = 0; kc < 4; kc++) {
            pf[kc][0] = packbf(s[2*kc][0],   s[2*kc][1]);
            pf[kc][1] = packbf(s[2*kc][2],   s[2*kc][3]);
            pf[kc][2] = packbf(s[2*kc+1][0], s[2*kc+1][1]);
            pf[kc][3] = packbf(s[2*kc+1][2], s[2*kc+1][3]);
        }

        #pragma unroll
        for (int nf = 0; nf < 8; nf++) {
            #pragma unroll
            for (int kc = 0; kc < 4; kc++) {
                uint32_t bv[2];
                ldsm_x2t(bv, smem_u32(&sV[kc*16 + (lane & 15)][nf*8]));
                mma16816(oacc[nf], pf[kc], bv);
            }
        }
        __syncthreads();
    }

    int r0 = wid*16 + (lane >> 2);
    #pragma unroll
    for (int hh = 0; hh < 2; hh++) {
        float inv = 1.0f / lrun[hh];
        int row = q0 + r0 + hh*8;
        size_t o = ((size_t)(b*SEQL) + row)*DIM_ + h*64 + (lane & 3)*2;
        #pragma unroll
        for (int nf = 0; nf < 8; nf++) {
            __nv_bfloat162 p = __floats2bfloat162_rn(oacc[nf][hh*2]*inv, oacc[nf][hh*2+1]*inv);
            *(__nv_bfloat162*)(g_attnb + o + nf*8) = p;
        }
    }
}

// ------------- combine --------------------------------------------------------
__device__ __forceinline__ float block_sum(float v, float* shm)
{
    #pragma unroll
    for (int o = 16; o; o >>= 1) v += __shfl_xor_sync(0xffffffffu, v, o);
    __syncthreads();
    if ((threadIdx.x & 31) == 0) shm[threadIdx.x >> 5] = v;
    __syncthreads();
    if (threadIdx.x < 32) {
        float t = (threadIdx.x < 8) ? shm[threadIdx.x] : 0.f;
        #pragma unroll
        for (int o = 4; o; o >>= 1) t += __shfl_xor_sync(0xffffffffu, t, o);
        if (threadIdx.x == 0) shm[0] = t;
    }
    __syncthreads();
    return shm[0];
}

__global__ __launch_bounds__(256) void combine_kernel(const float* __restrict__ X,
                                                      const float* __restrict__ H,
                                                      const float* __restrict__ alpha,
                                                      float* __restrict__ Out)
{
    __shared__ float shm[8];
    int row = blockIdx.x;
    const float* xp = X + (size_t)row*DIM_;
    const float* hp = H + (size_t)row*DIM_;
    float xv[4], hv[4];
    float sx = 0.f, sh = 0.f;
    #pragma unroll
    for (int i = 0; i < 4; i++) {
        int j = threadIdx.x + i*256;
        xv[i] = xp[j]; hv[i] = hp[j];
        sx = fmaf(xv[i], xv[i], sx);
        sh = fmaf(hv[i], hv[i], sh);
    }
    float nx = block_sum(sx, shm);
    float nh = block_sum(sh, shm);
    float invx = 1.0f / fmaxf(sqrtf(nx), 1e-12f);
    float invh = 1.0f / fmaxf(sqrtf(nh), 1e-12f);
    float yv[4]; float sy = 0.f;
    #pragma unroll
    for (int i = 0; i < 4; i++) {
        int j = threadIdx.x + i*256;
        float lr = fabsf(alpha[j] * 1.6f);
        float hn = xv[i]*invx;
        float y = hn + lr*(hv[i]*invh - hn);
        yv[i] = y; sy = fmaf(y, y, sy);
    }
    float ny = block_sum(sy, shm);
    float invy = 1.0f / fmaxf(sqrtf(ny), 1e-12f);
    #pragma unroll
    for (int i = 0; i < 4; i++)
        Out[(size_t)row*DIM_ + threadIdx.x + i*256] = yv[i]*invy;
}

// ------------- swiglu gate (reads fused g13 bf16) -> bf16 --------------------
__global__ void hmid_kernel(const float* __restrict__ su, const float* __restrict__ sv)
{
    int j = blockIdx.x*256 + threadIdx.x;
    int row = blockIdx.y;
    float g1 = __bfloat162float(g_g13b[(size_t)row*N13 + j]);
    float g3 = __bfloat162float(g_g13b[(size_t)row*N13 + HID_ + j]);
    float z = g1 * sv[j] * 53.06599665f;
    float sg = 1.0f / (1.0f + __expf(-z));
    g_hhb[(size_t)row*HID_ + j] = __float2bfloat16(z * sg * (g3 * su[j]));
}

// ------------------------------- launcher -------------------------------------
extern "C" void kernel_launch(void* const* d_in, const int* in_sizes, int n_in,
                              void* d_out, int out_size)
{
    const float* x   = (const float*)d_in[0];
    const float* fc  = (const float*)d_in[1];
    const float* fs  = (const float*)d_in[2];
    const float* ada = (const float*)d_in[3];
    const float* wq  = (const float*)d_in[4];
    const float* wk  = (const float*)d_in[5];
    const float* wv  = (const float*)d_in[6];
    const float* wo  = (const float*)d_in[7];
    const float* sqk = (const float*)d_in[8];
    const float* w1  = (const float*)d_in[9];
    const float* w2  = (const float*)d_in[10];
    const float* w3  = (const float*)d_in[11];
    const float* su  = (const float*)d_in[12];
    const float* sv  = (const float*)d_in[13];
    const float* pw  = (const float*)d_in[14];
    const float* pb  = (const float*)d_in[15];
    const float* aat = (const float*)d_in[16];
    const float* aml = (const float*)d_in[17];
    float* out = (float*)d_out;

    float *ha, *x1, *hm;
    __nv_bfloat16 *xmodb, *attnb, *x1mb, *hhb, *qkvb, *g13b, *kmat, *xpat, *ypat;
    __nv_bfloat16 *wqkvt, *wot, *w13t, *w2t;
    cudaGetSymbolAddress((void**)&ha,   g_ha);
    cudaGetSymbolAddress((void**)&x1,   g_x1);
    cudaGetSymbolAddress((void**)&hm,   g_hm);
    cudaGetSymbolAddress((void**)&xmodb, g_xmodb);
    cudaGetSymbolAddress((void**)&attnb, g_attnb);
    cudaGetSymbolAddress((void**)&x1mb,  g_x1mb);
    cudaGetSymbolAddress((void**)&hhb,   g_hhb);
    cudaGetSymbolAddress((void**)&qkvb,  g_qkvb);
    cudaGetSymbolAddress((void**)&g13b,  g_g13b);
    cudaGetSymbolAddress((void**)&kmat,  g_kmat);
    cudaGetSymbolAddress((void**)&xpat,  g_xpat);
    cudaGetSymbolAddress((void**)&ypat,  g_ypat);
    cudaGetSymbolAddress((void**)&wqkvt, g_wqkvt);
    cudaGetSymbolAddress((void**)&wot,   g_wot);
    cudaGetSymbolAddress((void**)&w13t,  g_w13t);
    cudaGetSymbolAddress((void**)&w2t,   g_w2t);

    cudaFuncSetAttribute(tgemm_kernel<float>, cudaFuncAttributeMaxDynamicSharedMemorySize, GEMM_SMEM);
    cudaFuncSetAttribute(tgemm_kernel<__nv_bfloat16>, cudaFuncAttributeMaxDynamicSharedMemorySize, GEMM_SMEM);
    cudaFuncSetAttribute(tgemm_modb, cudaFuncAttributeMaxDynamicSharedMemorySize, GEMM_SMEM);

    // 0. weight transposes (bf16, [N][K]); qkv and w1/w3 packed contiguously
    wtrans_kernel<<<dim3(DIM_/32, DIM_/32), dim3(32,8)>>>(wq, wqkvt,               DIM_, DIM_);
    wtrans_kernel<<<dim3(DIM_/32, DIM_/32), dim3(32,8)>>>(wk, wqkvt + DIM_*DIM_,   DIM_, DIM_);
    wtrans_kernel<<<dim3(DIM_/32, DIM_/32), dim3(32,8)>>>(wv, wqkvt + 2*DIM_*DIM_, DIM_, DIM_);
    wtrans_kernel<<<dim3(DIM_/32, DIM_/32), dim3(32,8)>>>(wo, wot, DIM_, DIM_);
    wtrans_kernel<<<dim3(HID_/32, DIM_/32), dim3(32,8)>>>(w1, w13t,              DIM_, HID_);
    wtrans_kernel<<<dim3(HID_/32, DIM_/32), dim3(32,8)>>>(w3, w13t + HID_*DIM_,  DIM_, HID_);
    wtrans_kernel<<<dim3(DIM_/32, HID_/32), dim3(32,8)>>>(w2, w2t, HID_, DIM_);

    // 1. adafm projection + conv kernel matrices
    proj_kernel<<<dim3(2, 2), 256>>>(ada, pw, pb);
    kconv_kernel<<<dim3(2, 2), 256>>>();
    kmat_kernel<<<4, 256>>>();

    // 2. attention branch: modulate(which=0) as GEMM
    gather_kernel<<<dim3(NPATB/4, B_), 256>>>(x, xpat);
    tgemm_modb<<<dim3(2, NPATB/128, B_), 256, GEMM_SMEM>>>(xpat, kmat, ypat);
    scatter_kernel<<<dim3(NPATB/4, B_), 256>>>(ypat, xmodb);
    tgemm_kernel<__nv_bfloat16><<<dim3(NQKV/128, NTOK/128), 256, GEMM_SMEM>>>(xmodb, wqkvt, qkvb, NTOK, NQKV, DIM_);
    rotnorm_kernel<<<NTOK, 512>>>(fc, fs, sqk);
    attn_kernel<<<dim3(SEQL/128, NH_, B_), 256>>>();
    tgemm_kernel<float><<<dim3(DIM_/128, NTOK/128), 256, GEMM_SMEM>>>(attnb, wot, ha, NTOK, DIM_, DIM_);
    combine_kernel<<<NTOK, 256>>>(x, ha, aat, x1);

    // 3. mlp branch: modulate(which=1) as GEMM
    gather_kernel<<<dim3(NPATB/4, B_), 256>>>(x1, xpat);
    tgemm_modb<<<dim3(2, NPATB/128, B_), 256, GEMM_SMEM>>>(xpat, kmat + 2*256*256, ypat);
    scatter_kernel<<<dim3(NPATB/4, B_), 256>>>(ypat, x1mb);
    tgemm_kernel<__nv_bfloat16><<<dim3(N13/128, NTOK/128), 256, GEMM_SMEM>>>(x1mb, w13t, g13b, NTOK, N13, DIM_);
    hmid_kernel<<<dim3(HID_/256, NTOK), 256>>>(su, sv);
    tgemm_kernel<float><<<dim3(DIM_/128, NTOK/128), 256, GEMM_SMEM>>>(hhb, w2t, hm, NTOK, DIM_, HID_);
    combine_kernel<<<NTOK, 256>>>(x1, hm, aml, out);
}

// round 8
// speedup vs baseline: 5.4622x; 1.0055x over previous
#include <cuda_runtime.h>
#include <cuda_bf16.h>
#include <math.h>
#include <cstdint>

#define B_    2
#define SEQL  2048
#define DIM_  1024
#define NH_   16
#define HD_   64
#define HID_  2816
#define NTOK  (B_*SEQL)          // 4096
#define NQKV  (3*DIM_)           // 3072
#define N13   (2*HID_)           // 5632
#define NPATB 8192               // patches per batch (128*64)

// ---------------- scratch (device globals; no allocations allowed) ----------
__device__ float g_t[B_*512];
__device__ float g_kc[4*256];
__device__ float g_x1[NTOK*DIM_];
// bf16 activations
__device__ __nv_bfloat16 g_qkvb[NTOK*NQKV];
__device__ __nv_bfloat16 g_qb[NTOK*DIM_];
__device__ __nv_bfloat16 g_kb[NTOK*DIM_];
__device__ __nv_bfloat16 g_vb[NTOK*DIM_];
__device__ __nv_bfloat16 g_xmodb[NTOK*DIM_];
__device__ __nv_bfloat16 g_attnb[NTOK*DIM_];
__device__ __nv_bfloat16 g_x1mb[NTOK*DIM_];
__device__ __nv_bfloat16 g_hhb[NTOK*HID_];
__device__ __nv_bfloat16 g_hab[NTOK*DIM_];
__device__ __nv_bfloat16 g_hmb[NTOK*DIM_];
// modulate-as-GEMM scratch
__device__ __nv_bfloat16 g_kmat[4*256*256];        // [which][b][n][k]
__device__ __nv_bfloat16 g_xpat[NTOK*DIM_];        // patch-major input
// bf16 transposed weights [N][K]
__device__ __nv_bfloat16 g_wqkvt[NQKV*DIM_];
__device__ __nv_bfloat16 g_wot[DIM_*DIM_];
__device__ __nv_bfloat16 g_w13t[N13*DIM_];         // interleaved: row 2j=w1_j, 2j+1=w3_j
__device__ __nv_bfloat16 g_w2t[DIM_*HID_];

// ====================== mma.sync helpers (family-safe) =======================
__device__ __forceinline__ uint32_t smem_u32(const void* p) {
    uint32_t a;
    asm("{ .reg .u64 t; cvta.to.shared.u64 t, %1; cvt.u32.u64 %0, t; }" : "=r"(a) : "l"(p));
    return a;
}
__device__ __forceinline__ void ldsm_x4(uint32_t* r, uint32_t addr) {
    asm volatile("ldmatrix.sync.aligned.m8n8.x4.shared.b16 {%0,%1,%2,%3}, [%4];"
                 : "=r"(r[0]), "=r"(r[1]), "=r"(r[2]), "=r"(r[3]) : "r"(addr));
}
__device__ __forceinline__ void ldsm_x2(uint32_t* r, uint32_t addr) {
    asm volatile("ldmatrix.sync.aligned.m8n8.x2.shared.b16 {%0,%1}, [%2];"
                 : "=r"(r[0]), "=r"(r[1]) : "r"(addr));
}
__device__ __forceinline__ void ldsm_x2t(uint32_t* r, uint32_t addr) {
    asm volatile("ldmatrix.sync.aligned.m8n8.x2.trans.shared.b16 {%0,%1}, [%2];"
                 : "=r"(r[0]), "=r"(r[1]) : "r"(addr));
}
__device__ __forceinline__ void mma16816(float* c, const uint32_t* a, const uint32_t* b) {
    asm volatile("mma.sync.aligned.m16n8k16.row.col.f32.bf16.bf16.f32 "
                 "{%0,%1,%2,%3}, {%4,%5,%6,%7}, {%8,%9}, {%0,%1,%2,%3};"
                 : "+f"(c[0]), "+f"(c[1]), "+f"(c[2]), "+f"(c[3])
                 : "r"(a[0]), "r"(a[1]), "r"(a[2]), "r"(a[3]), "r"(b[0]), "r"(b[1]));
}
__device__ __forceinline__ uint32_t packbf(float lo, float hi) {
    __nv_bfloat162 p = __floats2bfloat162_rn(lo, hi);
    return *(uint32_t*)&p;
}
#define CPASYNC16(saddr, gptr) \
    asm volatile("cp.async.cg.shared.global [%0], [%1], 16;" :: "r"(saddr), "l"(gptr))
#define CP_COMMIT() asm volatile("cp.async.commit_group;" ::: "memory")
#define CP_WAIT(n)  asm volatile("cp.async.wait_group %0;" :: "n"(n) : "memory")

// ============== cp.async 4-stage mma.sync GEMM core ==========================
#define SPAD 40
#define STG  4
#define STAGEB (2*128*SPAD*2)
#define GEMM_SMEM (STG*STAGEB)

// ---- epilogues: receive (global row r0 [and r0+8], global col, acc[4]) ------
struct EpiBF16 {
    __nv_bfloat16* C; int N;
    __device__ __forceinline__ void store(int r0, int col, const float* a) const {
        *(uint32_t*)(C + (size_t)r0*N + col)     = packbf(a[0], a[1]);
        *(uint32_t*)(C + (size_t)(r0+8)*N + col) = packbf(a[2], a[3]);
    }
};
struct EpiSwiglu {      // w13 interleaved: col even=g1_j, col+1=g3_j ; out[row][j]
    __nv_bfloat16* out; const float* su; const float* sv;
    __device__ __forceinline__ void store(int r0, int col, const float* a) const {
        int j = col >> 1;
        float svj = sv[j] * 53.06599665f;       // sqrt(2816)
        float suj = su[j];
        float z0 = a[0]*svj, z1 = a[2]*svj;
        float h0 = z0 / (1.f + __expf(-z0)) * (a[1]*suj);
        float h1 = z1 / (1.f + __expf(-z1)) * (a[3]*suj);
        out[(size_t)r0*HID_ + j]     = __float2bfloat16(h0);
        out[(size_t)(r0+8)*HID_ + j] = __float2bfloat16(h1);
    }
};
struct EpiMod {         // modulate GEMM: row=patch p, col=pos n -> row-major Y
    __nv_bfloat16* Y;   // batch-offset applied
    __device__ __forceinline__ void store(int p, int n, const float* a) const {
        int grow0 = ((p >> 6) << 4) + (n >> 4);
        int gcol  = ((p & 63) << 4) + (n & 15);
        int grow1 = (((p+8) >> 6) << 4) + (n >> 4);
        int gcol1 = (((p+8) & 63) << 4) + (n & 15);
        *(uint32_t*)(Y + (size_t)grow0*DIM_ + gcol)  = packbf(a[0], a[1]);
        *(uint32_t*)(Y + (size_t)grow1*DIM_ + gcol1) = packbf(a[2], a[3]);
    }
};

template<class Epi>
__device__ __forceinline__ void tgemm_core(const __nv_bfloat16* __restrict__ A,
                                           const __nv_bfloat16* __restrict__ Bt,
                                           int K, uint32_t sbase, const Epi& epi)
{
    int tid = threadIdx.x, lane = tid & 31, wid = tid >> 5;
    int wr = wid >> 2, wc = wid & 3;
    int row0 = blockIdx.y * 128, col0 = blockIdx.x * 128;

    int srow = tid >> 2, sseg = tid & 3;
    const __nv_bfloat16* Ag = A  + (size_t)(row0 + srow)*K + sseg*8;
    const __nv_bfloat16* Bg = Bt + (size_t)(col0 + srow)*K + sseg*8;
    uint32_t sAoff = srow*(SPAD*2) + sseg*16;
    uint32_t sAoff2 = (srow+64)*(SPAD*2) + sseg*16;
    uint32_t sBhalf = 128*SPAD*2;

    int NC = K >> 5;

    #pragma unroll
    for (int s = 0; s < STG-1; s++) {
        uint32_t st = sbase + s*STAGEB;
        const __nv_bfloat16* Ap = Ag + (size_t)s*32;
        const __nv_bfloat16* Bp = Bg + (size_t)s*32;
        CPASYNC16(st + sAoff,  Ap);
        CPASYNC16(st + sAoff2, Ap + (size_t)64*K);
        CPASYNC16(st + sBhalf + sAoff,  Bp);
        CPASYNC16(st + sBhalf + sAoff2, Bp + (size_t)64*K);
        CP_COMMIT();
    }

    float acc[4][4][4];
    #pragma unroll
    for (int i = 0; i < 4; i++)
        #pragma unroll
        for (int j = 0; j < 4; j++)
            #pragma unroll
            for (int q = 0; q < 4; q++) acc[i][j][q] = 0.f;

    int aq = lane >> 3, arow = lane & 7;
    int a_r = (aq & 1)*8 + arow;
    int a_kb = (aq >> 1)*16;
    int b_l = lane & 15;
    int b_r = b_l & 7;
    int b_kb = (b_l >> 3)*16;

    int buf = 0;
    for (int c = 0; c < NC; c++) {
        CP_WAIT(STG-2);
        __syncthreads();

        if (c + STG-1 < NC) {
            int pb = buf - 1; if (pb < 0) pb += STG;
            uint32_t st = sbase + pb*STAGEB;
            const __nv_bfloat16* Ap = Ag + (size_t)(c+STG-1)*32;
            const __nv_bfloat16* Bp = Bg + (size_t)(c+STG-1)*32;
            CPASYNC16(st + sAoff,  Ap);
            CPASYNC16(st + sAoff2, Ap + (size_t)64*K);
            CPASYNC16(st + sBhalf + sAoff,  Bp);
            CPASYNC16(st + sBhalf + sAoff2, Bp + (size_t)64*K);
        }
        CP_COMMIT();

        uint32_t aBase = sbase + buf*STAGEB;
        uint32_t bBase = aBase + sBhalf;
        #pragma unroll
        for (int ks = 0; ks < 2; ks++) {
            uint32_t afr[4][4], bfr[4][2];
            #pragma unroll
            for (int mt = 0; mt < 4; mt++)
                ldsm_x4(afr[mt], aBase + (wr*64 + mt*16 + a_r)*(SPAD*2) + ks*32 + a_kb);
            #pragma unroll
            for (int nt = 0; nt < 4; nt++)
                ldsm_x2(bfr[nt], bBase + (wc*32 + nt*8 + b_r)*(SPAD*2) + ks*32 + b_kb);
            #pragma unroll
            for (int mt = 0; mt < 4; mt++)
                #pragma unroll
                for (int nt = 0; nt < 4; nt++)
                    mma16816(acc[mt][nt], afr[mt], bfr[nt]);
        }
        __syncthreads();
        buf++; if (buf == STG) buf = 0;
    }

    int cr = lane >> 2, cc = (lane & 3)*2;
    #pragma unroll
    for (int mt = 0; mt < 4; mt++) {
        int r0 = row0 + wr*64 + mt*16 + cr;
        #pragma unroll
        for (int nt = 0; nt < 4; nt++)
            epi.store(r0, col0 + wc*32 + nt*8 + cc, acc[mt][nt]);
    }
}

template<class Epi>
__global__ __launch_bounds__(256) void tgemm_epi(const __nv_bfloat16* __restrict__ A,
                                                 const __nv_bfloat16* __restrict__ Bt,
                                                 int K, Epi epi)
{
    extern __shared__ char smemraw[];
    tgemm_core<Epi>(A, Bt, K, smem_u32(smemraw), epi);
}

// batched modulate GEMM with fused scatter epilogue
__global__ __launch_bounds__(256) void tgemm_mod(const __nv_bfloat16* __restrict__ A,
                                                 const __nv_bfloat16* __restrict__ Bt,
                                                 __nv_bfloat16* __restrict__ Y)
{
    extern __shared__ char smemraw[];
    int z = blockIdx.z;
    EpiMod epi{ Y + (size_t)z*SEQL*DIM_ };
    tgemm_core<EpiMod>(A + (size_t)z*NPATB*256, Bt + (size_t)z*256*256,
                       256, smem_u32(smemraw), epi);
}

// -------- weight transpose + bf16 convert (with output row stride/offset) ----
__global__ void wtrans_kernel(const float* __restrict__ W, __nv_bfloat16* __restrict__ Wt,
                              int K, int N, int rs, int ro)
{
    __shared__ float t[32][33];
    int tx = threadIdx.x, ty = threadIdx.y;
    int n = blockIdx.x*32 + tx;
    int k0 = blockIdx.y*32;
    #pragma unroll
    for (int j = 0; j < 32; j += 8)
        t[ty+j][tx] = W[(size_t)(k0+ty+j)*N + n];
    __syncthreads();
    int k = k0 + tx;
    int nb = blockIdx.x*32;
    #pragma unroll
    for (int j = 0; j < 32; j += 8)
        Wt[((size_t)(nb+ty+j)*rs + ro)*K + k] = __float2bfloat16(t[tx][ty+j]);
}

// ---------------- adafm projection -------------------------------------------
__global__ void proj_kernel(const float* __restrict__ ada, const float* __restrict__ pw,
                            const float* __restrict__ pb)
{
    int j = blockIdx.x * blockDim.x + threadIdx.x;
    int b = blockIdx.y;
    float acc = pb[j];
    const float* ap = ada + b*DIM_;
    for (int d = 0; d < DIM_; ++d) {
        float a = ap[d];
        float s = a / (1.0f + __expf(-a));
        acc = fmaf(s, pw[d*512 + j], acc);
    }
    g_t[b*512 + j] = acc;
}

__global__ void kconv_kernel()
{
    int d = threadIdx.x;
    int which = blockIdx.x, b = blockIdx.y;
    const float* F = g_t + b*512 + which*256;
    float acc = 0.f;
    for (int m = 0; m < 256; ++m) {
        int md = (m * d) & 255;
        acc = fmaf(F[m], cospif((float)md * (1.0f/128.0f)), acc);
    }
    g_kc[(which*2 + b)*256 + d] = acc * (1.0f/256.0f);
}

// -------- build conv matrices: Kmat[wb][n][k] = kk[(n-k)&255] ----------------
__global__ void kmat_kernel()
{
    int wb = blockIdx.x;
    int n = threadIdx.x;
    const float* kk = g_kc + wb*256;
    __nv_bfloat16* Km = g_kmat + (size_t)wb*256*256 + n*256;
    #pragma unroll 4
    for (int k = 0; k < 256; ++k)
        Km[k] = __float2bfloat16(kk[(n - k) & 255]);
}

// -------- gather: X fp32 row-major -> bf16 patch-major [b][p][256] -----------
__global__ __launch_bounds__(256) void gather_kernel(const float* __restrict__ X,
                                                     __nv_bfloat16* __restrict__ Xp)
{
    int b = blockIdx.y;
    int p = blockIdx.x*4 + (threadIdx.x >> 6);
    int q = threadIdx.x & 63;
    int r = q >> 2, cs = (q & 3)*4;
    int ib = p >> 6, jb = p & 63;
    float4 v = *(const float4*)(X + ((size_t)(b*SEQL + ib*16 + r))*DIM_ + jb*16 + cs);
    uint2 o;
    o.x = packbf(v.x, v.y);
    o.y = packbf(v.z, v.w);
    *(uint2*)(Xp + ((size_t)(b*NPATB + p))*256 + r*16 + cs) = o;
}

// ------------- rotary + justnorm -> bf16 q(×8)/k/v [B][H][S][64] -------------
__global__ __launch_bounds__(512) void rotnorm_kernel(const float* __restrict__ fc,
                                                      const float* __restrict__ fs,
                                                      const float* __restrict__ sqk)
{
    int row = blockIdx.x;
    int s = row & (SEQL - 1);
    int b = row >> 11;
    int h = threadIdx.x >> 5;
    int i = threadIdx.x & 31;
    float c = fc[s*32 + i], sn = fs[s*32 + i];
    size_t gin = (size_t)row*NQKV + h*64 + 2*i;
    __nv_bfloat162 qv = *(const __nv_bfloat162*)(g_qkvb + gin);
    __nv_bfloat162 kv = *(const __nv_bfloat162*)(g_qkvb + gin + DIM_);
    __nv_bfloat162 vv = *(const __nv_bfloat162*)(g_qkvb + gin + 2*DIM_);
    float qa = __bfloat162float(qv.x), qb = __bfloat162float(qv.y);
    float ka = __bfloat162float(kv.x), kb = __bfloat162float(kv.y);
    float ra = qa*c - qb*sn, rb = qa*sn + qb*c;
    float ta = ka*c - kb*sn, tb = ka*sn + kb*c;
    float sq = ra*ra + rb*rb, sk = ta*ta + tb*tb;
    #pragma unroll
    for (int o = 16; o; o >>= 1) {
        sq += __shfl_xor_sync(0xffffffffu, sq, o);
        sk += __shfl_xor_sync(0xffffffffu, sk, o);
    }
    float invq = 1.0f / fmaxf(sqrtf(sq), 1e-12f);
    float invk = 1.0f / fmaxf(sqrtf(sk), 1e-12f);
    float sa = sqk[h*64 + 2*i]   * 32.0f;
    float sb = sqk[h*64 + 2*i+1] * 32.0f;
    size_t go = ((size_t)(b*NH_ + h)*SEQL + s)*64 + 2*i;
    *(__nv_bfloat162*)(g_qb + go) = __floats2bfloat162_rn(ra*invq*sa*8.0f, rb*invq*sb*8.0f);
    *(__nv_bfloat162*)(g_kb + go) = __floats2bfloat162_rn(ta*invk*sa, tb*invk*sb);
    *(__nv_bfloat162*)(g_vb + go) = vv;
}

// ------------- flash attention, bf16 mma.sync --------------------------------
#define APAD 72
__global__ __launch_bounds__(256) void attn_kernel()
{
    __shared__ __nv_bfloat16 sQ[128][APAD];
    __shared__ __nv_bfloat16 sK[64][APAD];
    __shared__ __nv_bfloat16 sV[64][APAD];
    int tid = threadIdx.x, lane = tid & 31, wid = tid >> 5;
    int q0 = blockIdx.x * 128;
    int h = blockIdx.y, b = blockIdx.z;
    size_t base = ((size_t)(b*NH_ + h))*SEQL*HD_;
    const __nv_bfloat16* Qg = g_qb + base;
    const __nv_bfloat16* Kg = g_kb + base;
    const __nv_bfloat16* Vg = g_vb + base;

    {
        int r = tid >> 1, c = (tid & 1)*32;
        const uint4* src = (const uint4*)(Qg + (size_t)(q0 + r)*64 + c);
        uint4 v0 = src[0], v1 = src[1], v2 = src[2], v3 = src[3];
        uint4* d = (uint4*)&sQ[r][c];
        d[0] = v0; d[1] = v1; d[2] = v2; d[3] = v3;
    }

    int kvr = tid >> 2, kvc = (tid & 3)*16;
    uint4 pk0, pk1, pv0, pv1;
    {
        pk0 = *(const uint4*)(Kg + (size_t)kvr*64 + kvc);
        pk1 = *(const uint4*)(Kg + (size_t)kvr*64 + kvc + 8);
        pv0 = *(const uint4*)(Vg + (size_t)kvr*64 + kvc);
        pv1 = *(const uint4*)(Vg + (size_t)kvr*64 + kvc + 8);
    }
    __syncthreads();

    uint32_t aq[4][4];
    {
        int r = wid*16 + (lane & 15);
        int cb = (lane >> 4)*8;
        #pragma unroll
        for (int kc = 0; kc < 4; kc++)
            ldsm_x4(aq[kc], smem_u32(&sQ[r][kc*16 + cb]));
    }

    float mrun[2] = {-1e30f, -1e30f}, lrun[2] = {0.f, 0.f};
    float oacc[8][4];
    #pragma unroll
    for (int nf = 0; nf < 8; nf++)
        #pragma unroll
        for (int q = 0; q < 4; q++) oacc[nf][q] = 0.f;

    for (int t = 0; t < SEQL/64; t++) {
        *(uint4*)&sK[kvr][kvc]     = pk0;
        *(uint4*)&sK[kvr][kvc + 8] = pk1;
        *(uint4*)&sV[kvr][kvc]     = pv0;
        *(uint4*)&sV[kvr][kvc + 8] = pv1;
        __syncthreads();
        if (t + 1 < SEQL/64) {
            const __nv_bfloat16* Kt = Kg + (size_t)(t+1)*64*64;
            const __nv_bfloat16* Vt = Vg + (size_t)(t+1)*64*64;
            pk0 = *(const uint4*)(Kt + (size_t)kvr*64 + kvc);
            pk1 = *(const uint4*)(Kt + (size_t)kvr*64 + kvc + 8);
            pv0 = *(const uint4*)(Vt + (size_t)kvr*64 + kvc);
            pv1 = *(const uint4*)(Vt + (size_t)kvr*64 + kvc + 8);
        }

        float s[8][4];
        #pragma unroll
        for (int nf = 0; nf < 8; nf++)
            #pragma unroll
            for (int q = 0; q < 4; q++) s[nf][q] = 0.f;
        #pragma unroll
        for (int kc = 0; kc < 4; kc++) {
            #pragma unroll
            for (int nf = 0; nf < 8; nf++) {
                uint32_t bk[2];
                ldsm_x2(bk, smem_u32(&sK[nf*8 + (lane & 7)][kc*16 + ((lane >> 3) & 1)*8]));
                mma16816(s[nf], aq[kc], bk);
            }
        }

        #pragma unroll
        for (int hh = 0; hh < 2; hh++) {
            float tm = -1e30f;
            #pragma unroll
            for (int nf = 0; nf < 8; nf++)
                tm = fmaxf(tm, fmaxf(s[nf][hh*2], s[nf][hh*2+1]));
            tm = fmaxf(tm, __shfl_xor_sync(0xffffffffu, tm, 1));
            tm = fmaxf(tm, __shfl_xor_sync(0xffffffffu, tm, 2));
            float mn = fmaxf(mrun[hh], tm);
            float f = __expf(mrun[hh] - mn);
            float rs = 0.f;
            #pragma unroll
            for (int nf = 0; nf < 8; nf++) {
                float p0 = __expf(s[nf][hh*2]   - mn);
                float p1 = __expf(s[nf][hh*2+1] - mn);
                s[nf][hh*2] = p0; s[nf][hh*2+1] = p1;
                rs += p0 + p1;
            }
            rs += __shfl_xor_sync(0xffffffffu, rs, 1);
            rs += __shfl_xor_sync(0xffffffffu, rs, 2);
            lrun[hh] = lrun[hh]*f + rs;
            mrun[hh] = mn;
            #pragma unroll
            for (int nf = 0; nf < 8; nf++) {
                oacc[nf][hh*2]   *= f;
                oacc[nf][hh*2+1] *= f;
            }
        }

        uint32_t pf[4][4];
        #pragma unroll
        for (int kc = 0; kc < 4; kc++) {
            pf[kc][0] = packbf(s[2*kc][0],   s[2*kc][1]);
            pf[kc][1] = packbf(s[2*kc][2],   s[2*kc][3]);
            pf[kc][2] = packbf(s[2*kc+1][0], s[2*kc+1][1]);
            pf[kc][3] = packbf(s[2*kc+1][2], s[2*kc+1][3]);
        }

        #pragma unroll
        for (int nf = 0; nf < 8; nf++) {
            #pragma unroll
            for (int kc = 0; kc < 4; kc++) {
                uint32_t bv[2];
                ldsm_x2t(bv, smem_u32(&sV[kc*16 + (lane & 15)][nf*8]));
                mma16816(oacc[nf], pf[kc], bv);
            }
        }
        __syncthreads();
    }

    int r0 = wid*16 + (lane >> 2);
    #pragma unroll
    for (int hh = 0; hh < 2; hh++) {
        float inv = 1.0f / lrun[hh];
        int row = q0 + r0 + hh*8;
        size_t o = ((size_t)(b*SEQL) + row)*DIM_ + h*64 + (lane & 3)*2;
        #pragma unroll
        for (int nf = 0; nf < 8; nf++) {
            __nv_bfloat162 p = __floats2bfloat162_rn(oacc[nf][hh*2]*inv, oacc[nf][hh*2+1]*inv);
            *(__nv_bfloat162*)(g_attnb + o + nf*8) = p;
        }
    }
}

// ------------- combine (H in bf16) -------------------------------------------
__device__ __forceinline__ float block_sum(float v, float* shm)
{
    #pragma unroll
    for (int o = 16; o; o >>= 1) v += __shfl_xor_sync(0xffffffffu, v, o);
    __syncthreads();
    if ((threadIdx.x & 31) == 0) shm[threadIdx.x >> 5] = v;
    __syncthreads();
    if (threadIdx.x < 32) {
        float t = (threadIdx.x < 8) ? shm[threadIdx.x] : 0.f;
        #pragma unroll
        for (int o = 4; o; o >>= 1) t += __shfl_xor_sync(0xffffffffu, t, o);
        if (threadIdx.x == 0) shm[0] = t;
    }
    __syncthreads();
    return shm[0];
}

__global__ __launch_bounds__(256) void combine_kernel(const float* __restrict__ X,
                                                      const __nv_bfloat16* __restrict__ H,
                                                      const float* __restrict__ alpha,
                                                      float* __restrict__ Out)
{
    __shared__ float shm[8];
    int row = blockIdx.x;
    const float* xp = X + (size_t)row*DIM_;
    const __nv_bfloat16* hp = H + (size_t)row*DIM_;
    float xv[4], hv[4];
    float sx = 0.f, sh = 0.f;
    #pragma unroll
    for (int i = 0; i < 4; i++) {
        int j = threadIdx.x + i*256;
        xv[i] = xp[j]; hv[i] = __bfloat162float(hp[j]);
        sx = fmaf(xv[i], xv[i], sx);
        sh = fmaf(hv[i], hv[i], sh);
    }
    float nx = block_sum(sx, shm);
    float nh = block_sum(sh, shm);
    float invx = 1.0f / fmaxf(sqrtf(nx), 1e-12f);
    float invh = 1.0f / fmaxf(sqrtf(nh), 1e-12f);
    float yv[4]; float sy = 0.f;
    #pragma unroll
    for (int i = 0; i < 4; i++) {
        int j = threadIdx.x + i*256;
        float lr = fabsf(alpha[j] * 1.6f);
        float hn = xv[i]*invx;
        float y = hn + lr*(hv[i]*invh - hn);
        yv[i] = y; sy = fmaf(y, y, sy);
    }
    float ny = block_sum(sy, shm);
    float invy = 1.0f / fmaxf(sqrtf(ny), 1e-12f);
    #pragma unroll
    for (int i = 0; i < 4; i++)
        Out[(size_t)row*DIM_ + threadIdx.x + i*256] = yv[i]*invy;
}

// ------------------------------- launcher -------------------------------------
extern "C" void kernel_launch(void* const* d_in, const int* in_sizes, int n_in,
                              void* d_out, int out_size)
{
    const float* x   = (const float*)d_in[0];
    const float* fc  = (const float*)d_in[1];
    const float* fs  = (const float*)d_in[2];
    const float* ada = (const float*)d_in[3];
    const float* wq  = (const float*)d_in[4];
    const float* wk  = (const float*)d_in[5];
    const float* wv  = (const float*)d_in[6];
    const float* wo  = (const float*)d_in[7];
    const float* sqk = (const float*)d_in[8];
    const float* w1  = (const float*)d_in[9];
    const float* w2  = (const float*)d_in[10];
    const float* w3  = (const float*)d_in[11];
    const float* su  = (const float*)d_in[12];
    const float* sv  = (const float*)d_in[13];
    const float* pw  = (const float*)d_in[14];
    const float* pb  = (const float*)d_in[15];
    const float* aat = (const float*)d_in[16];
    const float* aml = (const float*)d_in[17];
    float* out = (float*)d_out;

    float *x1;
    __nv_bfloat16 *xmodb, *attnb, *x1mb, *hhb, *qkvb, *kmat, *xpat, *hab, *hmb;
    __nv_bfloat16 *wqkvt, *wot, *w13t, *w2t;
    cudaGetSymbolAddress((void**)&x1,   g_x1);
    cudaGetSymbolAddress((void**)&xmodb, g_xmodb);
    cudaGetSymbolAddress((void**)&attnb, g_attnb);
    cudaGetSymbolAddress((void**)&x1mb,  g_x1mb);
    cudaGetSymbolAddress((void**)&hhb,   g_hhb);
    cudaGetSymbolAddress((void**)&qkvb,  g_qkvb);
    cudaGetSymbolAddress((void**)&kmat,  g_kmat);
    cudaGetSymbolAddress((void**)&xpat,  g_xpat);
    cudaGetSymbolAddress((void**)&hab,   g_hab);
    cudaGetSymbolAddress((void**)&hmb,   g_hmb);
    cudaGetSymbolAddress((void**)&wqkvt, g_wqkvt);
    cudaGetSymbolAddress((void**)&wot,   g_wot);
    cudaGetSymbolAddress((void**)&w13t,  g_w13t);
    cudaGetSymbolAddress((void**)&w2t,   g_w2t);

    cudaFuncSetAttribute(tgemm_epi<EpiBF16>,   cudaFuncAttributeMaxDynamicSharedMemorySize, GEMM_SMEM);
    cudaFuncSetAttribute(tgemm_epi<EpiSwiglu>, cudaFuncAttributeMaxDynamicSharedMemorySize, GEMM_SMEM);
    cudaFuncSetAttribute(tgemm_mod,            cudaFuncAttributeMaxDynamicSharedMemorySize, GEMM_SMEM);

    // 0. weight transposes (bf16, [N][K]); qkv packed; w1/w3 interleaved
    wtrans_kernel<<<dim3(DIM_/32, DIM_/32), dim3(32,8)>>>(wq, wqkvt,               DIM_, DIM_, 1, 0);
    wtrans_kernel<<<dim3(DIM_/32, DIM_/32), dim3(32,8)>>>(wk, wqkvt + DIM_*DIM_,   DIM_, DIM_, 1, 0);
    wtrans_kernel<<<dim3(DIM_/32, DIM_/32), dim3(32,8)>>>(wv, wqkvt + 2*DIM_*DIM_, DIM_, DIM_, 1, 0);
    wtrans_kernel<<<dim3(DIM_/32, DIM_/32), dim3(32,8)>>>(wo, wot, DIM_, DIM_, 1, 0);
    wtrans_kernel<<<dim3(HID_/32, DIM_/32), dim3(32,8)>>>(w1, w13t, DIM_, HID_, 2, 0);
    wtrans_kernel<<<dim3(HID_/32, DIM_/32), dim3(32,8)>>>(w3, w13t, DIM_, HID_, 2, 1);
    wtrans_kernel<<<dim3(DIM_/32, HID_/32), dim3(32,8)>>>(w2, w2t, HID_, DIM_, 1, 0);

    // 1. adafm projection + conv kernel matrices
    proj_kernel<<<dim3(2, 2), 256>>>(ada, pw, pb);
    kconv_kernel<<<dim3(2, 2), 256>>>();
    kmat_kernel<<<4, 256>>>();

    // 2. attention branch
    gather_kernel<<<dim3(NPATB/4, B_), 256>>>(x, xpat);
    tgemm_mod<<<dim3(2, NPATB/128, B_), 256, GEMM_SMEM>>>(xpat, kmat, xmodb);
    tgemm_epi<EpiBF16><<<dim3(NQKV/128, NTOK/128), 256, GEMM_SMEM>>>(xmodb, wqkvt, DIM_, EpiBF16{qkvb, NQKV});
    rotnorm_kernel<<<NTOK, 512>>>(fc, fs, sqk);
    attn_kernel<<<dim3(SEQL/128, NH_, B_), 256>>>();
    tgemm_epi<EpiBF16><<<dim3(DIM_/128, NTOK/128), 256, GEMM_SMEM>>>(attnb, wot, DIM_, EpiBF16{hab, DIM_});
    combine_kernel<<<NTOK, 256>>>(x, hab, aat, x1);

    // 3. mlp branch
    gather_kernel<<<dim3(NPATB/4, B_), 256>>>(x1, xpat);
    tgemm_mod<<<dim3(2, NPATB/128, B_), 256, GEMM_SMEM>>>(xpat, kmat + 2*256*256, x1mb);
    tgemm_epi<EpiSwiglu><<<dim3(N13/128, NTOK/128), 256, GEMM_SMEM>>>(x1mb, w13t, DIM_, EpiSwiglu{hhb, su, sv});
    tgemm_epi<EpiBF16><<<dim3(DIM_/128, NTOK/128), 256, GEMM_SMEM>>>(hhb, w2t, HID_, EpiBF16{hmb, DIM_});
    combine_kernel<<<NTOK, 256>>>(x1, hmb, aml, out);
}

// round 9
// speedup vs baseline: 5.5028x; 1.0074x over previous
#include <cuda_runtime.h>
#include <cuda_bf16.h>
#include <math.h>
#include <cstdint>

#define B_    2
#define SEQL  2048
#define DIM_  1024
#define NH_   16
#define HD_   64
#define HID_  2816
#define NTOK  (B_*SEQL)          // 4096
#define NQKV  (3*DIM_)           // 3072
#define N13   (2*HID_)           // 5632
#define NPATB 8192               // patches per batch (128*64)

// ---------------- scratch (device globals; no allocations allowed) ----------
__device__ float g_t[B_*512];
__device__ float g_kc[4*256];
__device__ float g_x1[NTOK*DIM_];
// bf16 activations
__device__ __nv_bfloat16 g_qkvb[NTOK*NQKV];
__device__ __nv_bfloat16 g_qb[NTOK*DIM_];
__device__ __nv_bfloat16 g_kb[NTOK*DIM_];
__device__ __nv_bfloat16 g_vb[NTOK*DIM_];
__device__ __nv_bfloat16 g_xmodb[NTOK*DIM_];
__device__ __nv_bfloat16 g_attnb[NTOK*DIM_];
__device__ __nv_bfloat16 g_x1mb[NTOK*DIM_];
__device__ __nv_bfloat16 g_hhb[NTOK*HID_];
__device__ __nv_bfloat16 g_hab[NTOK*DIM_];
__device__ __nv_bfloat16 g_hmb[NTOK*DIM_];
// modulate-as-GEMM scratch
__device__ __nv_bfloat16 g_kmat[4*256*256];        // [which][b][n][k]
__device__ __nv_bfloat16 g_xpat[NTOK*DIM_];        // patch-major input
// bf16 transposed weights [N][K]
__device__ __nv_bfloat16 g_wqkvt[NQKV*DIM_];
__device__ __nv_bfloat16 g_wot[DIM_*DIM_];
__device__ __nv_bfloat16 g_w13t[N13*DIM_];         // interleaved: row 2j=w1_j, 2j+1=w3_j
__device__ __nv_bfloat16 g_w2t[DIM_*HID_];

// ====================== mma.sync helpers (family-safe) =======================
__device__ __forceinline__ uint32_t smem_u32(const void* p) {
    uint32_t a;
    asm("{ .reg .u64 t; cvta.to.shared.u64 t, %1; cvt.u32.u64 %0, t; }" : "=r"(a) : "l"(p));
    return a;
}
__device__ __forceinline__ void ldsm_x4(uint32_t* r, uint32_t addr) {
    asm volatile("ldmatrix.sync.aligned.m8n8.x4.shared.b16 {%0,%1,%2,%3}, [%4];"
                 : "=r"(r[0]), "=r"(r[1]), "=r"(r[2]), "=r"(r[3]) : "r"(addr));
}
__device__ __forceinline__ void ldsm_x2(uint32_t* r, uint32_t addr) {
    asm volatile("ldmatrix.sync.aligned.m8n8.x2.shared.b16 {%0,%1}, [%2];"
                 : "=r"(r[0]), "=r"(r[1]) : "r"(addr));
}
__device__ __forceinline__ void ldsm_x2t(uint32_t* r, uint32_t addr) {
    asm volatile("ldmatrix.sync.aligned.m8n8.x2.trans.shared.b16 {%0,%1}, [%2];"
                 : "=r"(r[0]), "=r"(r[1]) : "r"(addr));
}
__device__ __forceinline__ void mma16816(float* c, const uint32_t* a, const uint32_t* b) {
    asm volatile("mma.sync.aligned.m16n8k16.row.col.f32.bf16.bf16.f32 "
                 "{%0,%1,%2,%3}, {%4,%5,%6,%7}, {%8,%9}, {%0,%1,%2,%3};"
                 : "+f"(c[0]), "+f"(c[1]), "+f"(c[2]), "+f"(c[3])
                 : "r"(a[0]), "r"(a[1]), "r"(a[2]), "r"(a[3]), "r"(b[0]), "r"(b[1]));
}
__device__ __forceinline__ uint32_t packbf(float lo, float hi) {
    __nv_bfloat162 p = __floats2bfloat162_rn(lo, hi);
    return *(uint32_t*)&p;
}
#define CPASYNC16(saddr, gptr) \
    asm volatile("cp.async.cg.shared.global [%0], [%1], 16;" :: "r"(saddr), "l"(gptr))
#define CP_COMMIT() asm volatile("cp.async.commit_group;" ::: "memory")
#define CP_WAIT(n)  asm volatile("cp.async.wait_group %0;" :: "n"(n) : "memory")

// ============== cp.async 3-stage mma.sync GEMM, 256x128 CTA tile =============
// 8 warps in 4x2 grid, each 64x64. K-chunk 32. Row stride 40 bf16 (80B):
// 8-row ldmatrix groups hit banks 20r mod 32 -> all distinct, conflict-free.
#define SPAD   40
#define STG    3
#define ASTAGE (256*SPAD*2)          // 20480 B
#define BSTAGE (128*SPAD*2)          // 10240 B
#define STAGEB (ASTAGE+BSTAGE)       // 30720 B
#define GEMM_SMEM (STG*STAGEB)       // 92160 B

// ---- epilogues: receive (global row r0 [and r0+8], global col, acc[4]) ------
struct EpiBF16 {
    __nv_bfloat16* C; int N;
    __device__ __forceinline__ void store(int r0, int col, const float* a) const {
        *(uint32_t*)(C + (size_t)r0*N + col)     = packbf(a[0], a[1]);
        *(uint32_t*)(C + (size_t)(r0+8)*N + col) = packbf(a[2], a[3]);
    }
};
struct EpiSwiglu {      // w13 interleaved: col even=g1_j, col+1=g3_j ; out[row][j]
    __nv_bfloat16* out; const float* su; const float* sv;
    __device__ __forceinline__ void store(int r0, int col, const float* a) const {
        int j = col >> 1;
        float svj = sv[j] * 53.06599665f;       // sqrt(2816)
        float suj = su[j];
        float z0 = a[0]*svj, z1 = a[2]*svj;
        float h0 = z0 / (1.f + __expf(-z0)) * (a[1]*suj);
        float h1 = z1 / (1.f + __expf(-z1)) * (a[3]*suj);
        out[(size_t)r0*HID_ + j]     = __float2bfloat16(h0);
        out[(size_t)(r0+8)*HID_ + j] = __float2bfloat16(h1);
    }
};
struct EpiMod {         // modulate GEMM: row=patch p, col=pos n -> row-major Y
    __nv_bfloat16* Y;   // batch-offset applied
    __device__ __forceinline__ void store(int p, int n, const float* a) const {
        int grow0 = ((p >> 6) << 4) + (n >> 4);
        int gcol  = ((p & 63) << 4) + (n & 15);
        int grow1 = (((p+8) >> 6) << 4) + (n >> 4);
        int gcol1 = (((p+8) & 63) << 4) + (n & 15);
        *(uint32_t*)(Y + (size_t)grow0*DIM_ + gcol)  = packbf(a[0], a[1]);
        *(uint32_t*)(Y + (size_t)grow1*DIM_ + gcol1) = packbf(a[2], a[3]);
    }
};

template<class Epi>
__device__ __forceinline__ void tgemm_core(const __nv_bfloat16* __restrict__ A,
                                           const __nv_bfloat16* __restrict__ Bt,
                                           int K, uint32_t sbase, const Epi& epi)
{
    int tid = threadIdx.x, lane = tid & 31, wid = tid >> 5;
    int wr = wid >> 1, wc = wid & 1;              // 4x2 warp grid
    int row0 = blockIdx.y * 256, col0 = blockIdx.x * 128;

    int arow = tid >> 2, aseg = tid & 3;          // arow 0..63, aseg 0..3 (16B)
    const __nv_bfloat16* Ag = A  + (size_t)(row0 + arow)*K + aseg*8;
    const __nv_bfloat16* Bg = Bt + (size_t)(col0 + arow)*K + aseg*8;
    uint32_t sAo = arow*(SPAD*2) + aseg*16;
    uint32_t sBo = ASTAGE + arow*(SPAD*2) + aseg*16;

    int NC = K >> 5;

    #pragma unroll
    for (int s = 0; s < STG-1; s++) {
        uint32_t st = sbase + s*STAGEB;
        const __nv_bfloat16* Ap = Ag + (size_t)s*32;
        const __nv_bfloat16* Bp = Bg + (size_t)s*32;
        #pragma unroll
        for (int i = 0; i < 4; i++)
            CPASYNC16(st + sAo + i*64*(SPAD*2), Ap + (size_t)i*64*K);
        #pragma unroll
        for (int i = 0; i < 2; i++)
            CPASYNC16(st + sBo + i*64*(SPAD*2), Bp + (size_t)i*64*K);
        CP_COMMIT();
    }

    float acc[4][8][4];
    #pragma unroll
    for (int i = 0; i < 4; i++)
        #pragma unroll
        for (int j = 0; j < 8; j++)
            #pragma unroll
            for (int q = 0; q < 4; q++) acc[i][j][q] = 0.f;

    // A ldmatrix lane addressing (x4: m16 x k16)
    int aq = lane >> 3, arw = lane & 7;
    int a_r = (aq & 1)*8 + arw;                   // row within 16
    int a_kb = (aq >> 1)*16;                      // byte offset of k-half
    // B paired-x4 lane addressing (two n-tiles x two k-halves)
    int b_r2 = ((lane >> 4) << 3) + (lane & 7);   // row within 16 (two 8-row tiles)
    int b_kb2 = ((lane >> 3) & 1)*16;

    int buf = 0;
    for (int c = 0; c < NC; c++) {
        CP_WAIT(STG-2);
        __syncthreads();

        if (c + STG-1 < NC) {
            int pb = buf - 1; if (pb < 0) pb += STG;
            uint32_t st = sbase + pb*STAGEB;
            const __nv_bfloat16* Ap = Ag + (size_t)(c+STG-1)*32;
            const __nv_bfloat16* Bp = Bg + (size_t)(c+STG-1)*32;
            #pragma unroll
            for (int i = 0; i < 4; i++)
                CPASYNC16(st + sAo + i*64*(SPAD*2), Ap + (size_t)i*64*K);
            #pragma unroll
            for (int i = 0; i < 2; i++)
                CPASYNC16(st + sBo + i*64*(SPAD*2), Bp + (size_t)i*64*K);
        }
        CP_COMMIT();

        uint32_t aBase = sbase + buf*STAGEB;
        uint32_t bBase = aBase + ASTAGE;
        #pragma unroll
        for (int ks = 0; ks < 2; ks++) {
            uint32_t afr[4][4], bfr[8][2];
            #pragma unroll
            for (int mt = 0; mt < 4; mt++)
                ldsm_x4(afr[mt], aBase + (wr*64 + mt*16 + a_r)*(SPAD*2) + ks*32 + a_kb);
            #pragma unroll
            for (int ntp = 0; ntp < 4; ntp++) {
                uint32_t b4[4];
                ldsm_x4(b4, bBase + (wc*64 + ntp*16 + b_r2)*(SPAD*2) + ks*32 + b_kb2);
                bfr[2*ntp][0]   = b4[0]; bfr[2*ntp][1]   = b4[1];
                bfr[2*ntp+1][0] = b4[2]; bfr[2*ntp+1][1] = b4[3];
            }
            #pragma unroll
            for (int mt = 0; mt < 4; mt++)
                #pragma unroll
                for (int nt = 0; nt < 8; nt++)
                    mma16816(acc[mt][nt], afr[mt], bfr[nt]);
        }
        __syncthreads();
        buf++; if (buf == STG) buf = 0;
    }

    int cr = lane >> 2, cc = (lane & 3)*2;
    #pragma unroll
    for (int mt = 0; mt < 4; mt++) {
        int r0 = row0 + wr*64 + mt*16 + cr;
        #pragma unroll
        for (int nt = 0; nt < 8; nt++)
            epi.store(r0, col0 + wc*64 + nt*8 + cc, acc[mt][nt]);
    }
}

template<class Epi>
__global__ __launch_bounds__(256) void tgemm_epi(const __nv_bfloat16* __restrict__ A,
                                                 const __nv_bfloat16* __restrict__ Bt,
                                                 int K, Epi epi)
{
    extern __shared__ char smemraw[];
    tgemm_core<Epi>(A, Bt, K, smem_u32(smemraw), epi);
}

// batched modulate GEMM with fused scatter epilogue
__global__ __launch_bounds__(256) void tgemm_mod(const __nv_bfloat16* __restrict__ A,
                                                 const __nv_bfloat16* __restrict__ Bt,
                                                 __nv_bfloat16* __restrict__ Y)
{
    extern __shared__ char smemraw[];
    int z = blockIdx.z;
    EpiMod epi{ Y + (size_t)z*SEQL*DIM_ };
    tgemm_core<EpiMod>(A + (size_t)z*NPATB*256, Bt + (size_t)z*256*256,
                       256, smem_u32(smemraw), epi);
}

// -------- weight transpose + bf16 convert (with output row stride/offset) ----
__global__ void wtrans_kernel(const float* __restrict__ W, __nv_bfloat16* __restrict__ Wt,
                              int K, int N, int rs, int ro)
{
    __shared__ float t[32][33];
    int tx = threadIdx.x, ty = threadIdx.y;
    int n = blockIdx.x*32 + tx;
    int k0 = blockIdx.y*32;
    #pragma unroll
    for (int j = 0; j < 32; j += 8)
        t[ty+j][tx] = W[(size_t)(k0+ty+j)*N + n];
    __syncthreads();
    int k = k0 + tx;
    int nb = blockIdx.x*32;
    #pragma unroll
    for (int j = 0; j < 32; j += 8)
        Wt[((size_t)(nb+ty+j)*rs + ro)*K + k] = __float2bfloat16(t[tx][ty+j]);
}

// ---------------- adafm projection -------------------------------------------
__global__ void proj_kernel(const float* __restrict__ ada, const float* __restrict__ pw,
                            const float* __restrict__ pb)
{
    int j = blockIdx.x * blockDim.x + threadIdx.x;
    int b = blockIdx.y;
    float acc = pb[j];
    const float* ap = ada + b*DIM_;
    for (int d = 0; d < DIM_; ++d) {
        float a = ap[d];
        float s = a / (1.0f + __expf(-a));
        acc = fmaf(s, pw[d*512 + j], acc);
    }
    g_t[b*512 + j] = acc;
}

__global__ void kconv_kernel()
{
    int d = threadIdx.x;
    int which = blockIdx.x, b = blockIdx.y;
    const float* F = g_t + b*512 + which*256;
    float acc = 0.f;
    for (int m = 0; m < 256; ++m) {
        int md = (m * d) & 255;
        acc = fmaf(F[m], cospif((float)md * (1.0f/128.0f)), acc);
    }
    g_kc[(which*2 + b)*256 + d] = acc * (1.0f/256.0f);
}

// -------- build conv matrices: Kmat[wb][n][k] = kk[(n-k)&255] ----------------
__global__ void kmat_kernel()
{
    int wb = blockIdx.x;
    int n = threadIdx.x;
    const float* kk = g_kc + wb*256;
    __nv_bfloat16* Km = g_kmat + (size_t)wb*256*256 + n*256;
    #pragma unroll 4
    for (int k = 0; k < 256; ++k)
        Km[k] = __float2bfloat16(kk[(n - k) & 255]);
}

// -------- gather: X fp32 row-major -> bf16 patch-major [b][p][256] -----------
__global__ __launch_bounds__(256) void gather_kernel(const float* __restrict__ X,
                                                     __nv_bfloat16* __restrict__ Xp)
{
    int b = blockIdx.y;
    int p = blockIdx.x*4 + (threadIdx.x >> 6);
    int q = threadIdx.x & 63;
    int r = q >> 2, cs = (q & 3)*4;
    int ib = p >> 6, jb = p & 63;
    float4 v = *(const float4*)(X + ((size_t)(b*SEQL + ib*16 + r))*DIM_ + jb*16 + cs);
    uint2 o;
    o.x = packbf(v.x, v.y);
    o.y = packbf(v.z, v.w);
    *(uint2*)(Xp + ((size_t)(b*NPATB + p))*256 + r*16 + cs) = o;
}

// ------------- rotary + justnorm -> bf16 q(×8)/k/v [B][H][S][64] -------------
__global__ __launch_bounds__(512) void rotnorm_kernel(const float* __restrict__ fc,
                                                      const float* __restrict__ fs,
                                                      const float* __restrict__ sqk)
{
    int row = blockIdx.x;
    int s = row & (SEQL - 1);
    int b = row >> 11;
    int h = threadIdx.x >> 5;
    int i = threadIdx.x & 31;
    float c = fc[s*32 + i], sn = fs[s*32 + i];
    size_t gin = (size_t)row*NQKV + h*64 + 2*i;
    __nv_bfloat162 qv = *(const __nv_bfloat162*)(g_qkvb + gin);
    __nv_bfloat162 kv = *(const __nv_bfloat162*)(g_qkvb + gin + DIM_);
    __nv_bfloat162 vv = *(const __nv_bfloat162*)(g_qkvb + gin + 2*DIM_);
    float qa = __bfloat162float(qv.x), qb = __bfloat162float(qv.y);
    float ka = __bfloat162float(kv.x), kb = __bfloat162float(kv.y);
    float ra = qa*c - qb*sn, rb = qa*sn + qb*c;
    float ta = ka*c - kb*sn, tb = ka*sn + kb*c;
    float sq = ra*ra + rb*rb, sk = ta*ta + tb*tb;
    #pragma unroll
    for (int o = 16; o; o >>= 1) {
        sq += __shfl_xor_sync(0xffffffffu, sq, o);
        sk += __shfl_xor_sync(0xffffffffu, sk, o);
    }
    float invq = 1.0f / fmaxf(sqrtf(sq), 1e-12f);
    float invk = 1.0f / fmaxf(sqrtf(sk), 1e-12f);
    float sa = sqk[h*64 + 2*i]   * 32.0f;
    float sb = sqk[h*64 + 2*i+1] * 32.0f;
    size_t go = ((size_t)(b*NH_ + h)*SEQL + s)*64 + 2*i;
    *(__nv_bfloat162*)(g_qb + go) = __floats2bfloat162_rn(ra*invq*sa*8.0f, rb*invq*sb*8.0f);
    *(__nv_bfloat162*)(g_kb + go) = __floats2bfloat162_rn(ta*invk*sa, tb*invk*sb);
    *(__nv_bfloat162*)(g_vb + go) = vv;
}

// ------------- flash attention, bf16 mma.sync --------------------------------
#define APAD 72
__global__ __launch_bounds__(256) void attn_kernel()
{
    __shared__ __nv_bfloat16 sQ[128][APAD];
    __shared__ __nv_bfloat16 sK[64][APAD];
    __shared__ __nv_bfloat16 sV[64][APAD];
    int tid = threadIdx.x, lane = tid & 31, wid = tid >> 5;
    int q0 = blockIdx.x * 128;
    int h = blockIdx.y, b = blockIdx.z;
    size_t base = ((size_t)(b*NH_ + h))*SEQL*HD_;
    const __nv_bfloat16* Qg = g_qb + base;
    const __nv_bfloat16* Kg = g_kb + base;
    const __nv_bfloat16* Vg = g_vb + base;

    {
        int r = tid >> 1, c = (tid & 1)*32;
        const uint4* src = (const uint4*)(Qg + (size_t)(q0 + r)*64 + c);
        uint4 v0 = src[0], v1 = src[1], v2 = src[2], v3 = src[3];
        uint4* d = (uint4*)&sQ[r][c];
        d[0] = v0; d[1] = v1; d[2] = v2; d[3] = v3;
    }

    int kvr = tid >> 2, kvc = (tid & 3)*16;
    uint4 pk0, pk1, pv0, pv1;
    {
        pk0 = *(const uint4*)(Kg + (size_t)kvr*64 + kvc);
        pk1 = *(const uint4*)(Kg + (size_t)kvr*64 + kvc + 8);
        pv0 = *(const uint4*)(Vg + (size_t)kvr*64 + kvc);
        pv1 = *(const uint4*)(Vg + (size_t)kvr*64 + kvc + 8);
    }
    __syncthreads();

    uint32_t aq[4][4];
    {
        int r = wid*16 + (lane & 15);
        int cb = (lane >> 4)*8;
        #pragma unroll
        for (int kc = 0; kc < 4; kc++)
            ldsm_x4(aq[kc], smem_u32(&sQ[r][kc*16 + cb]));
    }

    float mrun[2] = {-1e30f, -1e30f}, lrun[2] = {0.f, 0.f};
    float oacc[8][4];
    #pragma unroll
    for (int nf = 0; nf < 8; nf++)
        #pragma unroll
        for (int q = 0; q < 4; q++) oacc[nf][q] = 0.f;

    for (int t = 0; t < SEQL/64; t++) {
        *(uint4*)&sK[kvr][kvc]     = pk0;
        *(uint4*)&sK[kvr][kvc + 8] = pk1;
        *(uint4*)&sV[kvr][kvc]     = pv0;
        *(uint4*)&sV[kvr][kvc + 8] = pv1;
        __syncthreads();
        if (t + 1 < SEQL/64) {
            const __nv_bfloat16* Kt = Kg + (size_t)(t+1)*64*64;
            const __nv_bfloat16* Vt = Vg + (size_t)(t+1)*64*64;
            pk0 = *(const uint4*)(Kt + (size_t)kvr*64 + kvc);
            pk1 = *(const uint4*)(Kt + (size_t)kvr*64 + kvc + 8);
            pv0 = *(const uint4*)(Vt + (size_t)kvr*64 + kvc);
            pv1 = *(const uint4*)(Vt + (size_t)kvr*64 + kvc + 8);
        }

        float s[8][4];
        #pragma unroll
        for (int nf = 0; nf < 8; nf++)
            #pragma unroll
            for (int q = 0; q < 4; q++) s[nf][q] = 0.f;
        #pragma unroll
        for (int kc = 0; kc < 4; kc++) {
            #pragma unroll
            for (int nf = 0; nf < 8; nf++) {
                uint32_t bk[2];
                ldsm_x2(bk, smem_u32(&sK[nf*8 + (lane & 7)][kc*16 + ((lane >> 3) & 1)*8]));
                mma16816(s[nf], aq[kc], bk);
            }
        }

        #pragma unroll
        for (int hh = 0; hh < 2; hh++) {
            float tm = -1e30f;
            #pragma unroll
            for (int nf = 0; nf < 8; nf++)
                tm = fmaxf(tm, fmaxf(s[nf][hh*2], s[nf][hh*2+1]));
            tm = fmaxf(tm, __shfl_xor_sync(0xffffffffu, tm, 1));
            tm = fmaxf(tm, __shfl_xor_sync(0xffffffffu, tm, 2));
            float mn = fmaxf(mrun[hh], tm);
            float f = __expf(mrun[hh] - mn);
            float rs = 0.f;
            #pragma unroll
            for (int nf = 0; nf < 8; nf++) {
                float p0 = __expf(s[nf][hh*2]   - mn);
                float p1 = __expf(s[nf][hh*2+1] - mn);
                s[nf][hh*2] = p0; s[nf][hh*2+1] = p1;
                rs += p0 + p1;
            }
            rs += __shfl_xor_sync(0xffffffffu, rs, 1);
            rs += __shfl_xor_sync(0xffffffffu, rs, 2);
            lrun[hh] = lrun[hh]*f + rs;
            mrun[hh] = mn;
            #pragma unroll
            for (int nf = 0; nf < 8; nf++) {
                oacc[nf][hh*2]   *= f;
                oacc[nf][hh*2+1] *= f;
            }
        }

        uint32_t pf[4][4];
        #pragma unroll
        for (int kc = 0; kc < 4; kc++) {
            pf[kc][0] = packbf(s[2*kc][0],   s[2*kc][1]);
            pf[kc][1] = packbf(s[2*kc][2],   s[2*kc][3]);
            pf[kc][2] = packbf(s[2*kc+1][0], s[2*kc+1][1]);
            pf[kc][3] = packbf(s[2*kc+1][2], s[2*kc+1][3]);
        }

        #pragma unroll
        for (int nf = 0; nf < 8; nf++) {
            #pragma unroll
            for (int kc = 0; kc < 4; kc++) {
                uint32_t bv[2];
                ldsm_x2t(bv, smem_u32(&sV[kc*16 + (lane & 15)][nf*8]));
                mma16816(oacc[nf], pf[kc], bv);
            }
        }
        __syncthreads();
    }

    int r0 = wid*16 + (lane >> 2);
    #pragma unroll
    for (int hh = 0; hh < 2; hh++) {
        float inv = 1.0f / lrun[hh];
        int row = q0 + r0 + hh*8;
        size_t o = ((size_t)(b*SEQL) + row)*DIM_ + h*64 + (lane & 3)*2;
        #pragma unroll
        for (int nf = 0; nf < 8; nf++) {
            __nv_bfloat162 p = __floats2bfloat162_rn(oacc[nf][hh*2]*inv, oacc[nf][hh*2+1]*inv);
            *(__nv_bfloat162*)(g_attnb + o + nf*8) = p;
        }
    }
}

// ------------- combine (H in bf16) -------------------------------------------
__device__ __forceinline__ float block_sum(float v, float* shm)
{
    #pragma unroll
    for (int o = 16; o; o >>= 1) v += __shfl_xor_sync(0xffffffffu, v, o);
    __syncthreads();
    if ((threadIdx.x & 31) == 0) shm[threadIdx.x >> 5] = v;
    __syncthreads();
    if (threadIdx.x < 32) {
        float t = (threadIdx.x < 8) ? shm[threadIdx.x] : 0.f;
        #pragma unroll
        for (int o = 4; o; o >>= 1) t += __shfl_xor_sync(0xffffffffu, t, o);
        if (threadIdx.x == 0) shm[0] = t;
    }
    __syncthreads();
    return shm[0];
}

__global__ __launch_bounds__(256) void combine_kernel(const float* __restrict__ X,
                                                      const __nv_bfloat16* __restrict__ H,
                                                      const float* __restrict__ alpha,
                                                      float* __restrict__ Out)
{
    __shared__ float shm[8];
    int row = blockIdx.x;
    const float* xp = X + (size_t)row*DIM_;
    const __nv_bfloat16* hp = H + (size_t)row*DIM_;
    float xv[4], hv[4];
    float sx = 0.f, sh = 0.f;
    #pragma unroll
    for (int i = 0; i < 4; i++) {
        int j = threadIdx.x + i*256;
        xv[i] = xp[j]; hv[i] = __bfloat162float(hp[j]);
        sx = fmaf(xv[i], xv[i], sx);
        sh = fmaf(hv[i], hv[i], sh);
    }
    float nx = block_sum(sx, shm);
    float nh = block_sum(sh, shm);
    float invx = 1.0f / fmaxf(sqrtf(nx), 1e-12f);
    float invh = 1.0f / fmaxf(sqrtf(nh), 1e-12f);
    float yv[4]; float sy = 0.f;
    #pragma unroll
    for (int i = 0; i < 4; i++) {
        int j = threadIdx.x + i*256;
        float lr = fabsf(alpha[j] * 1.6f);
        float hn = xv[i]*invx;
        float y = hn + lr*(hv[i]*invh - hn);
        yv[i] = y; sy = fmaf(y, y, sy);
    }
    float ny = block_sum(sy, shm);
    float invy = 1.0f / fmaxf(sqrtf(ny), 1e-12f);
    #pragma unroll
    for (int i = 0; i < 4; i++)
        Out[(size_t)row*DIM_ + threadIdx.x + i*256] = yv[i]*invy;
}

// ------------------------------- launcher -------------------------------------
extern "C" void kernel_launch(void* const* d_in, const int* in_sizes, int n_in,
                              void* d_out, int out_size)
{
    const float* x   = (const float*)d_in[0];
    const float* fc  = (const float*)d_in[1];
    const float* fs  = (const float*)d_in[2];
    const float* ada = (const float*)d_in[3];
    const float* wq  = (const float*)d_in[4];
    const float* wk  = (const float*)d_in[5];
    const float* wv  = (const float*)d_in[6];
    const float* wo  = (const float*)d_in[7];
    const float* sqk = (const float*)d_in[8];
    const float* w1  = (const float*)d_in[9];
    const float* w2  = (const float*)d_in[10];
    const float* w3  = (const float*)d_in[11];
    const float* su  = (const float*)d_in[12];
    const float* sv  = (const float*)d_in[13];
    const float* pw  = (const float*)d_in[14];
    const float* pb  = (const float*)d_in[15];
    const float* aat = (const float*)d_in[16];
    const float* aml = (const float*)d_in[17];
    float* out = (float*)d_out;

    float *x1;
    __nv_bfloat16 *xmodb, *attnb, *x1mb, *hhb, *qkvb, *kmat, *xpat, *hab, *hmb;
    __nv_bfloat16 *wqkvt, *wot, *w13t, *w2t;
    cudaGetSymbolAddress((void**)&x1,   g_x1);
    cudaGetSymbolAddress((void**)&xmodb, g_xmodb);
    cudaGetSymbolAddress((void**)&attnb, g_attnb);
    cudaGetSymbolAddress((void**)&x1mb,  g_x1mb);
    cudaGetSymbolAddress((void**)&hhb,   g_hhb);
    cudaGetSymbolAddress((void**)&qkvb,  g_qkvb);
    cudaGetSymbolAddress((void**)&kmat,  g_kmat);
    cudaGetSymbolAddress((void**)&xpat,  g_xpat);
    cudaGetSymbolAddress((void**)&hab,   g_hab);
    cudaGetSymbolAddress((void**)&hmb,   g_hmb);
    cudaGetSymbolAddress((void**)&wqkvt, g_wqkvt);
    cudaGetSymbolAddress((void**)&wot,   g_wot);
    cudaGetSymbolAddress((void**)&w13t,  g_w13t);
    cudaGetSymbolAddress((void**)&w2t,   g_w2t);

    cudaFuncSetAttribute(tgemm_epi<EpiBF16>,   cudaFuncAttributeMaxDynamicSharedMemorySize, GEMM_SMEM);
    cudaFuncSetAttribute(tgemm_epi<EpiSwiglu>, cudaFuncAttributeMaxDynamicSharedMemorySize, GEMM_SMEM);
    cudaFuncSetAttribute(tgemm_mod,            cudaFuncAttributeMaxDynamicSharedMemorySize, GEMM_SMEM);

    // 0. weight transposes (bf16, [N][K]); qkv packed; w1/w3 interleaved
    wtrans_kernel<<<dim3(DIM_/32, DIM_/32), dim3(32,8)>>>(wq, wqkvt,               DIM_, DIM_, 1, 0);
    wtrans_kernel<<<dim3(DIM_/32, DIM_/32), dim3(32,8)>>>(wk, wqkvt + DIM_*DIM_,   DIM_, DIM_, 1, 0);
    wtrans_kernel<<<dim3(DIM_/32, DIM_/32), dim3(32,8)>>>(wv, wqkvt + 2*DIM_*DIM_, DIM_, DIM_, 1, 0);
    wtrans_kernel<<<dim3(DIM_/32, DIM_/32), dim3(32,8)>>>(wo, wot, DIM_, DIM_, 1, 0);
    wtrans_kernel<<<dim3(HID_/32, DIM_/32), dim3(32,8)>>>(w1, w13t, DIM_, HID_, 2, 0);
    wtrans_kernel<<<dim3(HID_/32, DIM_/32), dim3(32,8)>>>(w3, w13t, DIM_, HID_, 2, 1);
    wtrans_kernel<<<dim3(DIM_/32, HID_/32), dim3(32,8)>>>(w2, w2t, HID_, DIM_, 1, 0);

    // 1. adafm projection + conv kernel matrices
    proj_kernel<<<dim3(2, 2), 256>>>(ada, pw, pb);
    kconv_kernel<<<dim3(2, 2), 256>>>();
    kmat_kernel<<<4, 256>>>();

    // 2. attention branch
    gather_kernel<<<dim3(NPATB/4, B_), 256>>>(x, xpat);
    tgemm_mod<<<dim3(2, NPATB/256, B_), 256, GEMM_SMEM>>>(xpat, kmat, xmodb);
    tgemm_epi<EpiBF16><<<dim3(NQKV/128, NTOK/256), 256, GEMM_SMEM>>>(xmodb, wqkvt, DIM_, EpiBF16{qkvb, NQKV});
    rotnorm_kernel<<<NTOK, 512>>>(fc, fs, sqk);
    attn_kernel<<<dim3(SEQL/128, NH_, B_), 256>>>();
    tgemm_epi<EpiBF16><<<dim3(DIM_/128, NTOK/256), 256, GEMM_SMEM>>>(attnb, wot, DIM_, EpiBF16{hab, DIM_});
    combine_kernel<<<NTOK, 256>>>(x, hab, aat, x1);

    // 3. mlp branch
    gather_kernel<<<dim3(NPATB/4, B_), 256>>>(x1, xpat);
    tgemm_mod<<<dim3(2, NPATB/256, B_), 256, GEMM_SMEM>>>(xpat, kmat + 2*256*256, x1mb);
    tgemm_epi<EpiSwiglu><<<dim3(N13/128, NTOK/256), 256, GEMM_SMEM>>>(x1mb, w13t, DIM_, EpiSwiglu{hhb, su, sv});
    tgemm_epi<EpiBF16><<<dim3(DIM_/128, NTOK/256), 256, GEMM_SMEM>>>(hhb, w2t, HID_, EpiBF16{hmb, DIM_});
    combine_kernel<<<NTOK, 256>>>(x1, hmb, aml, out);
}